// round 1
// baseline (speedup 1.0000x reference)
#include <cuda_runtime.h>
#include <cuda_bf16.h>
#include <math.h>

typedef unsigned long long ull;

#define Bn 8
#define Cn 64
#define HWn 4096

// ---------------- scratch (device globals; no allocs allowed) ----------------
__device__ __align__(16) float d_psi[Bn*Cn*HWn];     // 8MB
__device__ __align__(16) float d_fb [Bn*8*HWn];
__device__ __align__(16) float d_fc [Bn*8*HWn];
__device__ __align__(16) float d_fd [Bn*Cn*HWn];     // 8MB
__device__ __align__(16) float d_cam[Bn*Cn*HWn];     // 8MB
__device__ __align__(16) float d_pam[Bn*Cn*HWn];     // 8MB
__device__ __align__(16) float d_attp[8*Bn*64*64];   // CAM partial gram (8 segments)
__device__ __align__(16) float d_attw[Bn*64*64];     // CAM softmaxed weights
__device__ __align__(16) float d_WfT[512*64];        // folded fused weights, [c][o]
__device__ __align__(16) float d_bias[64];
__device__ __align__(16) float d_wp[64];
__device__ __align__(16) float d_bp[1];
__device__ __align__(16) float d_da[Bn*HWn];

// ---------------- f32x2 helpers ----------------
__device__ __forceinline__ ull pk2(float lo, float hi) {
    ull r; asm("mov.b64 %0, {%1, %2};" : "=l"(r) : "f"(lo), "f"(hi)); return r;
}
__device__ __forceinline__ void upk2(ull v, float& lo, float& hi) {
    asm("mov.b64 {%0, %1}, %2;" : "=f"(lo), "=f"(hi) : "l"(v));
}
__device__ __forceinline__ ull ffma2(ull a, ull b, ull c) {
    ull d; asm("fma.rn.f32x2 %0, %1, %2, %3;" : "=l"(d) : "l"(a), "l"(b), "l"(c)); return d;
}
__device__ __forceinline__ ull fmul2(ull a, ull b) {
    ull d; asm("mul.rn.f32x2 %0, %1, %2;" : "=l"(d) : "l"(a), "l"(b)); return d;
}

// ---------------- prep: fold BN into conv weights ----------------
__global__ void k_prep(const float* Wg_w, const float* Wg_b, const float* gg, const float* gb,
                       const float* gm, const float* gv,
                       const float* Wx_w, const float* Wx_b, const float* xg, const float* xb,
                       const float* xm, const float* xv,
                       const float* psi_w, const float* psi_b, const float* pg, const float* pbt,
                       const float* pm, const float* pv) {
    int o = blockIdx.x, t = threadIdx.x;   // 64 blocks x 256 threads
    float invg = gg[o] * rsqrtf(gv[o] + 1e-5f);
    float invx = xg[o] * rsqrtf(xv[o] + 1e-5f);
    d_WfT[t*64 + o]       = Wg_w[o*256 + t] * invg;
    d_WfT[(256+t)*64 + o] = Wx_w[o*256 + t] * invx;
    if (t == 0) {
        d_bias[o] = (Wg_b[o] - gm[o]) * invg + gb[o]
                  + (Wx_b[o] - xm[o]) * invx + xb[o];
    }
    if (o == 0 && t < 64) {
        float invp = pg[0] * rsqrtf(pv[0] + 1e-5f);
        d_wp[t] = psi_w[t] * invp;
        if (t == 0) d_bp[0] = (psi_b[0] - pm[0]) * invp + pbt[0];
    }
}

// ---------------- psi = relu(BN(Wg g) + BN(Wx x)) ----------------
// grid (16, 8), 256 threads; each thread = 1 position, all 64 out channels (as 32 f32x2)
__global__ void __launch_bounds__(256) k_psi(const float* __restrict__ g, const float* __restrict__ x) {
    __shared__ float in_s[16*256];
    __shared__ float w_s[16*64];
    int b = blockIdx.y, p0 = blockIdx.x*256, t = threadIdx.x;
    ull acc2[32];
#pragma unroll
    for (int q = 0; q < 32; q++) acc2[q] = 0ull;
    for (int cb = 0; cb < 512; cb += 16) {
        __syncthreads();
#pragma unroll
        for (int r = 0; r < 16; r++) {
            int c = cb + r;
            const float* src = (c < 256) ? (g + ((size_t)b*256 + c)*HWn + p0)
                                         : (x + ((size_t)b*256 + (c-256))*HWn + p0);
            in_s[r*256 + t] = src[t];
        }
        for (int i = t; i < 16*64; i += 256)
            w_s[i] = d_WfT[(cb + (i >> 6))*64 + (i & 63)];
        __syncthreads();
#pragma unroll
        for (int r = 0; r < 16; r++) {
            float v = in_s[r*256 + t];
            ull v2 = pk2(v, v);
            const ull* w2 = (const ull*)&w_s[r*64];
#pragma unroll
            for (int q = 0; q < 32; q++) acc2[q] = ffma2(v2, w2[q], acc2[q]);
        }
    }
#pragma unroll
    for (int q = 0; q < 32; q++) {
        float lo, hi; upk2(acc2[q], lo, hi);
        lo += d_bias[2*q];  hi += d_bias[2*q+1];
        size_t base = ((size_t)b*Cn + 2*q)*HWn + p0 + t;
        d_psi[base]       = fmaxf(lo, 0.f);
        d_psi[base + HWn] = fmaxf(hi, 0.f);
    }
}

// ---------------- fb/fc/fd = small 1x1 convs of psi ----------------
// grid (16,8), 256 threads, dynamic smem
__global__ void __launch_bounds__(256) k_small(const float* __restrict__ pb_w, const float* __restrict__ pb_b,
                                               const float* __restrict__ pc_w, const float* __restrict__ pc_b,
                                               const float* __restrict__ pd_w, const float* __restrict__ pd_b) {
    extern __shared__ float smm[];
    float* psi_s  = smm;              // 64*256
    float* w_s    = smm + 64*256;     // 80*64
    float* bias_s = w_s + 80*64;      // 80
    int b = blockIdx.y, p0 = blockIdx.x*256, t = threadIdx.x;
    for (int i = t; i < 80*64; i += 256) {
        int o = i >> 6, c = i & 63;
        float w;
        if (o < 8)       w = pb_w[o*64 + c];
        else if (o < 16) w = pc_w[(o-8)*64 + c];
        else             w = pd_w[(o-16)*64 + c];
        w_s[i] = w;
    }
    if (t < 80) bias_s[t] = (t < 8) ? pb_b[t] : (t < 16 ? pc_b[t-8] : pd_b[t-16]);
    for (int c = 0; c < 64; c++)
        psi_s[c*256 + t] = d_psi[((size_t)b*Cn + c)*HWn + p0 + t];
    __syncthreads();
    float acc[80];
#pragma unroll
    for (int o = 0; o < 80; o++) acc[o] = bias_s[o];
    for (int c = 0; c < 64; c++) {
        float v = psi_s[c*256 + t];
#pragma unroll
        for (int o = 0; o < 80; o++) acc[o] += w_s[o*64 + c] * v;
    }
#pragma unroll
    for (int k = 0; k < 8; k++) d_fb[((size_t)b*8 + k)*HWn + p0 + t] = acc[k];
#pragma unroll
    for (int k = 0; k < 8; k++) d_fc[((size_t)b*8 + k)*HWn + p0 + t] = acc[8 + k];
#pragma unroll
    for (int c = 0; c < 64; c++) d_fd[((size_t)b*Cn + c)*HWn + p0 + t] = acc[16 + c];
}

// ---------------- CAM gram partials: att[b,ci,cj] over p-segment ----------------
// grid (8 seg, 8 b), 256 threads
__global__ void __launch_bounds__(256) k_cam_att() {
    __shared__ float psi_s[64*129];
    int b = blockIdx.y, seg = blockIdx.x, t = threadIdx.x;
    int ci = t & 63, cjb = (t >> 6) * 16;
    float acc[16];
#pragma unroll
    for (int q = 0; q < 16; q++) acc[q] = 0.f;
    for (int pc = 0; pc < 512; pc += 128) {
        __syncthreads();
        for (int i = t; i < 64*128; i += 256) {
            int c = i >> 7, p = i & 127;
            psi_s[c*129 + p] = d_psi[((size_t)b*Cn + c)*HWn + seg*512 + pc + p];
        }
        __syncthreads();
        for (int p = 0; p < 128; p++) {
            float a = psi_s[ci*129 + p];
#pragma unroll
            for (int q = 0; q < 16; q++) acc[q] += a * psi_s[(cjb + q)*129 + p];
        }
    }
#pragma unroll
    for (int q = 0; q < 16; q++)
        d_attp[seg*(Bn*64*64) + (b*64 + ci)*64 + cjb + q] = acc[q];
}

// ---------------- CAM softmax of (rowmax - att) ----------------
__global__ void k_cam_soft() {
    int b = blockIdx.x, ci = threadIdx.x;   // 8 blocks x 64 threads
    float v[64];
#pragma unroll
    for (int d = 0; d < 64; d++) {
        float s = 0.f;
#pragma unroll
        for (int sgm = 0; sgm < 8; sgm++) s += d_attp[sgm*(Bn*64*64) + (b*64 + ci)*64 + d];
        v[d] = s;
    }
    float mx = -1e30f, mn = 1e30f;
#pragma unroll
    for (int d = 0; d < 64; d++) { mx = fmaxf(mx, v[d]); mn = fminf(mn, v[d]); }
    float m2 = mx - mn;   // max of (mx - v)
    float ssum = 0.f;
#pragma unroll
    for (int d = 0; d < 64; d++) { float e = __expf((mx - v[d]) - m2); v[d] = e; ssum += e; }
    float inv = 1.f / ssum;
#pragma unroll
    for (int d = 0; d < 64; d++) d_attw[b*4096 + ci*64 + d] = v[d] * inv;
}

// ---------------- CAM out: cam = beta * (attw @ psi) + psi ----------------
// grid (16,8), 256 threads, dynamic smem
__global__ void __launch_bounds__(256) k_cam_out(const float* __restrict__ beta_p) {
    extern __shared__ float smm[];
    float* w_s   = smm;           // 4096
    float* psi_s = smm + 4096;    // 64*256
    int b = blockIdx.y, p0 = blockIdx.x*256, t = threadIdx.x;
    for (int i = t; i < 4096; i += 256) w_s[i] = d_attw[b*4096 + i];
    for (int c = 0; c < 64; c++)
        psi_s[c*256 + t] = d_psi[((size_t)b*Cn + c)*HWn + p0 + t];
    __syncthreads();
    float acc[64];
#pragma unroll
    for (int c = 0; c < 64; c++) acc[c] = 0.f;
    for (int d = 0; d < 64; d++) {
        float v = psi_s[d*256 + t];
#pragma unroll
        for (int c = 0; c < 64; c++) acc[c] += w_s[c*64 + d] * v;
    }
    float beta = beta_p[0];
#pragma unroll
    for (int c = 0; c < 64; c++)
        d_cam[((size_t)b*Cn + c)*HWn + p0 + t] = beta * acc[c] + psi_s[c*256 + t];
}

// ---------------- PAM: flash-attention over positions ----------------
// grid (32 I-tiles, 8 b), 256 threads, dynamic smem 60416B.
// TI=128 rows (i), TJ=64 cols (j). Online softmax, fd accumulated with f32x2.
__global__ void __launch_bounds__(256) k_pam(const float* __restrict__ alpha_p) {
    extern __shared__ float sm[];
    float* fb_s = sm;                 // 8*128   = 1024
    float* fc_s = fb_s + 1024;        // 8*64    = 512
    float* fd_s = fc_s + 512;         // 64*68   = 4352 (layout [j][c], pad 68)
    float* p_s  = fd_s + 4352;        // 128*65  = 8320 (layout [i][j], pad 65)
    float* m_s  = p_s + 8320;         // 128
    float* z_s  = m_s + 128;          // 128
    float* sc_s = z_s + 128;          // 128
    float* pm_s = sc_s + 128;         // 256
    float* ps_s = pm_s + 256;         // 256
    int b = blockIdx.y, I0 = blockIdx.x * 128, t = threadIdx.x;
    int iT = t & 127;                 // row handled in phases A/B2/C
    int jh = t >> 7;                  // j-half in phase A/B2; channel group in C
    for (int idx = t; idx < 1024; idx += 256)
        fb_s[idx] = d_fb[((size_t)b*8 + (idx >> 7))*HWn + I0 + (idx & 127)];
    if (t < 128) { m_s[t] = -1e30f; z_s[t] = 0.f; }
    ull acc2[16];
#pragma unroll
    for (int q = 0; q < 16; q++) acc2[q] = 0ull;
    __syncthreads();

    for (int jt = 0; jt < 64; jt++) {
        int j0 = jt * 64;
        __syncthreads();   // previous phase C finished with p_s/fd_s
        for (int idx = t; idx < 512; idx += 256)
            fc_s[idx] = d_fc[((size_t)b*8 + (idx >> 6))*HWn + j0 + (idx & 63)];
        for (int idx = t; idx < 4096; idx += 256) {
            int c = idx >> 6, j = idx & 63;
            fd_s[j*68 + c] = d_fd[((size_t)b*Cn + c)*HWn + j0 + j];
        }
        __syncthreads();
        // --- Phase A: energies e = fb^T fc, per-thread 32 j of one row ---
        {
            ull fb2[8];
#pragma unroll
            for (int k = 0; k < 8; k++) { float f = fb_s[k*128 + iT]; fb2[k] = pk2(f, f); }
            float mx = -1e30f;
#pragma unroll
            for (int jj = 0; jj < 32; jj += 2) {
                int j = jh*32 + jj;
                ull e2 = 0ull;
#pragma unroll
                for (int k = 0; k < 8; k++)
                    e2 = ffma2(fb2[k], *(const ull*)&fc_s[k*64 + j], e2);
                float lo, hi; upk2(e2, lo, hi);
                p_s[iT*65 + j]     = lo;
                p_s[iT*65 + j + 1] = hi;
                mx = fmaxf(mx, fmaxf(lo, hi));
            }
            pm_s[t] = mx;
        }
        __syncthreads();
        // --- Phase B: running max update ---
        if (t < 128) {
            float tm   = fmaxf(pm_s[t], pm_s[t + 128]);
            float mold = m_s[t];
            float mnew = fmaxf(mold, tm);
            sc_s[t] = __expf(mold - mnew);
            m_s[t]  = mnew;
        }
        __syncthreads();
        // --- Phase B2: exponentiate + partial sums ---
        {
            float mnew = m_s[iT];
            float s = 0.f;
#pragma unroll
            for (int jj = 0; jj < 32; jj++) {
                int j = jh*32 + jj;
                float p = __expf(p_s[iT*65 + j] - mnew);
                p_s[iT*65 + j] = p;
                s += p;
            }
            ps_s[t] = s;
        }
        __syncthreads();
        if (t < 128) z_s[t] = z_s[t] * sc_s[t] + ps_s[t] + ps_s[t + 128];
        // --- Phase C: acc[c,i] = acc*scale + sum_j p[i,j]*fd[c,j] (f32x2 over channel pairs) ---
        {
            float sc = sc_s[iT];
            ull sc2 = pk2(sc, sc);
#pragma unroll
            for (int q = 0; q < 16; q++) acc2[q] = fmul2(acc2[q], sc2);
            for (int j = 0; j < 64; j++) {
                float p = p_s[iT*65 + j];
                ull p2 = pk2(p, p);
                const ull* f2 = (const ull*)&fd_s[j*68 + jh*32];
#pragma unroll
                for (int q = 0; q < 16; q++) acc2[q] = ffma2(p2, f2[q], acc2[q]);
            }
        }
    }
    __syncthreads();
    float alpha = alpha_p[0];
    float invz = alpha / z_s[iT];
#pragma unroll
    for (int q = 0; q < 16; q++) {
        float lo, hi; upk2(acc2[q], lo, hi);
        int c0 = jh*32 + 2*q;
        size_t b0 = ((size_t)b*Cn + c0)*HWn + I0 + iT;
        d_pam[b0]       = lo * invz + d_psi[b0];
        d_pam[b0 + HWn] = hi * invz + d_psi[b0 + HWn];
    }
}

// ---------------- gate: da = sigmoid(BN(psi_w . (cam*pam))) ----------------
__global__ void __launch_bounds__(256) k_gate() {
    __shared__ float wp_s[64];
    int b = blockIdx.y, p0 = blockIdx.x*256, t = threadIdx.x;
    if (t < 64) wp_s[t] = d_wp[t];
    __syncthreads();
    float acc = d_bp[0];
    size_t base = ((size_t)b*Cn)*HWn + p0 + t;
#pragma unroll 8
    for (int c = 0; c < 64; c++) {
        size_t idx = base + (size_t)c*HWn;
        acc += wp_s[c] * d_cam[idx] * d_pam[idx];
    }
    d_da[b*HWn + p0 + t] = 1.f / (1.f + __expf(-acc));
}

// ---------------- out = x * da ----------------
__global__ void __launch_bounds__(256) k_mul(const float* __restrict__ x, float* __restrict__ out) {
    int idx = blockIdx.x * 256 + threadIdx.x;   // float4 index, 2^21 total
    float4 v = ((const float4*)x)[idx];
    int b  = idx >> 18;            // 256ch * 1024 f4/row
    int p4 = idx & 1023;
    float4 dv = ((const float4*)d_da)[b*1024 + p4];
    float4 o;
    o.x = v.x * dv.x; o.y = v.y * dv.y; o.z = v.z * dv.z; o.w = v.w * dv.w;
    ((float4*)out)[idx] = o;
}

// ---------------- launch ----------------
extern "C" void kernel_launch(void* const* d_in, const int* in_sizes, int n_in,
                              void* d_out, int out_size) {
    const float* g    = (const float*)d_in[0];
    const float* x    = (const float*)d_in[1];

    cudaFuncSetAttribute(k_small,   cudaFuncAttributeMaxDynamicSharedMemorySize, (64*256 + 80*64 + 80)*4);
    cudaFuncSetAttribute(k_cam_out, cudaFuncAttributeMaxDynamicSharedMemorySize, (4096 + 64*256)*4);
    cudaFuncSetAttribute(k_pam,     cudaFuncAttributeMaxDynamicSharedMemorySize, 15104*4);

    k_prep<<<64, 256>>>((const float*)d_in[2],  (const float*)d_in[3],  (const float*)d_in[4],
                        (const float*)d_in[5],  (const float*)d_in[6],  (const float*)d_in[7],
                        (const float*)d_in[8],  (const float*)d_in[9],  (const float*)d_in[10],
                        (const float*)d_in[11], (const float*)d_in[12], (const float*)d_in[13],
                        (const float*)d_in[14], (const float*)d_in[15], (const float*)d_in[16],
                        (const float*)d_in[17], (const float*)d_in[18], (const float*)d_in[19]);

    k_psi<<<dim3(16, 8), 256>>>(g, x);

    k_small<<<dim3(16, 8), 256, (64*256 + 80*64 + 80)*4>>>(
        (const float*)d_in[20], (const float*)d_in[21],
        (const float*)d_in[22], (const float*)d_in[23],
        (const float*)d_in[24], (const float*)d_in[25]);

    k_cam_att<<<dim3(8, 8), 256>>>();
    k_cam_soft<<<8, 64>>>();
    k_cam_out<<<dim3(16, 8), 256, (4096 + 64*256)*4>>>((const float*)d_in[27]);

    k_pam<<<dim3(32, 8), 256, 15104*4>>>((const float*)d_in[26]);

    k_gate<<<dim3(16, 8), 256>>>();
    k_mul<<<8192, 256>>>(x, (float*)d_out);
}

// round 2
// speedup vs baseline: 1.2292x; 1.2292x over previous
#include <cuda_runtime.h>
#include <cuda_bf16.h>
#include <math.h>

typedef unsigned long long ull;

#define Bn 8
#define Cn 64
#define HWn 4096

// ---------------- scratch (device globals; no allocs allowed) ----------------
__device__ __align__(16) float d_psi[Bn*Cn*HWn];     // 8MB
__device__ __align__(16) float d_fb [Bn*8*HWn];
__device__ __align__(16) float d_fc [Bn*8*HWn];
__device__ __align__(16) float d_fdT[Bn*HWn*Cn];     // 8MB, [b][pos][c]
__device__ __align__(16) float d_cam[Bn*Cn*HWn];     // 8MB
__device__ __align__(16) float d_pam[Bn*Cn*HWn];     // 8MB
__device__ __align__(16) float d_attp[32*Bn*64*64];  // CAM partial gram (32 segments)
__device__ __align__(16) float d_attw[Bn*64*64];     // CAM softmaxed weights
__device__ __align__(16) float d_WfT[512*64];        // folded fused weights, [c][o]
__device__ __align__(16) float d_bias[64];
__device__ __align__(16) float d_wp[64];
__device__ __align__(16) float d_bp[1];
__device__ __align__(16) float d_da[Bn*HWn];

// ---------------- f32x2 helpers ----------------
__device__ __forceinline__ ull pk2(float lo, float hi) {
    ull r; asm("mov.b64 %0, {%1, %2};" : "=l"(r) : "f"(lo), "f"(hi)); return r;
}
__device__ __forceinline__ void upk2(ull v, float& lo, float& hi) {
    asm("mov.b64 {%0, %1}, %2;" : "=f"(lo), "=f"(hi) : "l"(v));
}
__device__ __forceinline__ ull ffma2(ull a, ull b, ull c) {
    ull d; asm("fma.rn.f32x2 %0, %1, %2, %3;" : "=l"(d) : "l"(a), "l"(b), "l"(c)); return d;
}
__device__ __forceinline__ ull fmul2(ull a, ull b) {
    ull d; asm("mul.rn.f32x2 %0, %1, %2;" : "=l"(d) : "l"(a), "l"(b)); return d;
}

// ---------------- prep: fold BN into conv weights ----------------
__global__ void k_prep(const float* Wg_w, const float* Wg_b, const float* gg, const float* gb,
                       const float* gm, const float* gv,
                       const float* Wx_w, const float* Wx_b, const float* xg, const float* xb,
                       const float* xm, const float* xv,
                       const float* psi_w, const float* psi_b, const float* pg, const float* pbt,
                       const float* pm, const float* pv) {
    int o = blockIdx.x, t = threadIdx.x;   // 64 blocks x 256 threads
    float invg = gg[o] * rsqrtf(gv[o] + 1e-5f);
    float invx = xg[o] * rsqrtf(xv[o] + 1e-5f);
    d_WfT[t*64 + o]       = Wg_w[o*256 + t] * invg;
    d_WfT[(256+t)*64 + o] = Wx_w[o*256 + t] * invx;
    if (t == 0) {
        d_bias[o] = (Wg_b[o] - gm[o]) * invg + gb[o]
                  + (Wx_b[o] - xm[o]) * invx + xb[o];
    }
    if (o == 0 && t < 64) {
        float invp = pg[0] * rsqrtf(pv[0] + 1e-5f);
        d_wp[t] = psi_w[t] * invp;
        if (t == 0) d_bp[0] = (psi_b[0] - pm[0]) * invp + pbt[0];
    }
}

// ---------------- psi = relu(BN(Wg g) + BN(Wx x)) ----------------
// grid (32, 8), 256 threads; thread tile: 8 pos x 4 out-ch (f32x2 packed)
__global__ void __launch_bounds__(256) k_psi(const float* __restrict__ g, const float* __restrict__ x) {
    __shared__ __align__(16) float in_s[32*128];
    __shared__ __align__(16) float w_s[32*64];
    int b = blockIdx.y, p0 = blockIdx.x*128, t = threadIdx.x;
    int cg = t & 15, pg = t >> 4;
    ull acc[16];
#pragma unroll
    for (int q = 0; q < 16; q++) acc[q] = 0ull;
    for (int cb = 0; cb < 512; cb += 32) {
        __syncthreads();
        for (int idx = t; idx < 4096; idx += 256) {
            int r = idx >> 7, p = idx & 127;
            int c = cb + r;
            const float* src = (c < 256) ? (g + ((size_t)b*256 + c)*HWn)
                                         : (x + ((size_t)b*256 + (c-256))*HWn);
            in_s[idx] = src[p0 + p];
        }
        for (int idx = t; idx < 2048; idx += 256)
            w_s[idx] = d_WfT[(cb + (idx >> 6))*64 + (idx & 63)];
        __syncthreads();
#pragma unroll 4
        for (int c = 0; c < 32; c++) {
            float4 w = *(const float4*)&w_s[c*64 + cg*4];
            ull w01 = pk2(w.x, w.y), w23 = pk2(w.z, w.w);
            float4 a0 = *(const float4*)&in_s[c*128 + pg*8];
            float4 a1 = *(const float4*)&in_s[c*128 + pg*8 + 4];
            float av[8] = {a0.x,a0.y,a0.z,a0.w,a1.x,a1.y,a1.z,a1.w};
#pragma unroll
            for (int r = 0; r < 8; r++) {
                ull p2 = pk2(av[r], av[r]);
                acc[2*r]   = ffma2(p2, w01, acc[2*r]);
                acc[2*r+1] = ffma2(p2, w23, acc[2*r+1]);
            }
        }
    }
    // epilogue: bias + relu; positions contiguous per channel -> STG.128
    float vals[8][4];
#pragma unroll
    for (int r = 0; r < 8; r++) {
        float v0,v1,v2,v3;
        upk2(acc[2*r],   v0, v1);
        upk2(acc[2*r+1], v2, v3);
        vals[r][0]=v0; vals[r][1]=v1; vals[r][2]=v2; vals[r][3]=v3;
    }
#pragma unroll
    for (int cc = 0; cc < 4; cc++) {
        float bi = d_bias[cg*4 + cc];
        float4 o0 = make_float4(fmaxf(vals[0][cc]+bi,0.f), fmaxf(vals[1][cc]+bi,0.f),
                                fmaxf(vals[2][cc]+bi,0.f), fmaxf(vals[3][cc]+bi,0.f));
        float4 o1 = make_float4(fmaxf(vals[4][cc]+bi,0.f), fmaxf(vals[5][cc]+bi,0.f),
                                fmaxf(vals[6][cc]+bi,0.f), fmaxf(vals[7][cc]+bi,0.f));
        size_t base = ((size_t)b*Cn + cg*4 + cc)*HWn + p0 + pg*8;
        *(float4*)&d_psi[base]     = o0;
        *(float4*)&d_psi[base + 4] = o1;
    }
}

// ---------------- fb/fc/fdT = small 1x1 convs of psi ----------------
// grid (32,8), 256 threads, dynamic smem. Thread = 1 pos, 40 of 80 outputs.
__global__ void __launch_bounds__(256) k_small(const float* __restrict__ pb_w, const float* __restrict__ pb_b,
                                               const float* __restrict__ pc_w, const float* __restrict__ pc_b,
                                               const float* __restrict__ pd_w, const float* __restrict__ pd_b) {
    extern __shared__ float smm[];
    float* A      = smm;              // psi tile 64*128 = 8192, reused as ts 64*130 = 8320
    float* w_s    = smm + 8320;       // [c][o] 64*80 = 5120
    float* bias_s = w_s + 5120;       // 80
    int b = blockIdx.y, p0 = blockIdx.x*128, t = threadIdx.x;
    int pos = t & 127, half = t >> 7;
    for (int idx = t; idx < 8192; idx += 256) {
        int c = idx >> 7, p = idx & 127;
        A[idx] = d_psi[((size_t)b*Cn + c)*HWn + p0 + p];
    }
    for (int idx = t; idx < 5120; idx += 256) {
        int c = idx / 80, o = idx % 80;
        float w;
        if (o < 8)       w = pb_w[o*64 + c];
        else if (o < 16) w = pc_w[(o-8)*64 + c];
        else             w = pd_w[(o-16)*64 + c];
        w_s[idx] = w;
    }
    if (t < 80) bias_s[t] = (t < 8) ? pb_b[t] : (t < 16 ? pc_b[t-8] : pd_b[t-16]);
    __syncthreads();
    int o0 = half*40;
    ull acc[20];
#pragma unroll
    for (int q = 0; q < 20; q++) acc[q] = pk2(bias_s[o0 + 2*q], bias_s[o0 + 2*q + 1]);
    for (int c = 0; c < 64; c++) {
        float v = A[c*128 + pos];
        ull v2 = pk2(v, v);
        const ull* wr = (const ull*)&w_s[c*80 + o0];
#pragma unroll
        for (int q = 0; q < 20; q++) acc[q] = ffma2(v2, wr[q], acc[q]);
    }
    __syncthreads();   // done reading A (psi); reuse as ts
#pragma unroll
    for (int q = 0; q < 20; q++) {
        float v0, v1; upk2(acc[q], v0, v1);
        int o = o0 + 2*q;
#pragma unroll
        for (int s = 0; s < 2; s++) {
            float v = s ? v1 : v0;
            int oo = o + s;
            if (oo < 8)       d_fb[((size_t)b*8 + oo)*HWn + p0 + pos] = v;
            else if (oo < 16) d_fc[((size_t)b*8 + (oo-8))*HWn + p0 + pos] = v;
            else              A[(oo-16)*130 + pos] = v;   // stage fd transposed
        }
    }
    __syncthreads();
    for (int idx = t; idx < 8192; idx += 256) {
        int p = idx >> 6, c = idx & 63;
        d_fdT[((size_t)b*HWn + p0 + p)*64 + c] = A[c*130 + p];
    }
}

// ---------------- CAM gram partials: att[b,ci,cj] over p-segment ----------------
// grid (32 seg, 8 b), 256 threads; thread tile 4ci x 4cj
__global__ void __launch_bounds__(256) k_cam_att() {
    __shared__ float psi_s[64*129];
    int b = blockIdx.y, seg = blockIdx.x, t = threadIdx.x;
    int cjg = t & 15, cig = t >> 4;
    float acc[4][4];
#pragma unroll
    for (int r = 0; r < 4; r++)
#pragma unroll
        for (int q = 0; q < 4; q++) acc[r][q] = 0.f;
    for (int idx = t; idx < 8192; idx += 256) {
        int c = idx >> 7, p = idx & 127;
        psi_s[c*129 + p] = d_psi[((size_t)b*Cn + c)*HWn + seg*128 + p];
    }
    __syncthreads();
    for (int p = 0; p < 128; p++) {
        float a0 = psi_s[(cig*4+0)*129 + p];
        float a1 = psi_s[(cig*4+1)*129 + p];
        float a2 = psi_s[(cig*4+2)*129 + p];
        float a3 = psi_s[(cig*4+3)*129 + p];
        float b0 = psi_s[(cjg*4+0)*129 + p];
        float b1 = psi_s[(cjg*4+1)*129 + p];
        float b2 = psi_s[(cjg*4+2)*129 + p];
        float b3 = psi_s[(cjg*4+3)*129 + p];
        acc[0][0]+=a0*b0; acc[0][1]+=a0*b1; acc[0][2]+=a0*b2; acc[0][3]+=a0*b3;
        acc[1][0]+=a1*b0; acc[1][1]+=a1*b1; acc[1][2]+=a1*b2; acc[1][3]+=a1*b3;
        acc[2][0]+=a2*b0; acc[2][1]+=a2*b1; acc[2][2]+=a2*b2; acc[2][3]+=a2*b3;
        acc[3][0]+=a3*b0; acc[3][1]+=a3*b1; acc[3][2]+=a3*b2; acc[3][3]+=a3*b3;
    }
#pragma unroll
    for (int r = 0; r < 4; r++)
#pragma unroll
        for (int q = 0; q < 4; q++)
            d_attp[seg*(Bn*64*64) + (b*64 + cig*4 + r)*64 + cjg*4 + q] = acc[r][q];
}

// ---------------- CAM softmax of (rowmax - att) ----------------
__global__ void k_cam_soft() {
    int b = blockIdx.x, ci = threadIdx.x;   // 8 blocks x 64 threads
    float v[64];
#pragma unroll
    for (int d = 0; d < 64; d++) {
        float s = 0.f;
        for (int sgm = 0; sgm < 32; sgm++) s += d_attp[sgm*(Bn*64*64) + (b*64 + ci)*64 + d];
        v[d] = s;
    }
    float mx = -1e30f, mn = 1e30f;
#pragma unroll
    for (int d = 0; d < 64; d++) { mx = fmaxf(mx, v[d]); mn = fminf(mn, v[d]); }
    float m2 = mx - mn;   // max of (mx - v)
    float ssum = 0.f;
#pragma unroll
    for (int d = 0; d < 64; d++) { float e = __expf((mx - v[d]) - m2); v[d] = e; ssum += e; }
    float inv = 1.f / ssum;
#pragma unroll
    for (int d = 0; d < 64; d++) d_attw[b*4096 + ci*64 + d] = v[d] * inv;
}

// ---------------- CAM out: cam = beta * (attw @ psi) + psi ----------------
// grid (16,8), 256 threads, dynamic smem
__global__ void __launch_bounds__(256) k_cam_out(const float* __restrict__ beta_p) {
    extern __shared__ float smm[];
    float* w_s   = smm;           // 4096
    float* psi_s = smm + 4096;    // 64*256
    int b = blockIdx.y, p0 = blockIdx.x*256, t = threadIdx.x;
    for (int i = t; i < 4096; i += 256) w_s[i] = d_attw[b*4096 + i];
    for (int c = 0; c < 64; c++)
        psi_s[c*256 + t] = d_psi[((size_t)b*Cn + c)*HWn + p0 + t];
    __syncthreads();
    float acc[64];
#pragma unroll
    for (int c = 0; c < 64; c++) acc[c] = 0.f;
    for (int d = 0; d < 64; d++) {
        float v = psi_s[d*256 + t];
#pragma unroll
        for (int c = 0; c < 64; c++) acc[c] += w_s[c*64 + d] * v;
    }
    float beta = beta_p[0];
#pragma unroll
    for (int c = 0; c < 64; c++)
        d_cam[((size_t)b*Cn + c)*HWn + p0 + t] = beta * acc[c] + psi_s[c*256 + t];
}

// ---------------- PAM: flash-attention over positions ----------------
// grid (32 I-tiles, 8 b), 256 threads. TI=128, TJ=64.
// Thread tile: 8 i-rows x 4 channels (phase C) / 8 i-rows x 4 j-cols (phase A).
__global__ void __launch_bounds__(256) k_pam(const float* __restrict__ alpha_p) {
    extern __shared__ __align__(16) float sm[];
    float* fb_s = sm;                 // 8*128   = 1024
    float* fc_s = fb_s + 1024;        // 8*64    = 512
    float* fd_s = fc_s + 512;         // 64*68   = 4352 ([j][c], pad 68)
    float* p_s  = fd_s + 4352;        // 128*68  = 8704 ([i][j], pad 68); reused as ts 64*129
    float* pm_s = p_s + 8704;         // 128*17  = 2176
    float* ps_s = pm_s + 2176;        // 2176
    float* m_s  = ps_s + 2176;        // 128
    float* z_s  = m_s + 128;          // 128
    float* sc_s = z_s + 128;          // 128   -> total 19328 floats
    int b = blockIdx.y, I0 = blockIdx.x * 128, t = threadIdx.x;
    int cg = t & 15, ig = t >> 4;     // cg: j-group (A) / ch-group (C); ig: 8-row group
    int i0 = ig * 8;
    for (int idx = t; idx < 1024; idx += 256)
        fb_s[idx] = d_fb[((size_t)b*8 + (idx >> 7))*HWn + I0 + (idx & 127)];
    if (t < 128) { m_s[t] = -1e30f; z_s[t] = 0.f; }
    ull acc[16];
#pragma unroll
    for (int q = 0; q < 16; q++) acc[q] = 0ull;
    __syncthreads();

    for (int jt = 0; jt < 64; jt++) {
        int j0 = jt * 64;
        for (int idx = t; idx < 512; idx += 256)
            fc_s[idx] = d_fc[((size_t)b*8 + (idx >> 6))*HWn + j0 + (idx & 63)];
        for (int idx = t; idx < 4096; idx += 256) {
            int j = idx >> 6, c = idx & 63;
            fd_s[j*68 + c] = d_fdT[((size_t)b*HWn + j0 + j)*64 + c];
        }
        __syncthreads();
        // --- Phase A: e[8i][4j] = fb^T fc ---
        {
            ull fc2[16];
#pragma unroll
            for (int k = 0; k < 8; k++) {
                float4 f = *(const float4*)&fc_s[k*64 + cg*4];
                fc2[2*k]   = pk2(f.x, f.y);
                fc2[2*k+1] = pk2(f.z, f.w);
            }
#pragma unroll
            for (int r = 0; r < 8; r++) {
                int i = i0 + r;
                ull e0 = 0ull, e1 = 0ull;
#pragma unroll
                for (int k = 0; k < 8; k++) {
                    float fv = fb_s[k*128 + i];
                    ull f2 = pk2(fv, fv);
                    e0 = ffma2(f2, fc2[2*k],   e0);
                    e1 = ffma2(f2, fc2[2*k+1], e1);
                }
                float ea, eb, ec, ed;
                upk2(e0, ea, eb); upk2(e1, ec, ed);
                *(float4*)&p_s[i*68 + cg*4] = make_float4(ea, eb, ec, ed);
                pm_s[i*17 + cg] = fmaxf(fmaxf(ea, eb), fmaxf(ec, ed));
            }
        }
        __syncthreads();
        // --- Phase B: running max ---
        if (t < 128) {
            float tm = -1e30f;
#pragma unroll
            for (int q = 0; q < 16; q++) tm = fmaxf(tm, pm_s[t*17 + q]);
            float mold = m_s[t];
            float mnew = fmaxf(mold, tm);
            sc_s[t] = __expf(mold - mnew);
            m_s[t] = mnew;
        }
        __syncthreads();
        // --- Phase B2: exponentiate + partial sums ---
#pragma unroll
        for (int r = 0; r < 8; r++) {
            int i = i0 + r;
            float mnew = m_s[i];
            float4 ev = *(const float4*)&p_s[i*68 + cg*4];
            ev.x = __expf(ev.x - mnew); ev.y = __expf(ev.y - mnew);
            ev.z = __expf(ev.z - mnew); ev.w = __expf(ev.w - mnew);
            *(float4*)&p_s[i*68 + cg*4] = ev;
            ps_s[i*17 + cg] = (ev.x + ev.y) + (ev.z + ev.w);
        }
        __syncthreads();
        if (t < 128) {
            float s = 0.f;
#pragma unroll
            for (int q = 0; q < 16; q++) s += ps_s[t*17 + q];
            z_s[t] = z_s[t]*sc_s[t] + s;
        }
        // --- Phase C: acc[8i][4c] += p[i][j] * fd[j][c] ---
#pragma unroll
        for (int r = 0; r < 8; r++) {
            float sc = sc_s[i0 + r];
            ull s2 = pk2(sc, sc);
            acc[2*r]   = fmul2(acc[2*r],   s2);
            acc[2*r+1] = fmul2(acc[2*r+1], s2);
        }
        for (int j4 = 0; j4 < 16; j4++) {
            float4 fda = *(const float4*)&fd_s[(j4*4+0)*68 + cg*4];
            float4 fdb = *(const float4*)&fd_s[(j4*4+1)*68 + cg*4];
            float4 fdc = *(const float4*)&fd_s[(j4*4+2)*68 + cg*4];
            float4 fdd = *(const float4*)&fd_s[(j4*4+3)*68 + cg*4];
            ull f2[8] = { pk2(fda.x,fda.y), pk2(fda.z,fda.w),
                          pk2(fdb.x,fdb.y), pk2(fdb.z,fdb.w),
                          pk2(fdc.x,fdc.y), pk2(fdc.z,fdc.w),
                          pk2(fdd.x,fdd.y), pk2(fdd.z,fdd.w) };
#pragma unroll
            for (int r = 0; r < 8; r++) {
                float4 p4 = *(const float4*)&p_s[(i0+r)*68 + j4*4];
                ull pa = pk2(p4.x, p4.x), pb = pk2(p4.y, p4.y);
                ull pc = pk2(p4.z, p4.z), pd = pk2(p4.w, p4.w);
                acc[2*r]   = ffma2(pa, f2[0], acc[2*r]);
                acc[2*r+1] = ffma2(pa, f2[1], acc[2*r+1]);
                acc[2*r]   = ffma2(pb, f2[2], acc[2*r]);
                acc[2*r+1] = ffma2(pb, f2[3], acc[2*r+1]);
                acc[2*r]   = ffma2(pc, f2[4], acc[2*r]);
                acc[2*r+1] = ffma2(pc, f2[5], acc[2*r+1]);
                acc[2*r]   = ffma2(pd, f2[6], acc[2*r]);
                acc[2*r+1] = ffma2(pd, f2[7], acc[2*r+1]);
            }
        }
        __syncthreads();   // protect fc/fd/p before next tile's loads
    }
    // --- epilogue: normalize, transpose via smem, add psi, write coalesced ---
    float alpha = alpha_p[0];
    float* ts = p_s;   // 64*129 = 8256 <= 8704
#pragma unroll
    for (int r = 0; r < 8; r++) {
        float invz = alpha / z_s[i0 + r];
        float v0, v1, v2, v3;
        upk2(acc[2*r],   v0, v1);
        upk2(acc[2*r+1], v2, v3);
        ts[(cg*4+0)*129 + i0+r] = v0 * invz;
        ts[(cg*4+1)*129 + i0+r] = v1 * invz;
        ts[(cg*4+2)*129 + i0+r] = v2 * invz;
        ts[(cg*4+3)*129 + i0+r] = v3 * invz;
    }
    __syncthreads();
    for (int idx = t; idx < 8192; idx += 256) {
        int c = idx >> 7, i = idx & 127;
        size_t o = ((size_t)b*Cn + c)*HWn + I0 + i;
        d_pam[o] = ts[c*129 + i] + d_psi[o];
    }
}

// ---------------- gate: da = sigmoid(BN(psi_w . (cam*pam))) ----------------
__global__ void __launch_bounds__(256) k_gate() {
    __shared__ float wp_s[64];
    int b = blockIdx.y, p0 = blockIdx.x*256, t = threadIdx.x;
    if (t < 64) wp_s[t] = d_wp[t];
    __syncthreads();
    float acc = d_bp[0];
    size_t base = ((size_t)b*Cn)*HWn + p0 + t;
#pragma unroll 8
    for (int c = 0; c < 64; c++) {
        size_t idx = base + (size_t)c*HWn;
        acc += wp_s[c] * d_cam[idx] * d_pam[idx];
    }
    d_da[b*HWn + p0 + t] = 1.f / (1.f + __expf(-acc));
}

// ---------------- out = x * da ----------------
__global__ void __launch_bounds__(256) k_mul(const float* __restrict__ x, float* __restrict__ out) {
    int idx = blockIdx.x * 256 + threadIdx.x;   // float4 index
    float4 v = ((const float4*)x)[idx];
    int b  = idx >> 18;
    int p4 = idx & 1023;
    float4 dv = ((const float4*)d_da)[b*1024 + p4];
    float4 o;
    o.x = v.x * dv.x; o.y = v.y * dv.y; o.z = v.z * dv.z; o.w = v.w * dv.w;
    ((float4*)out)[idx] = o;
}

// ---------------- launch ----------------
extern "C" void kernel_launch(void* const* d_in, const int* in_sizes, int n_in,
                              void* d_out, int out_size) {
    const float* g = (const float*)d_in[0];
    const float* x = (const float*)d_in[1];

    cudaFuncSetAttribute(k_small,   cudaFuncAttributeMaxDynamicSharedMemorySize, 13520*4);
    cudaFuncSetAttribute(k_cam_out, cudaFuncAttributeMaxDynamicSharedMemorySize, (4096 + 64*256)*4);
    cudaFuncSetAttribute(k_pam,     cudaFuncAttributeMaxDynamicSharedMemorySize, 19328*4);

    k_prep<<<64, 256>>>((const float*)d_in[2],  (const float*)d_in[3],  (const float*)d_in[4],
                        (const float*)d_in[5],  (const float*)d_in[6],  (const float*)d_in[7],
                        (const float*)d_in[8],  (const float*)d_in[9],  (const float*)d_in[10],
                        (const float*)d_in[11], (const float*)d_in[12], (const float*)d_in[13],
                        (const float*)d_in[14], (const float*)d_in[15], (const float*)d_in[16],
                        (const float*)d_in[17], (const float*)d_in[18], (const float*)d_in[19]);

    k_psi<<<dim3(32, 8), 256>>>(g, x);

    k_small<<<dim3(32, 8), 256, 13520*4>>>(
        (const float*)d_in[20], (const float*)d_in[21],
        (const float*)d_in[22], (const float*)d_in[23],
        (const float*)d_in[24], (const float*)d_in[25]);

    k_cam_att<<<dim3(32, 8), 256>>>();
    k_cam_soft<<<8, 64>>>();
    k_cam_out<<<dim3(16, 8), 256, (4096 + 64*256)*4>>>((const float*)d_in[27]);

    k_pam<<<dim3(32, 8), 256, 19328*4>>>((const float*)d_in[26]);

    k_gate<<<dim3(16, 8), 256>>>();
    k_mul<<<8192, 256>>>(x, (float*)d_out);
}

// round 4
// speedup vs baseline: 2.5739x; 2.0940x over previous
#include <cuda_runtime.h>
#include <cuda_bf16.h>
#include <math.h>
#include <stdint.h>

typedef unsigned long long ull;

#define Bn 8
#define Cn 64
#define HWn 4096

// ---------------- scratch (device globals; no allocs allowed) ----------------
__device__ __align__(16) float d_psi[Bn*Cn*HWn];     // 8MB
__device__ __align__(16) float d_fb [Bn*8*HWn];
__device__ __align__(16) float d_fc [Bn*8*HWn];
__device__ __align__(16) float d_fd [Bn*Cn*HWn];     // 8MB [b][c][j]
__device__ __align__(16) float d_cam[Bn*Cn*HWn];     // 8MB
__device__ __align__(16) float d_pam[Bn*Cn*HWn];     // 8MB
__device__ __align__(16) float d_attp[32*Bn*64*64];  // CAM partial gram
__device__ __align__(16) float d_attw[Bn*64*64];     // CAM softmaxed weights
__device__ __align__(16) float d_WfT[512*64];        // folded fused weights, [c][o]
__device__ __align__(16) float d_bias[64];
__device__ __align__(16) float d_wp[64];
__device__ __align__(16) float d_bp[1];
__device__ __align__(16) float d_cmax[8];            // max_j ||fc_j||  per batch
__device__ __align__(16) float d_da[Bn*HWn];

// ---------------- f32x2 helpers ----------------
__device__ __forceinline__ ull pk2(float lo, float hi) {
    ull r; asm("mov.b64 %0, {%1, %2};" : "=l"(r) : "f"(lo), "f"(hi)); return r;
}
__device__ __forceinline__ void upk2(ull v, float& lo, float& hi) {
    asm("mov.b64 {%0, %1}, %2;" : "=f"(lo), "=f"(hi) : "l"(v));
}
__device__ __forceinline__ ull ffma2(ull a, ull b, ull c) {
    ull d; asm("fma.rn.f32x2 %0, %1, %2, %3;" : "=l"(d) : "l"(a), "l"(b), "l"(c)); return d;
}

// ---------------- warp MMA helpers (sm_80+ path; compiles at compute_103) ----------------
__device__ __forceinline__ uint32_t smem_u32(const void* p) {
    uint32_t a;
    asm("{ .reg .u64 t; cvta.to.shared.u64 t, %1; cvt.u32.u64 %0, t; }" : "=r"(a) : "l"(p));
    return a;
}
#define SWZ(off) ((off) ^ (((off) >> 3) & 0x70))
__device__ __forceinline__ void ldsm_x4(uint32_t& r0, uint32_t& r1, uint32_t& r2, uint32_t& r3,
                                        uint32_t addr) {
    asm volatile("ldmatrix.sync.aligned.m8n8.x4.shared.b16 {%0,%1,%2,%3}, [%4];"
                 : "=r"(r0), "=r"(r1), "=r"(r2), "=r"(r3) : "r"(addr));
}
__device__ __forceinline__ void mma_bf16(float* d, const uint32_t* a, const uint32_t* b) {
    asm volatile(
        "mma.sync.aligned.m16n8k16.row.col.f32.bf16.bf16.f32 "
        "{%0,%1,%2,%3}, {%4,%5,%6,%7}, {%8,%9}, {%0,%1,%2,%3};"
        : "+f"(d[0]), "+f"(d[1]), "+f"(d[2]), "+f"(d[3])
        : "r"(a[0]), "r"(a[1]), "r"(a[2]), "r"(a[3]), "r"(b[0]), "r"(b[1]));
}
__device__ __forceinline__ uint32_t cvt_bf16x2(float a, float b) {
    // memory layout: lower half = a, upper half = b
    uint32_t r;
    asm("cvt.rn.satfinite.bf16x2.f32 %0, %1, %2;" : "=r"(r) : "f"(b), "f"(a));
    return r;
}

// ---------------- prep: fold BN into conv weights ----------------
__global__ void k_prep(const float* Wg_w, const float* Wg_b, const float* gg, const float* gb,
                       const float* gm, const float* gv,
                       const float* Wx_w, const float* Wx_b, const float* xg, const float* xb,
                       const float* xm, const float* xv,
                       const float* psi_w, const float* psi_b, const float* pg, const float* pbt,
                       const float* pm, const float* pv) {
    int o = blockIdx.x, t = threadIdx.x;
    float invg = gg[o] * rsqrtf(gv[o] + 1e-5f);
    float invx = xg[o] * rsqrtf(xv[o] + 1e-5f);
    d_WfT[t*64 + o]       = Wg_w[o*256 + t] * invg;
    d_WfT[(256+t)*64 + o] = Wx_w[o*256 + t] * invx;
    if (t == 0) {
        d_bias[o] = (Wg_b[o] - gm[o]) * invg + gb[o]
                  + (Wx_b[o] - xm[o]) * invx + xb[o];
    }
    if (o == 0 && t < 64) {
        float invp = pg[0] * rsqrtf(pv[0] + 1e-5f);
        d_wp[t] = psi_w[t] * invp;
        if (t == 0) d_bp[0] = (psi_b[0] - pm[0]) * invp + pbt[0];
    }
}

// ---------------- psi = relu(BN(Wg g) + BN(Wx x)) ----------------
__global__ void __launch_bounds__(256) k_psi(const float* __restrict__ g, const float* __restrict__ x) {
    __shared__ __align__(16) float in_s[32*128];
    __shared__ __align__(16) float w_s[32*64];
    int b = blockIdx.y, p0 = blockIdx.x*128, t = threadIdx.x;
    int cg = t & 15, pg = t >> 4;
    ull acc[16];
#pragma unroll
    for (int q = 0; q < 16; q++) acc[q] = 0ull;
    for (int cb = 0; cb < 512; cb += 32) {
        __syncthreads();
        for (int idx = t; idx < 4096; idx += 256) {
            int r = idx >> 7, p = idx & 127;
            int c = cb + r;
            const float* src = (c < 256) ? (g + ((size_t)b*256 + c)*HWn)
                                         : (x + ((size_t)b*256 + (c-256))*HWn);
            in_s[idx] = src[p0 + p];
        }
        for (int idx = t; idx < 2048; idx += 256)
            w_s[idx] = d_WfT[(cb + (idx >> 6))*64 + (idx & 63)];
        __syncthreads();
#pragma unroll 4
        for (int c = 0; c < 32; c++) {
            float4 w = *(const float4*)&w_s[c*64 + cg*4];
            ull w01 = pk2(w.x, w.y), w23 = pk2(w.z, w.w);
            float4 a0 = *(const float4*)&in_s[c*128 + pg*8];
            float4 a1 = *(const float4*)&in_s[c*128 + pg*8 + 4];
            float av[8] = {a0.x,a0.y,a0.z,a0.w,a1.x,a1.y,a1.z,a1.w};
#pragma unroll
            for (int r = 0; r < 8; r++) {
                ull p2 = pk2(av[r], av[r]);
                acc[2*r]   = ffma2(p2, w01, acc[2*r]);
                acc[2*r+1] = ffma2(p2, w23, acc[2*r+1]);
            }
        }
    }
    float vals[8][4];
#pragma unroll
    for (int r = 0; r < 8; r++) {
        float v0,v1,v2,v3;
        upk2(acc[2*r],   v0, v1);
        upk2(acc[2*r+1], v2, v3);
        vals[r][0]=v0; vals[r][1]=v1; vals[r][2]=v2; vals[r][3]=v3;
    }
#pragma unroll
    for (int cc = 0; cc < 4; cc++) {
        float bi = d_bias[cg*4 + cc];
        float4 o0 = make_float4(fmaxf(vals[0][cc]+bi,0.f), fmaxf(vals[1][cc]+bi,0.f),
                                fmaxf(vals[2][cc]+bi,0.f), fmaxf(vals[3][cc]+bi,0.f));
        float4 o1 = make_float4(fmaxf(vals[4][cc]+bi,0.f), fmaxf(vals[5][cc]+bi,0.f),
                                fmaxf(vals[6][cc]+bi,0.f), fmaxf(vals[7][cc]+bi,0.f));
        size_t base = ((size_t)b*Cn + cg*4 + cc)*HWn + p0 + pg*8;
        *(float4*)&d_psi[base]     = o0;
        *(float4*)&d_psi[base + 4] = o1;
    }
}

// ---------------- fb/fc/fd = small 1x1 convs of psi ----------------
__global__ void __launch_bounds__(256) k_small(const float* __restrict__ pb_w, const float* __restrict__ pb_b,
                                               const float* __restrict__ pc_w, const float* __restrict__ pc_b,
                                               const float* __restrict__ pd_w, const float* __restrict__ pd_b) {
    extern __shared__ float smm[];
    float* A      = smm;              // psi tile 64*128 = 8192
    float* w_s    = smm + 8192;       // [c][o] 64*80 = 5120
    float* bias_s = w_s + 5120;       // 80
    int b = blockIdx.y, p0 = blockIdx.x*128, t = threadIdx.x;
    int pos = t & 127, half = t >> 7;
    for (int idx = t; idx < 8192; idx += 256) {
        int c = idx >> 7, p = idx & 127;
        A[idx] = d_psi[((size_t)b*Cn + c)*HWn + p0 + p];
    }
    for (int idx = t; idx < 5120; idx += 256) {
        int c = idx / 80, o = idx % 80;
        float w;
        if (o < 8)       w = pb_w[o*64 + c];
        else if (o < 16) w = pc_w[(o-8)*64 + c];
        else             w = pd_w[(o-16)*64 + c];
        w_s[idx] = w;
    }
    if (t < 80) bias_s[t] = (t < 8) ? pb_b[t] : (t < 16 ? pc_b[t-8] : pd_b[t-16]);
    __syncthreads();
    int o0 = half*40;
    ull acc[20];
#pragma unroll
    for (int q = 0; q < 20; q++) acc[q] = pk2(bias_s[o0 + 2*q], bias_s[o0 + 2*q + 1]);
    for (int c = 0; c < 64; c++) {
        float v = A[c*128 + pos];
        ull v2 = pk2(v, v);
        const ull* wr = (const ull*)&w_s[c*80 + o0];
#pragma unroll
        for (int q = 0; q < 20; q++) acc[q] = ffma2(v2, wr[q], acc[q]);
    }
#pragma unroll
    for (int q = 0; q < 20; q++) {
        float v0, v1; upk2(acc[q], v0, v1);
        int o = o0 + 2*q;
#pragma unroll
        for (int s = 0; s < 2; s++) {
            float v = s ? v1 : v0;
            int oo = o + s;
            if (oo < 8)       d_fb[((size_t)b*8 + oo)*HWn + p0 + pos] = v;
            else if (oo < 16) d_fc[((size_t)b*8 + (oo-8))*HWn + p0 + pos] = v;
            else              d_fd[((size_t)b*64 + (oo-16))*HWn + p0 + pos] = v;
        }
    }
}

// ---------------- max_j ||fc_j||2 per batch ----------------
__global__ void k_fcmax() {
    __shared__ float red[256];
    int b = blockIdx.x, t = threadIdx.x;
    float mx = 0.f;
    for (int j = t; j < HWn; j += 256) {
        float s = 0.f;
#pragma unroll
        for (int k = 0; k < 8; k++) {
            float v = d_fc[((size_t)b*8 + k)*HWn + j];
            s += v*v;
        }
        mx = fmaxf(mx, s);
    }
    red[t] = mx;
    __syncthreads();
    for (int s = 128; s > 0; s >>= 1) {
        if (t < s) red[t] = fmaxf(red[t], red[t+s]);
        __syncthreads();
    }
    if (t == 0) d_cmax[b] = sqrtf(red[0]);
}

// ---------------- CAM gram partials ----------------
__global__ void __launch_bounds__(256) k_cam_att() {
    __shared__ float psi_s[64*129];
    int b = blockIdx.y, seg = blockIdx.x, t = threadIdx.x;
    int cjg = t & 15, cig = t >> 4;
    float acc[4][4];
#pragma unroll
    for (int r = 0; r < 4; r++)
#pragma unroll
        for (int q = 0; q < 4; q++) acc[r][q] = 0.f;
    for (int idx = t; idx < 8192; idx += 256) {
        int c = idx >> 7, p = idx & 127;
        psi_s[c*129 + p] = d_psi[((size_t)b*Cn + c)*HWn + seg*128 + p];
    }
    __syncthreads();
    for (int p = 0; p < 128; p++) {
        float a0 = psi_s[(cig*4+0)*129 + p];
        float a1 = psi_s[(cig*4+1)*129 + p];
        float a2 = psi_s[(cig*4+2)*129 + p];
        float a3 = psi_s[(cig*4+3)*129 + p];
        float b0 = psi_s[(cjg*4+0)*129 + p];
        float b1 = psi_s[(cjg*4+1)*129 + p];
        float b2 = psi_s[(cjg*4+2)*129 + p];
        float b3 = psi_s[(cjg*4+3)*129 + p];
        acc[0][0]+=a0*b0; acc[0][1]+=a0*b1; acc[0][2]+=a0*b2; acc[0][3]+=a0*b3;
        acc[1][0]+=a1*b0; acc[1][1]+=a1*b1; acc[1][2]+=a1*b2; acc[1][3]+=a1*b3;
        acc[2][0]+=a2*b0; acc[2][1]+=a2*b1; acc[2][2]+=a2*b2; acc[2][3]+=a2*b3;
        acc[3][0]+=a3*b0; acc[3][1]+=a3*b1; acc[3][2]+=a3*b2; acc[3][3]+=a3*b3;
    }
#pragma unroll
    for (int r = 0; r < 4; r++)
#pragma unroll
        for (int q = 0; q < 4; q++)
            d_attp[seg*(Bn*64*64) + (b*64 + cig*4 + r)*64 + cjg*4 + q] = acc[r][q];
}

// ---------------- CAM softmax of (rowmax - att) ----------------
__global__ void k_cam_soft() {
    int b = blockIdx.x, ci = threadIdx.x;
    float v[64];
#pragma unroll
    for (int d = 0; d < 64; d++) {
        float s = 0.f;
        for (int sgm = 0; sgm < 32; sgm++) s += d_attp[sgm*(Bn*64*64) + (b*64 + ci)*64 + d];
        v[d] = s;
    }
    float mx = -1e30f, mn = 1e30f;
#pragma unroll
    for (int d = 0; d < 64; d++) { mx = fmaxf(mx, v[d]); mn = fminf(mn, v[d]); }
    float m2 = mx - mn;
    float ssum = 0.f;
#pragma unroll
    for (int d = 0; d < 64; d++) { float e = __expf((mx - v[d]) - m2); v[d] = e; ssum += e; }
    float inv = 1.f / ssum;
#pragma unroll
    for (int d = 0; d < 64; d++) d_attw[b*4096 + ci*64 + d] = v[d] * inv;
}

// ---------------- CAM out ----------------
__global__ void __launch_bounds__(256) k_cam_out(const float* __restrict__ beta_p) {
    extern __shared__ float smm[];
    float* w_s   = smm;           // 4096
    float* psi_s = smm + 4096;    // 64*256
    int b = blockIdx.y, p0 = blockIdx.x*256, t = threadIdx.x;
    for (int i = t; i < 4096; i += 256) w_s[i] = d_attw[b*4096 + i];
    for (int c = 0; c < 64; c++)
        psi_s[c*256 + t] = d_psi[((size_t)b*Cn + c)*HWn + p0 + t];
    __syncthreads();
    float acc[64];
#pragma unroll
    for (int c = 0; c < 64; c++) acc[c] = 0.f;
    for (int d = 0; d < 64; d++) {
        float v = psi_s[d*256 + t];
#pragma unroll
        for (int c = 0; c < 64; c++) acc[c] += w_s[c*64 + d] * v;
    }
    float beta = beta_p[0];
#pragma unroll
    for (int c = 0; c < 64; c++)
        d_cam[((size_t)b*Cn + c)*HWn + p0 + t] = beta * acc[c] + psi_s[c*256 + t];
}

// ---------------- PAM: single-pass attention, bf16 mma.sync accumulate ----------------
// grid (32 I-tiles, 8 b), 256 threads.
// e computed SIMT fp32; p = exp(e - mhat_i) with mhat = ||fb_i||*Cmax >= e (no rescale);
// D[i,c] accumulated across 64 j-tiles in register fragments via HMMA; normalized once.
__global__ void __launch_bounds__(256, 2) k_pam3(const float* __restrict__ alpha_p) {
    __shared__ __align__(128) char p_bf[16384];    // p tile 128x64 bf16, 128B rows, SWZ
    __shared__ __align__(128) char fd_bf[8192];    // fd tile 64x64 bf16, 128B rows, SWZ
    __shared__ float fb_s[1024];
    __shared__ float fc_s[512];
    __shared__ float mh_s[128];
    __shared__ float z_s[128];
    __shared__ float zr_s[128*17];

    uint32_t pbase  = smem_u32(p_bf);
    uint32_t fdbase = smem_u32(fd_bf);

    int b = blockIdx.y, I0 = blockIdx.x*128, t = threadIdx.x;
    int w = t >> 5, lane = t & 31;
    int ig = t >> 4, cg = t & 15;       // energy-phase layout: 8 rows x 4 j per thread
    int i0 = ig * 8;

    for (int idx = t; idx < 1024; idx += 256)
        fb_s[idx] = d_fb[((size_t)b*8 + (idx >> 7))*HWn + I0 + (idx & 127)];
    __syncthreads();
    if (t < 128) {
        float s = 0.f;
#pragma unroll
        for (int k = 0; k < 8; k++) { float v = fb_s[k*128 + t]; s += v*v; }
        mh_s[t] = sqrtf(s) * d_cmax[b];
    }
    __syncthreads();

    float mhr[8];
#pragma unroll
    for (int r = 0; r < 8; r++) mhr[r] = mh_s[i0 + r];
    float zacc[8];
#pragma unroll
    for (int r = 0; r < 8; r++) zacc[r] = 0.f;

    float acc[8][4];                   // mma fragments: 16i x 64c per warp
#pragma unroll
    for (int ng = 0; ng < 8; ng++)
#pragma unroll
        for (int q = 0; q < 4; q++) acc[ng][q] = 0.f;

    // precompute ldmatrix lane addresses (swizzled)
    uint32_t a_addr[4], b_addr[8][2];
#pragma unroll
    for (int ks = 0; ks < 4; ks++) {
        uint32_t row = w*16 + (lane & 15);
        uint32_t off = row*128 + ks*32 + ((lane >> 4) ? 16u : 0u);
        a_addr[ks] = pbase + SWZ(off);
    }
#pragma unroll
    for (int ng = 0; ng < 8; ng++)
#pragma unroll
        for (int kp = 0; kp < 2; kp++) {
            uint32_t row = ng*8 + (lane & 7);
            uint32_t off = row*128 + kp*64 + ((lane >> 3) & 3)*16;
            b_addr[ng][kp] = fdbase + SWZ(off);
        }

    for (int jt = 0; jt < 64; jt++) {
        int j0 = jt * 64;
        __syncthreads();   // previous tile's mma done reading p/fd
        for (int idx = t; idx < 512; idx += 256)
            fc_s[idx] = d_fc[((size_t)b*8 + (idx >> 6))*HWn + j0 + (idx & 63)];
        for (int idx = t; idx < 2048; idx += 256) {
            int c = idx >> 5, jp = idx & 31;
            const float* row = &d_fd[((size_t)b*64 + c)*HWn + j0 + jp*2];
            uint32_t pr = cvt_bf16x2(row[0], row[1]);
            uint32_t off = (uint32_t)(c*128 + jp*4);
            *(uint32_t*)(fd_bf + SWZ(off)) = pr;
        }
        __syncthreads();
        // energies e[8i x 4j] fp32; p = exp(e - mhat) -> bf16 swizzled
        ull fc2[16];
#pragma unroll
        for (int k = 0; k < 8; k++) {
            float4 f = *(const float4*)&fc_s[k*64 + cg*4];
            fc2[2*k] = pk2(f.x, f.y); fc2[2*k+1] = pk2(f.z, f.w);
        }
        ull e[16];
#pragma unroll
        for (int q = 0; q < 16; q++) e[q] = 0ull;
#pragma unroll
        for (int k = 0; k < 8; k++) {
            float4 fa = *(const float4*)&fb_s[k*128 + i0];
            float4 fbv = *(const float4*)&fb_s[k*128 + i0 + 4];
            float fv[8] = {fa.x, fa.y, fa.z, fa.w, fbv.x, fbv.y, fbv.z, fbv.w};
#pragma unroll
            for (int r = 0; r < 8; r++) {
                ull f2 = pk2(fv[r], fv[r]);
                e[2*r]   = ffma2(f2, fc2[2*k],   e[2*r]);
                e[2*r+1] = ffma2(f2, fc2[2*k+1], e[2*r+1]);
            }
        }
#pragma unroll
        for (int r = 0; r < 8; r++) {
            float e0, e1, e2, e3;
            upk2(e[2*r], e0, e1); upk2(e[2*r+1], e2, e3);
            float m = mhr[r];
            float q0 = __expf(e0 - m), q1 = __expf(e1 - m);
            float q2 = __expf(e2 - m), q3 = __expf(e3 - m);
            zacc[r] += (q0 + q1) + (q2 + q3);
            uint32_t pa  = cvt_bf16x2(q0, q1);
            uint32_t pbb = cvt_bf16x2(q2, q3);
            ull pkd = (ull)pa | ((ull)pbb << 32);
            uint32_t off = (uint32_t)((i0 + r)*128 + cg*8);
            *(ull*)(p_bf + SWZ(off)) = pkd;
        }
        __syncthreads();
        // MMA: each warp computes its 16 x 64 fragment for this j-tile
        uint32_t afr[4][4];
#pragma unroll
        for (int ks = 0; ks < 4; ks++)
            ldsm_x4(afr[ks][0], afr[ks][1], afr[ks][2], afr[ks][3], a_addr[ks]);
#pragma unroll
        for (int ng = 0; ng < 8; ng++) {
#pragma unroll
            for (int kp = 0; kp < 2; kp++) {
                uint32_t bb[4];
                ldsm_x4(bb[0], bb[1], bb[2], bb[3], b_addr[ng][kp]);
                mma_bf16(acc[ng], afr[2*kp],     bb);
                mma_bf16(acc[ng], afr[2*kp + 1], bb + 2);
            }
        }
    }
    // z reduction
#pragma unroll
    for (int r = 0; r < 8; r++) zr_s[(i0 + r)*17 + cg] = zacc[r];
    __syncthreads();
    if (t < 128) {
        float s = 0.f;
#pragma unroll
        for (int q = 0; q < 16; q++) s += zr_s[t*17 + q];
        z_s[t] = s;
    }
    __syncthreads();
    // epilogue: D[i,c] * alpha/z + psi   (fragment layout: gr=lane/4, tc=lane%4)
    {
        int gr = lane >> 2, tc = lane & 3;
        int i1 = w*16 + gr, i2 = i1 + 8;
        float alpha = alpha_p[0];
        float invz1 = alpha / z_s[i1];
        float invz2 = alpha / z_s[i2];
#pragma unroll
        for (int ng = 0; ng < 8; ng++) {
            int c = ng*8 + 2*tc;
            size_t b0 = ((size_t)b*Cn + c)*HWn + I0;
            size_t b1 = b0 + HWn;
            d_pam[b0 + i1] = acc[ng][0]*invz1 + d_psi[b0 + i1];
            d_pam[b1 + i1] = acc[ng][1]*invz1 + d_psi[b1 + i1];
            d_pam[b0 + i2] = acc[ng][2]*invz2 + d_psi[b0 + i2];
            d_pam[b1 + i2] = acc[ng][3]*invz2 + d_psi[b1 + i2];
        }
    }
}

// ---------------- gate: da = sigmoid(BN(psi_w . (cam*pam))) ----------------
__global__ void __launch_bounds__(256) k_gate() {
    __shared__ float wp_s[64];
    int b = blockIdx.y, p0 = blockIdx.x*256, t = threadIdx.x;
    if (t < 64) wp_s[t] = d_wp[t];
    __syncthreads();
    float acc = d_bp[0];
    size_t base = ((size_t)b*Cn)*HWn + p0 + t;
#pragma unroll 8
    for (int c = 0; c < 64; c++) {
        size_t idx = base + (size_t)c*HWn;
        acc += wp_s[c] * d_cam[idx] * d_pam[idx];
    }
    d_da[b*HWn + p0 + t] = 1.f / (1.f + __expf(-acc));
}

// ---------------- out = x * da ----------------
__global__ void __launch_bounds__(256) k_mul(const float* __restrict__ x, float* __restrict__ out) {
    int idx = blockIdx.x * 256 + threadIdx.x;
    float4 v = ((const float4*)x)[idx];
    int b  = idx >> 18;
    int p4 = idx & 1023;
    float4 dv = ((const float4*)d_da)[b*1024 + p4];
    float4 o;
    o.x = v.x * dv.x; o.y = v.y * dv.y; o.z = v.z * dv.z; o.w = v.w * dv.w;
    ((float4*)out)[idx] = o;
}

// ---------------- launch ----------------
extern "C" void kernel_launch(void* const* d_in, const int* in_sizes, int n_in,
                              void* d_out, int out_size) {
    const float* g = (const float*)d_in[0];
    const float* x = (const float*)d_in[1];

    cudaFuncSetAttribute(k_small,   cudaFuncAttributeMaxDynamicSharedMemorySize, 13392*4);
    cudaFuncSetAttribute(k_cam_out, cudaFuncAttributeMaxDynamicSharedMemorySize, (4096 + 64*256)*4);

    k_prep<<<64, 256>>>((const float*)d_in[2],  (const float*)d_in[3],  (const float*)d_in[4],
                        (const float*)d_in[5],  (const float*)d_in[6],  (const float*)d_in[7],
                        (const float*)d_in[8],  (const float*)d_in[9],  (const float*)d_in[10],
                        (const float*)d_in[11], (const float*)d_in[12], (const float*)d_in[13],
                        (const float*)d_in[14], (const float*)d_in[15], (const float*)d_in[16],
                        (const float*)d_in[17], (const float*)d_in[18], (const float*)d_in[19]);

    k_psi<<<dim3(32, 8), 256>>>(g, x);

    k_small<<<dim3(32, 8), 256, 13392*4>>>(
        (const float*)d_in[20], (const float*)d_in[21],
        (const float*)d_in[22], (const float*)d_in[23],
        (const float*)d_in[24], (const float*)d_in[25]);

    k_fcmax<<<8, 256>>>();

    k_cam_att<<<dim3(32, 8), 256>>>();
    k_cam_soft<<<8, 64>>>();
    k_cam_out<<<dim3(16, 8), 256, (4096 + 64*256)*4>>>((const float*)d_in[27]);

    k_pam3<<<dim3(32, 8), 256>>>((const float*)d_in[26]);

    k_gate<<<dim3(16, 8), 256>>>();
    k_mul<<<8192, 256>>>(x, (float*)d_out);
}

// round 5
// speedup vs baseline: 2.9379x; 1.1414x over previous
#include <cuda_runtime.h>
#include <cuda_bf16.h>
#include <math.h>
#include <stdint.h>

typedef unsigned long long ull;

#define Bn 8
#define Cn 64
#define HWn 4096
#define LOG2E 1.4426950408889634f

// ---------------- scratch (device globals; no allocs allowed) ----------------
__device__ __align__(16) float d_psi[Bn*Cn*HWn];     // 8MB
__device__ __align__(16) float d_fb [Bn*8*HWn];      // pre-scaled by log2(e)
__device__ __align__(16) float d_fc [Bn*8*HWn];
__device__ __align__(16) __nv_bfloat16 d_fdh[Bn*Cn*HWn];  // 4MB bf16 [b][c][j]
__device__ __align__(16) float d_attp[32*Bn*64*64];  // CAM partial gram
__device__ __align__(16) float d_W2[Bn*64*64];       // beta*wp[c]*attw[c][d]
__device__ __align__(16) float d_WfT[512*64];        // folded fused weights, [c][o]
__device__ __align__(16) float d_bias[64];
__device__ __align__(16) float d_wp[64];
__device__ __align__(16) float d_bp[1];
__device__ unsigned d_cmax_u[8];                     // max_j ||fc_j||^2 (bits)
__device__ __align__(16) float d_da[Bn*HWn];

// ---------------- f32x2 helpers ----------------
__device__ __forceinline__ ull pk2(float lo, float hi) {
    ull r; asm("mov.b64 %0, {%1, %2};" : "=l"(r) : "f"(lo), "f"(hi)); return r;
}
__device__ __forceinline__ void upk2(ull v, float& lo, float& hi) {
    asm("mov.b64 {%0, %1}, %2;" : "=f"(lo), "=f"(hi) : "l"(v));
}
__device__ __forceinline__ ull ffma2(ull a, ull b, ull c) {
    ull d; asm("fma.rn.f32x2 %0, %1, %2, %3;" : "=l"(d) : "l"(a), "l"(b), "l"(c)); return d;
}
__device__ __forceinline__ float ex2f(float x) {
    float r; asm("ex2.approx.f32 %0, %1;" : "=f"(r) : "f"(x)); return r;
}

// ---------------- warp MMA helpers ----------------
__device__ __forceinline__ uint32_t smem_u32(const void* p) {
    uint32_t a;
    asm("{ .reg .u64 t; cvta.to.shared.u64 t, %1; cvt.u32.u64 %0, t; }" : "=r"(a) : "l"(p));
    return a;
}
#define SWZ(off) ((off) ^ (((off) >> 3) & 0x70))
__device__ __forceinline__ void ldsm_x4(uint32_t& r0, uint32_t& r1, uint32_t& r2, uint32_t& r3,
                                        uint32_t addr) {
    asm volatile("ldmatrix.sync.aligned.m8n8.x4.shared.b16 {%0,%1,%2,%3}, [%4];"
                 : "=r"(r0), "=r"(r1), "=r"(r2), "=r"(r3) : "r"(addr));
}
__device__ __forceinline__ void mma_bf16(float* d, const uint32_t* a, const uint32_t* b) {
    asm volatile(
        "mma.sync.aligned.m16n8k16.row.col.f32.bf16.bf16.f32 "
        "{%0,%1,%2,%3}, {%4,%5,%6,%7}, {%8,%9}, {%0,%1,%2,%3};"
        : "+f"(d[0]), "+f"(d[1]), "+f"(d[2]), "+f"(d[3])
        : "r"(a[0]), "r"(a[1]), "r"(a[2]), "r"(a[3]), "r"(b[0]), "r"(b[1]));
}
__device__ __forceinline__ uint32_t cvt_bf16x2(float a, float b) {
    uint32_t r;
    asm("cvt.rn.satfinite.bf16x2.f32 %0, %1, %2;" : "=r"(r) : "f"(b), "f"(a));
    return r;
}

// ---------------- prep: fold BN into conv weights ----------------
__global__ void k_prep(const float* Wg_w, const float* Wg_b, const float* gg, const float* gb,
                       const float* gm, const float* gv,
                       const float* Wx_w, const float* Wx_b, const float* xg, const float* xb,
                       const float* xm, const float* xv,
                       const float* psi_w, const float* psi_b, const float* pg, const float* pbt,
                       const float* pm, const float* pv) {
    int o = blockIdx.x, t = threadIdx.x;
    float invg = gg[o] * rsqrtf(gv[o] + 1e-5f);
    float invx = xg[o] * rsqrtf(xv[o] + 1e-5f);
    d_WfT[t*64 + o]       = Wg_w[o*256 + t] * invg;
    d_WfT[(256+t)*64 + o] = Wx_w[o*256 + t] * invx;
    if (t == 0) {
        d_bias[o] = (Wg_b[o] - gm[o]) * invg + gb[o]
                  + (Wx_b[o] - xm[o]) * invx + xb[o];
    }
    if (o == 0) {
        if (t < 8) d_cmax_u[t] = 0u;
        if (t < 64) {
            float invp = pg[0] * rsqrtf(pv[0] + 1e-5f);
            d_wp[t] = psi_w[t] * invp;
            if (t == 0) d_bp[0] = (psi_b[0] - pm[0]) * invp + pbt[0];
        }
    }
}

// ---------------- psi = relu(BN(Wg g) + BN(Wx x)) ----------------
__global__ void __launch_bounds__(256) k_psi(const float* __restrict__ g, const float* __restrict__ x) {
    __shared__ __align__(16) float in_s[32*128];
    __shared__ __align__(16) float w_s[32*64];
    int b = blockIdx.y, p0 = blockIdx.x*128, t = threadIdx.x;
    int cg = t & 15, pg = t >> 4;
    ull acc[16];
#pragma unroll
    for (int q = 0; q < 16; q++) acc[q] = 0ull;
    for (int cb = 0; cb < 512; cb += 32) {
        __syncthreads();
        for (int idx = t; idx < 4096; idx += 256) {
            int r = idx >> 7, p = idx & 127;
            int c = cb + r;
            const float* src = (c < 256) ? (g + ((size_t)b*256 + c)*HWn)
                                         : (x + ((size_t)b*256 + (c-256))*HWn);
            in_s[idx] = src[p0 + p];
        }
        for (int idx = t; idx < 2048; idx += 256)
            w_s[idx] = d_WfT[(cb + (idx >> 6))*64 + (idx & 63)];
        __syncthreads();
#pragma unroll 4
        for (int c = 0; c < 32; c++) {
            float4 w = *(const float4*)&w_s[c*64 + cg*4];
            ull w01 = pk2(w.x, w.y), w23 = pk2(w.z, w.w);
            float4 a0 = *(const float4*)&in_s[c*128 + pg*8];
            float4 a1 = *(const float4*)&in_s[c*128 + pg*8 + 4];
            float av[8] = {a0.x,a0.y,a0.z,a0.w,a1.x,a1.y,a1.z,a1.w};
#pragma unroll
            for (int r = 0; r < 8; r++) {
                ull p2 = pk2(av[r], av[r]);
                acc[2*r]   = ffma2(p2, w01, acc[2*r]);
                acc[2*r+1] = ffma2(p2, w23, acc[2*r+1]);
            }
        }
    }
    float vals[8][4];
#pragma unroll
    for (int r = 0; r < 8; r++) {
        float v0,v1,v2,v3;
        upk2(acc[2*r],   v0, v1);
        upk2(acc[2*r+1], v2, v3);
        vals[r][0]=v0; vals[r][1]=v1; vals[r][2]=v2; vals[r][3]=v3;
    }
#pragma unroll
    for (int cc = 0; cc < 4; cc++) {
        float bi = d_bias[cg*4 + cc];
        float4 o0 = make_float4(fmaxf(vals[0][cc]+bi,0.f), fmaxf(vals[1][cc]+bi,0.f),
                                fmaxf(vals[2][cc]+bi,0.f), fmaxf(vals[3][cc]+bi,0.f));
        float4 o1 = make_float4(fmaxf(vals[4][cc]+bi,0.f), fmaxf(vals[5][cc]+bi,0.f),
                                fmaxf(vals[6][cc]+bi,0.f), fmaxf(vals[7][cc]+bi,0.f));
        size_t base = ((size_t)b*Cn + cg*4 + cc)*HWn + p0 + pg*8;
        *(float4*)&d_psi[base]     = o0;
        *(float4*)&d_psi[base + 4] = o1;
    }
}

// ---------------- fb/fc/fd convs + fc-norm max (folded fcmax) ----------------
__global__ void __launch_bounds__(256) k_small(const float* __restrict__ pb_w, const float* __restrict__ pb_b,
                                               const float* __restrict__ pc_w, const float* __restrict__ pc_b,
                                               const float* __restrict__ pd_w, const float* __restrict__ pd_b) {
    extern __shared__ float smm[];
    float* A      = smm;              // psi tile 64*128 = 8192
    float* w_s    = smm + 8192;       // [c][o] 64*80 = 5120
    float* bias_s = w_s + 5120;       // 80
    int b = blockIdx.y, p0 = blockIdx.x*128, t = threadIdx.x;
    int pos = t & 127, half = t >> 7;
    for (int idx = t; idx < 8192; idx += 256) {
        int c = idx >> 7, p = idx & 127;
        A[idx] = d_psi[((size_t)b*Cn + c)*HWn + p0 + p];
    }
    for (int idx = t; idx < 5120; idx += 256) {
        int c = idx / 80, o = idx % 80;
        float w;
        if (o < 8)       w = pb_w[o*64 + c];
        else if (o < 16) w = pc_w[(o-8)*64 + c];
        else             w = pd_w[(o-16)*64 + c];
        w_s[idx] = w;
    }
    if (t < 80) bias_s[t] = (t < 8) ? pb_b[t] : (t < 16 ? pc_b[t-8] : pd_b[t-16]);
    __syncthreads();
    int o0 = half*40;
    ull acc[20];
#pragma unroll
    for (int q = 0; q < 20; q++) acc[q] = pk2(bias_s[o0 + 2*q], bias_s[o0 + 2*q + 1]);
    for (int c = 0; c < 64; c++) {
        float v = A[c*128 + pos];
        ull v2 = pk2(v, v);
        const ull* wr = (const ull*)&w_s[c*80 + o0];
#pragma unroll
        for (int q = 0; q < 20; q++) acc[q] = ffma2(v2, wr[q], acc[q]);
    }
    // fc norm max (half 0 threads hold the full fc vector: acc[4..7])
    if (half == 0) {
        float s = 0.f;
#pragma unroll
        for (int q = 4; q < 8; q++) { float v0, v1; upk2(acc[q], v0, v1); s += v0*v0 + v1*v1; }
#pragma unroll
        for (int m = 16; m; m >>= 1) s = fmaxf(s, __shfl_xor_sync(0xffffffffu, s, m));
        if ((t & 31) == 0) atomicMax(&d_cmax_u[b], __float_as_uint(s));
    }
#pragma unroll
    for (int q = 0; q < 20; q++) {
        float v0, v1; upk2(acc[q], v0, v1);
        int o = o0 + 2*q;
#pragma unroll
        for (int s = 0; s < 2; s++) {
            float v = s ? v1 : v0;
            int oo = o + s;
            if (oo < 8)       d_fb[((size_t)b*8 + oo)*HWn + p0 + pos] = v * LOG2E;
            else if (oo < 16) d_fc[((size_t)b*8 + (oo-8))*HWn + p0 + pos] = v;
            else              d_fdh[((size_t)b*64 + (oo-16))*HWn + p0 + pos] = __float2bfloat16(v);
        }
    }
}

// ---------------- CAM gram partials ----------------
__global__ void __launch_bounds__(256) k_cam_att() {
    __shared__ float psi_s[64*129];
    int b = blockIdx.y, seg = blockIdx.x, t = threadIdx.x;
    int cjg = t & 15, cig = t >> 4;
    float acc[4][4];
#pragma unroll
    for (int r = 0; r < 4; r++)
#pragma unroll
        for (int q = 0; q < 4; q++) acc[r][q] = 0.f;
    for (int idx = t; idx < 8192; idx += 256) {
        int c = idx >> 7, p = idx & 127;
        psi_s[c*129 + p] = d_psi[((size_t)b*Cn + c)*HWn + seg*128 + p];
    }
    __syncthreads();
    for (int p = 0; p < 128; p++) {
        float a0 = psi_s[(cig*4+0)*129 + p];
        float a1 = psi_s[(cig*4+1)*129 + p];
        float a2 = psi_s[(cig*4+2)*129 + p];
        float a3 = psi_s[(cig*4+3)*129 + p];
        float b0 = psi_s[(cjg*4+0)*129 + p];
        float b1 = psi_s[(cjg*4+1)*129 + p];
        float b2 = psi_s[(cjg*4+2)*129 + p];
        float b3 = psi_s[(cjg*4+3)*129 + p];
        acc[0][0]+=a0*b0; acc[0][1]+=a0*b1; acc[0][2]+=a0*b2; acc[0][3]+=a0*b3;
        acc[1][0]+=a1*b0; acc[1][1]+=a1*b1; acc[1][2]+=a1*b2; acc[1][3]+=a1*b3;
        acc[2][0]+=a2*b0; acc[2][1]+=a2*b1; acc[2][2]+=a2*b2; acc[2][3]+=a2*b3;
        acc[3][0]+=a3*b0; acc[3][1]+=a3*b1; acc[3][2]+=a3*b2; acc[3][3]+=a3*b3;
    }
#pragma unroll
    for (int r = 0; r < 4; r++)
#pragma unroll
        for (int q = 0; q < 4; q++)
            d_attp[seg*(Bn*64*64) + (b*64 + cig*4 + r)*64 + cjg*4 + q] = acc[r][q];
}

// ---------------- CAM softmax -> W2[c][d] = beta*wp[c]*attw[c][d] ----------------
__global__ void k_cam_soft(const float* __restrict__ beta_p) {
    int b = blockIdx.x, ci = threadIdx.x;
    float v[64];
#pragma unroll
    for (int d = 0; d < 64; d++) {
        float s = 0.f;
        for (int sgm = 0; sgm < 32; sgm++) s += d_attp[sgm*(Bn*64*64) + (b*64 + ci)*64 + d];
        v[d] = s;
    }
    float mx = -1e30f, mn = 1e30f;
#pragma unroll
    for (int d = 0; d < 64; d++) { mx = fmaxf(mx, v[d]); mn = fminf(mn, v[d]); }
    float m2 = mx - mn;
    float ssum = 0.f;
#pragma unroll
    for (int d = 0; d < 64; d++) { float e = __expf((mx - v[d]) - m2); v[d] = e; ssum += e; }
    float scale = beta_p[0] * d_wp[ci] / ssum;
#pragma unroll
    for (int d = 0; d < 64; d++) d_W2[b*4096 + ci*64 + d] = v[d] * scale;
}

// ---------------- PAM + CAM-gate fusion ----------------
// grid (32 I-tiles, 8 b), 256 threads, 85760B dynamic smem.
// Mainloop: single-pass attention (log2-domain energies, ex2, bf16 HMMA accumulate).
// Epilogue: pam tile -> smem, fused W2 GEMM + gate + sigmoid -> d_da. No cam/pam HBM buffers.
__global__ void __launch_bounds__(256, 2) k_pam3(const float* __restrict__ alpha_p) {
    extern __shared__ __align__(128) char dsm[];
    // mainloop layout
    char*  p_bf  = dsm;                       // 16384
    char*  fd_bf = dsm + 16384;               // 8192
    float* fb_s  = (float*)(dsm + 24576);     // 1024 f
    float* fc_s  = (float*)(dsm + 28672);     // 512 f
    float* zr_s  = (float*)(dsm + 30720);     // 2176 f (ends 39424)
    float* mh_s  = (float*)(dsm + 39424);     // 128 f
    // epilogue union (overwrites mainloop regions)
    float* psi_s = (float*)dsm;               // 64*132 f (33792 B)
    float* pam_s = (float*)(dsm + 33792);     // 64*132 f (33792 B)
    float* W2_s  = (float*)(dsm + 67584);     // 4096 f  (16384 B)
    float* wp_s  = (float*)(dsm + 83968);     // 64 f
    float* gred  = (float*)(dsm + 84224);     // 256 f
    // persistent
    float* z_s   = (float*)(dsm + 85248);     // 128 f  (total 85760)

    uint32_t pbase  = smem_u32(dsm);
    uint32_t fdbase = pbase + 16384;

    int b = blockIdx.y, I0 = blockIdx.x*128, t = threadIdx.x;
    int w = t >> 5, lane = t & 31;
    int ig = t >> 4, cg = t & 15;
    int i0 = ig * 8;

    for (int idx = t; idx < 1024; idx += 256)
        fb_s[idx] = d_fb[((size_t)b*8 + (idx >> 7))*HWn + I0 + (idx & 127)];
    __syncthreads();
    if (t < 128) {
        float s = 0.f;
#pragma unroll
        for (int k = 0; k < 8; k++) { float v = fb_s[k*128 + t]; s += v*v; }
        mh_s[t] = sqrtf(s) * sqrtf(__uint_as_float(d_cmax_u[b]));
    }
    __syncthreads();

    float mhr[8];
#pragma unroll
    for (int r = 0; r < 8; r++) mhr[r] = mh_s[i0 + r];
    float zacc[8];
#pragma unroll
    for (int r = 0; r < 8; r++) zacc[r] = 0.f;

    float acc[8][4];
#pragma unroll
    for (int ng = 0; ng < 8; ng++)
#pragma unroll
        for (int q = 0; q < 4; q++) acc[ng][q] = 0.f;

    uint32_t a_addr[4], b_addr[8][2];
#pragma unroll
    for (int ks = 0; ks < 4; ks++) {
        uint32_t row = w*16 + (lane & 15);
        uint32_t off = row*128 + ks*32 + ((lane >> 4) ? 16u : 0u);
        a_addr[ks] = pbase + SWZ(off);
    }
#pragma unroll
    for (int ng = 0; ng < 8; ng++)
#pragma unroll
        for (int kp = 0; kp < 2; kp++) {
            uint32_t row = ng*8 + (lane & 7);
            uint32_t off = row*128 + kp*64 + ((lane >> 3) & 3)*16;
            b_addr[ng][kp] = fdbase + SWZ(off);
        }

    for (int jt = 0; jt < 64; jt++) {
        int j0 = jt * 64;
        __syncthreads();
        for (int idx = t; idx < 512; idx += 256)
            fc_s[idx] = d_fc[((size_t)b*8 + (idx >> 6))*HWn + j0 + (idx & 63)];
        for (int idx = t; idx < 2048; idx += 256) {
            int c = idx >> 5, jp = idx & 31;
            uint32_t pr = *(const uint32_t*)&d_fdh[((size_t)b*64 + c)*HWn + j0 + jp*2];
            uint32_t off = (uint32_t)(c*128 + jp*4);
            *(uint32_t*)(fd_bf + SWZ(off)) = pr;
        }
        __syncthreads();
        // energies (log2 domain; fb pre-scaled) -> p = ex2(e - mhat) -> bf16
        ull fc2[16];
#pragma unroll
        for (int k = 0; k < 8; k++) {
            float4 f = *(const float4*)&fc_s[k*64 + cg*4];
            fc2[2*k] = pk2(f.x, f.y); fc2[2*k+1] = pk2(f.z, f.w);
        }
        ull e[16];
#pragma unroll
        for (int q = 0; q < 16; q++) e[q] = 0ull;
#pragma unroll
        for (int k = 0; k < 8; k++) {
            float4 fa = *(const float4*)&fb_s[k*128 + i0];
            float4 fbv = *(const float4*)&fb_s[k*128 + i0 + 4];
            float fv[8] = {fa.x, fa.y, fa.z, fa.w, fbv.x, fbv.y, fbv.z, fbv.w};
#pragma unroll
            for (int r = 0; r < 8; r++) {
                ull f2 = pk2(fv[r], fv[r]);
                e[2*r]   = ffma2(f2, fc2[2*k],   e[2*r]);
                e[2*r+1] = ffma2(f2, fc2[2*k+1], e[2*r+1]);
            }
        }
#pragma unroll
        for (int r = 0; r < 8; r++) {
            float e0, e1, e2, e3;
            upk2(e[2*r], e0, e1); upk2(e[2*r+1], e2, e3);
            float m = mhr[r];
            float q0 = ex2f(e0 - m), q1 = ex2f(e1 - m);
            float q2 = ex2f(e2 - m), q3 = ex2f(e3 - m);
            zacc[r] += (q0 + q1) + (q2 + q3);
            uint32_t pa  = cvt_bf16x2(q0, q1);
            uint32_t pbb = cvt_bf16x2(q2, q3);
            ull pkd = (ull)pa | ((ull)pbb << 32);
            uint32_t off = (uint32_t)((i0 + r)*128 + cg*8);
            *(ull*)(p_bf + SWZ(off)) = pkd;
        }
        __syncthreads();
        uint32_t afr[4][4];
#pragma unroll
        for (int ks = 0; ks < 4; ks++)
            ldsm_x4(afr[ks][0], afr[ks][1], afr[ks][2], afr[ks][3], a_addr[ks]);
#pragma unroll
        for (int ng = 0; ng < 8; ng++) {
#pragma unroll
            for (int kp = 0; kp < 2; kp++) {
                uint32_t bb[4];
                ldsm_x4(bb[0], bb[1], bb[2], bb[3], b_addr[ng][kp]);
                mma_bf16(acc[ng], afr[2*kp],     bb);
                mma_bf16(acc[ng], afr[2*kp + 1], bb + 2);
            }
        }
    }
    // ---- z reduction (zr region still live) ----
    __syncthreads();
#pragma unroll
    for (int r = 0; r < 8; r++) zr_s[(i0 + r)*17 + cg] = zacc[r];
    __syncthreads();
    if (t < 128) {
        float s = 0.f;
#pragma unroll
        for (int q = 0; q < 16; q++) s += zr_s[t*17 + q];
        z_s[t] = alpha_p[0] / s;    // alpha/z directly
    }
    __syncthreads();
    // ---- load psi tile / W2 / wp (overwrites mainloop smem) ----
    for (int idx = t; idx < 8192; idx += 256) {
        int c = idx >> 7, p = idx & 127;
        psi_s[c*132 + p] = d_psi[((size_t)b*Cn + c)*HWn + I0 + p];
    }
    for (int idx = t; idx < 4096; idx += 256) W2_s[idx] = d_W2[b*4096 + idx];
    if (t < 64) wp_s[t] = d_wp[t];
    __syncthreads();
    // ---- fragments -> pam_s[c][i] = D*alpha/z + psi ----
    {
        int gr = lane >> 2, tc = lane & 3;
        int i1 = w*16 + gr, i2 = i1 + 8;
        float z1 = z_s[i1], z2 = z_s[i2];
#pragma unroll
        for (int ng = 0; ng < 8; ng++) {
            int c = ng*8 + 2*tc;
            pam_s[c*132 + i1]       = acc[ng][0]*z1 + psi_s[c*132 + i1];
            pam_s[(c+1)*132 + i1]   = acc[ng][1]*z1 + psi_s[(c+1)*132 + i1];
            pam_s[c*132 + i2]       = acc[ng][2]*z2 + psi_s[c*132 + i2];
            pam_s[(c+1)*132 + i2]   = acc[ng][3]*z2 + psi_s[(c+1)*132 + i2];
        }
    }
    __syncthreads();
    // ---- fused CAM + gate: gate[p] = bp + sum_c wp*psi*pam + sum_d psi[d,p]*(W2@pam)[d,p] ----
    {
        int p = t & 127, half = t >> 7;
        int c0 = half*32, d0 = half*32;
        float part1 = 0.f;
#pragma unroll 8
        for (int c = 0; c < 32; c++) {
            int cc = c0 + c;
            part1 += wp_s[cc] * psi_s[cc*132 + p] * pam_s[cc*132 + p];
        }
        ull v[16];
#pragma unroll
        for (int q = 0; q < 16; q++) v[q] = 0ull;
        for (int c = 0; c < 64; c++) {
            float pm = pam_s[c*132 + p];
            ull pm2 = pk2(pm, pm);
            const ull* wr = (const ull*)&W2_s[c*64 + d0];
#pragma unroll
            for (int q = 0; q < 16; q++) v[q] = ffma2(pm2, wr[q], v[q]);
        }
        float part2 = 0.f;
#pragma unroll
        for (int q = 0; q < 16; q++) {
            float v0, v1; upk2(v[q], v0, v1);
            part2 += psi_s[(d0+2*q)*132 + p]*v0 + psi_s[(d0+2*q+1)*132 + p]*v1;
        }
        gred[half*128 + p] = part1 + part2;
    }
    __syncthreads();
    if (t < 128) {
        float gate = d_bp[0] + gred[t] + gred[128 + t];
        d_da[b*HWn + I0 + t] = 1.f / (1.f + __expf(-gate));
    }
}

// ---------------- out = x * da ----------------
__global__ void __launch_bounds__(256) k_mul(const float* __restrict__ x, float* __restrict__ out) {
    int idx = blockIdx.x * 256 + threadIdx.x;
    float4 v = ((const float4*)x)[idx];
    int b  = idx >> 18;
    int p4 = idx & 1023;
    float4 dv = ((const float4*)d_da)[b*1024 + p4];
    float4 o;
    o.x = v.x * dv.x; o.y = v.y * dv.y; o.z = v.z * dv.z; o.w = v.w * dv.w;
    ((float4*)out)[idx] = o;
}

// ---------------- launch ----------------
extern "C" void kernel_launch(void* const* d_in, const int* in_sizes, int n_in,
                              void* d_out, int out_size) {
    const float* g = (const float*)d_in[0];
    const float* x = (const float*)d_in[1];

    cudaFuncSetAttribute(k_small, cudaFuncAttributeMaxDynamicSharedMemorySize, 13392*4);
    cudaFuncSetAttribute(k_pam3,  cudaFuncAttributeMaxDynamicSharedMemorySize, 85760);

    k_prep<<<64, 256>>>((const float*)d_in[2],  (const float*)d_in[3],  (const float*)d_in[4],
                        (const float*)d_in[5],  (const float*)d_in[6],  (const float*)d_in[7],
                        (const float*)d_in[8],  (const float*)d_in[9],  (const float*)d_in[10],
                        (const float*)d_in[11], (const float*)d_in[12], (const float*)d_in[13],
                        (const float*)d_in[14], (const float*)d_in[15], (const float*)d_in[16],
                        (const float*)d_in[17], (const float*)d_in[18], (const float*)d_in[19]);

    k_psi<<<dim3(32, 8), 256>>>(g, x);

    k_small<<<dim3(32, 8), 256, 13392*4>>>(
        (const float*)d_in[20], (const float*)d_in[21],
        (const float*)d_in[22], (const float*)d_in[23],
        (const float*)d_in[24], (const float*)d_in[25]);

    k_cam_att<<<dim3(32, 8), 256>>>();
    k_cam_soft<<<8, 64>>>((const float*)d_in[27]);

    k_pam3<<<dim3(32, 8), 256, 85760>>>((const float*)d_in[26]);

    k_mul<<<8192, 256>>>(x, (float*)d_out);
}

// round 6
// speedup vs baseline: 3.8166x; 1.2991x over previous
#include <cuda_runtime.h>
#include <cuda_bf16.h>
#include <math.h>
#include <stdint.h>

typedef unsigned long long ull;

#define Bn 8
#define Cn 64
#define HWn 4096
#define LOG2E 1.4426950408889634f

// ---------------- scratch (device globals; no allocs allowed) ----------------
__device__ __align__(16) float d_psi[Bn*Cn*HWn];     // 8MB
__device__ __align__(16) float d_fb [Bn*8*HWn];      // pre-scaled by log2(e)
__device__ __align__(16) float d_fc [Bn*8*HWn];
__device__ __align__(16) __nv_bfloat16 d_fdh[Bn*Cn*HWn];  // 4MB bf16 [b][c][j]
__device__ __align__(16) float d_attp[32*Bn*64*64];  // CAM partial gram
__device__ __align__(16) float d_W2[Bn*64*64];       // beta*wp[c]*attw[c][d]
__device__ __align__(16) __nv_bfloat16 d_Wh[512*64]; // folded weight hi, [cin][out]
__device__ __align__(16) __nv_bfloat16 d_Wl[512*64]; // folded weight lo
__device__ __align__(16) float d_bias[64];
__device__ __align__(16) float d_wp[64];
__device__ __align__(16) float d_bp[1];
__device__ unsigned d_cmax_u[8];                     // max_j ||fc_j||^2 (bits)

// ---------------- f32x2 helpers ----------------
__device__ __forceinline__ ull pk2(float lo, float hi) {
    ull r; asm("mov.b64 %0, {%1, %2};" : "=l"(r) : "f"(lo), "f"(hi)); return r;
}
__device__ __forceinline__ void upk2(ull v, float& lo, float& hi) {
    asm("mov.b64 {%0, %1}, %2;" : "=f"(lo), "=f"(hi) : "l"(v));
}
__device__ __forceinline__ ull ffma2(ull a, ull b, ull c) {
    ull d; asm("fma.rn.f32x2 %0, %1, %2, %3;" : "=l"(d) : "l"(a), "l"(b), "l"(c)); return d;
}
__device__ __forceinline__ float ex2f(float x) {
    float r; asm("ex2.approx.f32 %0, %1;" : "=f"(r) : "f"(x)); return r;
}

// ---------------- warp MMA helpers ----------------
__device__ __forceinline__ uint32_t smem_u32(const void* p) {
    uint32_t a;
    asm("{ .reg .u64 t; cvta.to.shared.u64 t, %1; cvt.u32.u64 %0, t; }" : "=r"(a) : "l"(p));
    return a;
}
#define SWZ(off) ((off) ^ (((off) >> 3) & 0x70))
__device__ __forceinline__ void ldsm_x4(uint32_t& r0, uint32_t& r1, uint32_t& r2, uint32_t& r3,
                                        uint32_t addr) {
    asm volatile("ldmatrix.sync.aligned.m8n8.x4.shared.b16 {%0,%1,%2,%3}, [%4];"
                 : "=r"(r0), "=r"(r1), "=r"(r2), "=r"(r3) : "r"(addr));
}
__device__ __forceinline__ void ldsm_x4t(uint32_t& r0, uint32_t& r1, uint32_t& r2, uint32_t& r3,
                                         uint32_t addr) {
    asm volatile("ldmatrix.sync.aligned.m8n8.x4.trans.shared.b16 {%0,%1,%2,%3}, [%4];"
                 : "=r"(r0), "=r"(r1), "=r"(r2), "=r"(r3) : "r"(addr));
}
__device__ __forceinline__ void mma_bf16(float* d, const uint32_t* a, const uint32_t* b) {
    asm volatile(
        "mma.sync.aligned.m16n8k16.row.col.f32.bf16.bf16.f32 "
        "{%0,%1,%2,%3}, {%4,%5,%6,%7}, {%8,%9}, {%0,%1,%2,%3};"
        : "+f"(d[0]), "+f"(d[1]), "+f"(d[2]), "+f"(d[3])
        : "r"(a[0]), "r"(a[1]), "r"(a[2]), "r"(a[3]), "r"(b[0]), "r"(b[1]));
}
__device__ __forceinline__ uint32_t cvt_bf16x2(float a, float b) {
    uint32_t r;
    asm("cvt.rn.satfinite.bf16x2.f32 %0, %1, %2;" : "=r"(r) : "f"(b), "f"(a));
    return r;
}

// ---------------- prep: fold BN into conv weights, split hi/lo bf16 ----------------
__global__ void k_prep(const float* Wg_w, const float* Wg_b, const float* gg, const float* gb,
                       const float* gm, const float* gv,
                       const float* Wx_w, const float* Wx_b, const float* xg, const float* xb,
                       const float* xm, const float* xv,
                       const float* psi_w, const float* psi_b, const float* pg, const float* pbt,
                       const float* pm, const float* pv) {
    int o = blockIdx.x, t = threadIdx.x;
    float invg = gg[o] * rsqrtf(gv[o] + 1e-5f);
    float invx = xg[o] * rsqrtf(xv[o] + 1e-5f);
    float vg = Wg_w[o*256 + t] * invg;
    float vx = Wx_w[o*256 + t] * invx;
    __nv_bfloat16 hg = __float2bfloat16(vg);
    __nv_bfloat16 hx = __float2bfloat16(vx);
    d_Wh[t*64 + o]       = hg;
    d_Wl[t*64 + o]       = __float2bfloat16(vg - __bfloat162float(hg));
    d_Wh[(256+t)*64 + o] = hx;
    d_Wl[(256+t)*64 + o] = __float2bfloat16(vx - __bfloat162float(hx));
    if (t == 0) {
        d_bias[o] = (Wg_b[o] - gm[o]) * invg + gb[o]
                  + (Wx_b[o] - xm[o]) * invx + xb[o];
    }
    if (o == 0) {
        if (t < 8) d_cmax_u[t] = 0u;
        if (t < 64) {
            float invp = pg[0] * rsqrtf(pv[0] + 1e-5f);
            d_wp[t] = psi_w[t] * invp;
            if (t == 0) d_bp[0] = (psi_b[0] - pm[0]) * invp + pbt[0];
        }
    }
}

// ---------------- psi via bf16-split HMMA ----------------
// grid (32 I-tiles, 8 b), 256 threads, 82176B dynamic smem.
// D[128 pos][64 out] = sum_{512 cin} in * Wf; inputs split hi/lo bf16 (3-product).
__global__ void __launch_bounds__(256) k_psi2(const float* __restrict__ g, const float* __restrict__ x) {
    extern __shared__ __align__(1024) char ps[];
    // A_hi [128 pos][64 cin] bf16 SWZ : 0..16384
    // A_lo                            : 16384..32768
    // W_hi [64 cin][64 out] bf16 SWZ  : 32768..40960
    // W_lo                            : 40960..49152
    // f32stage [64 c][128 p]          : 49152..81920
    // bias_s                          : 81920..82176
    // epilogue psi_t [64][132] f32    : 0..33792 (union)
    uint32_t base = smem_u32(ps);
    uint32_t ahi = base, whi = base + 32768;
    float* f32s   = (float*)(ps + 49152);
    float* bias_s = (float*)(ps + 81920);
    float* psi_t  = (float*)ps;

    int b = blockIdx.y, p0 = blockIdx.x*128, t = threadIdx.x;
    int w = t >> 5, lane = t & 31;
    if (t < 64) bias_s[t] = d_bias[t];

    float dfr[8][4];
#pragma unroll
    for (int nf = 0; nf < 8; nf++)
#pragma unroll
        for (int q = 0; q < 4; q++) dfr[nf][q] = 0.f;

    int r7 = lane & 7;
    int hsel = lane >> 4;
    uint32_t a_row = ahi + (uint32_t)(w*16 + (lane & 15))*128;
    uint32_t b_row = whi + (uint32_t)((((lane >> 3) & 1)*8 + r7))*128;

    for (int cb = 0; cb < 8; cb++) {
        __syncthreads();
        // stage fp32 input chunk [64 c][128 p]
        {
            const float* src = (cb < 4) ? g + ((size_t)b*256 + cb*64)*HWn
                                        : x + ((size_t)b*256 + (cb-4)*64)*HWn;
#pragma unroll
            for (int i = 0; i < 8; i++) {
                int idx = t + i*256;
                int c = idx >> 5, p4 = idx & 31;
                float4 v = *(const float4*)&src[(size_t)c*HWn + p0 + p4*4];
                *(float4*)&f32s[c*128 + p4*4] = v;
            }
        }
        // stage W chunk hi/lo (SWZ)
        {
#pragma unroll
            for (int q = 0; q < 2; q++) {
                int qi = t + q*256;
                int row = qi >> 3, qq = qi & 7;
                uint32_t so = SWZ((uint32_t)(row*128 + qq*16));
                *(uint4*)(ps + 32768 + so) =
                    *(const uint4*)((const char*)d_Wh + (size_t)(cb*64+row)*128 + qq*16);
                *(uint4*)(ps + 40960 + so) =
                    *(const uint4*)((const char*)d_Wl + (size_t)(cb*64+row)*128 + qq*16);
            }
        }
        __syncthreads();
        // convert fp32 -> A_hi/A_lo [pos][cin] bf16 SWZ
        {
            int p = t & 127, half = t >> 7;
#pragma unroll
            for (int oct = 0; oct < 4; oct++) {
                int c0 = half*32 + oct*8;
                float v[8];
#pragma unroll
                for (int j = 0; j < 8; j++) v[j] = f32s[(c0+j)*128 + p];
                uint32_t uh[4], ul[4];
#pragma unroll
                for (int j = 0; j < 4; j++) {
                    uint32_t h = cvt_bf16x2(v[2*j], v[2*j+1]);
                    float h0 = __uint_as_float(h << 16);
                    float h1 = __uint_as_float(h & 0xffff0000u);
                    uh[j] = h;
                    ul[j] = cvt_bf16x2(v[2*j] - h0, v[2*j+1] - h1);
                }
                uint32_t so = SWZ((uint32_t)(p*128 + c0*2));
                *(uint4*)(ps + so)         = make_uint4(uh[0], uh[1], uh[2], uh[3]);
                *(uint4*)(ps + 16384 + so) = make_uint4(ul[0], ul[1], ul[2], ul[3]);
            }
        }
        __syncthreads();
        // MMA: 4 k16 steps x 8 n8 tiles x 3 products
        uint32_t afh[4][4], afl[4][4];
#pragma unroll
        for (int ks = 0; ks < 4; ks++) {
            uint32_t aq = (uint32_t)(((2*ks + hsel) ^ r7) * 16);
            ldsm_x4(afh[ks][0], afh[ks][1], afh[ks][2], afh[ks][3], a_row + aq);
            ldsm_x4(afl[ks][0], afl[ks][1], afl[ks][2], afl[ks][3], a_row + 16384 + aq);
        }
#pragma unroll
        for (int ks = 0; ks < 4; ks++) {
#pragma unroll
            for (int nn = 0; nn < 4; nn++) {
                uint32_t bq = (uint32_t)(((2*nn + hsel) ^ r7) * 16);
                uint32_t baddr = b_row + ks*2048 + bq;
                uint32_t bh[4], bl[4];
                ldsm_x4t(bh[0], bh[1], bh[2], bh[3], baddr);
                ldsm_x4t(bl[0], bl[1], bl[2], bl[3], baddr + 8192);
                mma_bf16(dfr[2*nn],   afh[ks], bh);
                mma_bf16(dfr[2*nn],   afh[ks], bl);
                mma_bf16(dfr[2*nn],   afl[ks], bh);
                mma_bf16(dfr[2*nn+1], afh[ks], bh + 2);
                mma_bf16(dfr[2*nn+1], afh[ks], bl + 2);
                mma_bf16(dfr[2*nn+1], afl[ks], bh + 2);
            }
        }
    }
    __syncthreads();
    // epilogue: bias + relu, transpose via smem, coalesced store
    {
        int gr = lane >> 2, tc = lane & 3;
        int i1 = w*16 + gr, i2 = i1 + 8;
#pragma unroll
        for (int nf = 0; nf < 8; nf++) {
            int c0 = nf*8 + 2*tc;
            float b0 = bias_s[c0], b1 = bias_s[c0+1];
            psi_t[c0*132 + i1]     = fmaxf(dfr[nf][0] + b0, 0.f);
            psi_t[(c0+1)*132 + i1] = fmaxf(dfr[nf][1] + b1, 0.f);
            psi_t[c0*132 + i2]     = fmaxf(dfr[nf][2] + b0, 0.f);
            psi_t[(c0+1)*132 + i2] = fmaxf(dfr[nf][3] + b1, 0.f);
        }
    }
    __syncthreads();
    for (int idx = t; idx < 8192; idx += 256) {
        int c = idx >> 7, p = idx & 127;
        d_psi[((size_t)b*Cn + c)*HWn + p0 + p] = psi_t[c*132 + p];
    }
}

// ---------------- fb/fc/fd convs + fc-norm max + CAM gram partial ----------------
__global__ void __launch_bounds__(256) k_small(const float* __restrict__ pb_w, const float* __restrict__ pb_b,
                                               const float* __restrict__ pc_w, const float* __restrict__ pc_b,
                                               const float* __restrict__ pd_w, const float* __restrict__ pd_b) {
    extern __shared__ float smm[];
    float* A      = smm;              // psi tile [64][129] = 8256
    float* w_s    = smm + 8256;       // [c][o] 64*80 = 5120
    float* bias_s = w_s + 5120;       // 80
    int b = blockIdx.y, p0 = blockIdx.x*128, t = threadIdx.x;
    int pos = t & 127, half = t >> 7;
    for (int idx = t; idx < 8192; idx += 256) {
        int c = idx >> 7, p = idx & 127;
        A[c*129 + p] = d_psi[((size_t)b*Cn + c)*HWn + p0 + p];
    }
    for (int idx = t; idx < 5120; idx += 256) {
        int c = idx / 80, o = idx % 80;
        float w;
        if (o < 8)       w = pb_w[o*64 + c];
        else if (o < 16) w = pc_w[(o-8)*64 + c];
        else             w = pd_w[(o-16)*64 + c];
        w_s[idx] = w;
    }
    if (t < 80) bias_s[t] = (t < 8) ? pb_b[t] : (t < 16 ? pc_b[t-8] : pd_b[t-16]);
    __syncthreads();
    int o0 = half*40;
    ull acc[20];
#pragma unroll
    for (int q = 0; q < 20; q++) acc[q] = pk2(bias_s[o0 + 2*q], bias_s[o0 + 2*q + 1]);
    for (int c = 0; c < 64; c++) {
        float v = A[c*129 + pos];
        ull v2 = pk2(v, v);
        const ull* wr = (const ull*)&w_s[c*80 + o0];
#pragma unroll
        for (int q = 0; q < 20; q++) acc[q] = ffma2(v2, wr[q], acc[q]);
    }
    // fc norm max (half 0 threads hold the full fc vector: acc[4..7])
    if (half == 0) {
        float s = 0.f;
#pragma unroll
        for (int q = 4; q < 8; q++) { float v0, v1; upk2(acc[q], v0, v1); s += v0*v0 + v1*v1; }
#pragma unroll
        for (int m = 16; m; m >>= 1) s = fmaxf(s, __shfl_xor_sync(0xffffffffu, s, m));
        if ((t & 31) == 0) atomicMax(&d_cmax_u[b], __float_as_uint(s));
    }
#pragma unroll
    for (int q = 0; q < 20; q++) {
        float v0, v1; upk2(acc[q], v0, v1);
        int o = o0 + 2*q;
#pragma unroll
        for (int s = 0; s < 2; s++) {
            float v = s ? v1 : v0;
            int oo = o + s;
            if (oo < 8)       d_fb[((size_t)b*8 + oo)*HWn + p0 + pos] = v * LOG2E;
            else if (oo < 16) d_fc[((size_t)b*8 + (oo-8))*HWn + p0 + pos] = v;
            else              d_fdh[((size_t)b*64 + (oo-16))*HWn + p0 + pos] = __float2bfloat16(v);
        }
    }
    // CAM gram partial over this 128-pos segment (A still valid)
    {
        int cjg = t & 15, cig = t >> 4;
        float ga[4][4];
#pragma unroll
        for (int r = 0; r < 4; r++)
#pragma unroll
            for (int q = 0; q < 4; q++) ga[r][q] = 0.f;
        for (int p = 0; p < 128; p++) {
            float a0 = A[(cig*4+0)*129 + p];
            float a1 = A[(cig*4+1)*129 + p];
            float a2 = A[(cig*4+2)*129 + p];
            float a3 = A[(cig*4+3)*129 + p];
            float b0 = A[(cjg*4+0)*129 + p];
            float b1 = A[(cjg*4+1)*129 + p];
            float b2 = A[(cjg*4+2)*129 + p];
            float b3 = A[(cjg*4+3)*129 + p];
            ga[0][0]+=a0*b0; ga[0][1]+=a0*b1; ga[0][2]+=a0*b2; ga[0][3]+=a0*b3;
            ga[1][0]+=a1*b0; ga[1][1]+=a1*b1; ga[1][2]+=a1*b2; ga[1][3]+=a1*b3;
            ga[2][0]+=a2*b0; ga[2][1]+=a2*b1; ga[2][2]+=a2*b2; ga[2][3]+=a2*b3;
            ga[3][0]+=a3*b0; ga[3][1]+=a3*b1; ga[3][2]+=a3*b2; ga[3][3]+=a3*b3;
        }
#pragma unroll
        for (int r = 0; r < 4; r++)
#pragma unroll
            for (int q = 0; q < 4; q++)
                d_attp[blockIdx.x*(Bn*4096) + (b*64 + cig*4 + r)*64 + cjg*4 + q] = ga[r][q];
    }
}

// ---------------- CAM softmax -> W2[c][d] = beta*wp[c]*attw[c][d] ----------------
__global__ void k_cam_soft(const float* __restrict__ beta_p) {
    int b = blockIdx.x, ci = threadIdx.x;
    float v[64];
#pragma unroll
    for (int d = 0; d < 64; d++) {
        float s = 0.f;
        for (int sgm = 0; sgm < 32; sgm++) s += d_attp[sgm*(Bn*4096) + (b*64 + ci)*64 + d];
        v[d] = s;
    }
    float mx = -1e30f, mn = 1e30f;
#pragma unroll
    for (int d = 0; d < 64; d++) { mx = fmaxf(mx, v[d]); mn = fminf(mn, v[d]); }
    float m2 = mx - mn;
    float ssum = 0.f;
#pragma unroll
    for (int d = 0; d < 64; d++) { float e = __expf((mx - v[d]) - m2); v[d] = e; ssum += e; }
    float scale = beta_p[0] * d_wp[ci] / ssum;
#pragma unroll
    for (int d = 0; d < 64; d++) d_W2[b*4096 + ci*64 + d] = v[d] * scale;
}

// ---------------- PAM + CAM-gate + final multiply, fully fused ----------------
__global__ void __launch_bounds__(256, 2) k_pam3(const float* __restrict__ alpha_p,
                                                 const float* __restrict__ x,
                                                 float* __restrict__ out) {
    extern __shared__ __align__(1024) char dsm[];
    char*  p_bf  = dsm;                       // 16384
    char*  fd_bf = dsm + 16384;               // 8192
    float* fb_s  = (float*)(dsm + 24576);     // 1024 f
    float* fc_s  = (float*)(dsm + 28672);     // 512 f
    float* zr_s  = (float*)(dsm + 30720);     // 2176 f
    float* mh_s  = (float*)(dsm + 39424);     // 128 f
    // epilogue union
    float* psi_s = (float*)dsm;               // 64*132 f
    float* pam_s = (float*)(dsm + 33792);     // 64*132 f
    float* W2_s  = (float*)(dsm + 67584);     // 4096 f
    float* wp_s  = (float*)(dsm + 83968);     // 64 f
    float* gred  = (float*)(dsm + 84224);     // 256 f
    float* z_s   = (float*)(dsm + 85248);     // 128 f

    uint32_t pbase  = smem_u32(dsm);
    uint32_t fdbase = pbase + 16384;

    int b = blockIdx.y, I0 = blockIdx.x*128, t = threadIdx.x;
    int w = t >> 5, lane = t & 31;
    int ig = t >> 4, cg = t & 15;
    int i0 = ig * 8;

    for (int idx = t; idx < 1024; idx += 256)
        fb_s[idx] = d_fb[((size_t)b*8 + (idx >> 7))*HWn + I0 + (idx & 127)];
    __syncthreads();
    if (t < 128) {
        float s = 0.f;
#pragma unroll
        for (int k = 0; k < 8; k++) { float v = fb_s[k*128 + t]; s += v*v; }
        mh_s[t] = sqrtf(s) * sqrtf(__uint_as_float(d_cmax_u[b])) * LOG2E;
    }
    __syncthreads();

    float mhr[8];
#pragma unroll
    for (int r = 0; r < 8; r++) mhr[r] = mh_s[i0 + r];
    float zacc[8];
#pragma unroll
    for (int r = 0; r < 8; r++) zacc[r] = 0.f;

    float acc[8][4];
#pragma unroll
    for (int ng = 0; ng < 8; ng++)
#pragma unroll
        for (int q = 0; q < 4; q++) acc[ng][q] = 0.f;

    uint32_t a_addr[4], b_addr[8][2];
#pragma unroll
    for (int ks = 0; ks < 4; ks++) {
        uint32_t row = w*16 + (lane & 15);
        uint32_t off = row*128 + ks*32 + ((lane >> 4) ? 16u : 0u);
        a_addr[ks] = pbase + SWZ(off);
    }
#pragma unroll
    for (int ng = 0; ng < 8; ng++)
#pragma unroll
        for (int kp = 0; kp < 2; kp++) {
            uint32_t row = ng*8 + (lane & 7);
            uint32_t off = row*128 + kp*64 + ((lane >> 3) & 3)*16;
            b_addr[ng][kp] = fdbase + SWZ(off);
        }

    // prefetch jt=0 staging into registers
    float fcr0, fcr1;
    uint32_t fdr[8];
    {
        fcr0 = d_fc[((size_t)b*8 + (t >> 6))*HWn + (t & 63)];
        fcr1 = d_fc[((size_t)b*8 + ((t+256) >> 6))*HWn + ((t+256) & 63)];
#pragma unroll
        for (int q = 0; q < 8; q++) {
            int idx = t + q*256;
            int c = idx >> 5, jp = idx & 31;
            fdr[q] = *(const uint32_t*)&d_fdh[((size_t)b*64 + c)*HWn + jp*2];
        }
    }

    for (int jt = 0; jt < 64; jt++) {
        __syncthreads();   // prev mma done reading smem
        fc_s[t]       = fcr0;
        fc_s[t + 256] = fcr1;
#pragma unroll
        for (int q = 0; q < 8; q++) {
            int idx = t + q*256;
            int c = idx >> 5, jp = idx & 31;
            *(uint32_t*)(fd_bf + SWZ((uint32_t)(c*128 + jp*4))) = fdr[q];
        }
        __syncthreads();
        // energies (log2 domain) -> p = ex2(e - mhat) -> bf16
        ull fc2[16];
#pragma unroll
        for (int k = 0; k < 8; k++) {
            float4 f = *(const float4*)&fc_s[k*64 + cg*4];
            fc2[2*k] = pk2(f.x, f.y); fc2[2*k+1] = pk2(f.z, f.w);
        }
        ull e[16];
#pragma unroll
        for (int q = 0; q < 16; q++) e[q] = 0ull;
#pragma unroll
        for (int k = 0; k < 8; k++) {
            float4 fa = *(const float4*)&fb_s[k*128 + i0];
            float4 fbv = *(const float4*)&fb_s[k*128 + i0 + 4];
            float fv[8] = {fa.x, fa.y, fa.z, fa.w, fbv.x, fbv.y, fbv.z, fbv.w};
#pragma unroll
            for (int r = 0; r < 8; r++) {
                ull f2 = pk2(fv[r], fv[r]);
                e[2*r]   = ffma2(f2, fc2[2*k],   e[2*r]);
                e[2*r+1] = ffma2(f2, fc2[2*k+1], e[2*r+1]);
            }
        }
        // prefetch next tile (overlaps with exp/cvt below)
        if (jt < 63) {
            int j0n = (jt+1)*64;
            fcr0 = d_fc[((size_t)b*8 + (t >> 6))*HWn + j0n + (t & 63)];
            fcr1 = d_fc[((size_t)b*8 + ((t+256) >> 6))*HWn + j0n + ((t+256) & 63)];
#pragma unroll
            for (int q = 0; q < 8; q++) {
                int idx = t + q*256;
                int c = idx >> 5, jp = idx & 31;
                fdr[q] = *(const uint32_t*)&d_fdh[((size_t)b*64 + c)*HWn + j0n + jp*2];
            }
        }
#pragma unroll
        for (int r = 0; r < 8; r++) {
            float e0, e1, e2, e3;
            upk2(e[2*r], e0, e1); upk2(e[2*r+1], e2, e3);
            float m = mhr[r];
            float q0 = ex2f(e0 - m), q1 = ex2f(e1 - m);
            float q2 = ex2f(e2 - m), q3 = ex2f(e3 - m);
            zacc[r] += (q0 + q1) + (q2 + q3);
            uint32_t pa  = cvt_bf16x2(q0, q1);
            uint32_t pbb = cvt_bf16x2(q2, q3);
            ull pkd = (ull)pa | ((ull)pbb << 32);
            uint32_t off = (uint32_t)((i0 + r)*128 + cg*8);
            *(ull*)(p_bf + SWZ(off)) = pkd;
        }
        __syncthreads();
        uint32_t afr[4][4];
#pragma unroll
        for (int ks = 0; ks < 4; ks++)
            ldsm_x4(afr[ks][0], afr[ks][1], afr[ks][2], afr[ks][3], a_addr[ks]);
#pragma unroll
        for (int ng = 0; ng < 8; ng++) {
#pragma unroll
            for (int kp = 0; kp < 2; kp++) {
                uint32_t bb[4];
                ldsm_x4(bb[0], bb[1], bb[2], bb[3], b_addr[ng][kp]);
                mma_bf16(acc[ng], afr[2*kp],     bb);
                mma_bf16(acc[ng], afr[2*kp + 1], bb + 2);
            }
        }
    }
    // ---- z reduction ----
    __syncthreads();
#pragma unroll
    for (int r = 0; r < 8; r++) zr_s[(i0 + r)*17 + cg] = zacc[r];
    __syncthreads();
    if (t < 128) {
        float s = 0.f;
#pragma unroll
        for (int q = 0; q < 16; q++) s += zr_s[t*17 + q];
        z_s[t] = alpha_p[0] / s;
    }
    __syncthreads();
    // ---- load psi tile / W2 / wp ----
    for (int idx = t; idx < 8192; idx += 256) {
        int c = idx >> 7, p = idx & 127;
        psi_s[c*132 + p] = d_psi[((size_t)b*Cn + c)*HWn + I0 + p];
    }
    for (int idx = t; idx < 4096; idx += 256) W2_s[idx] = d_W2[b*4096 + idx];
    if (t < 64) wp_s[t] = d_wp[t];
    __syncthreads();
    // ---- fragments -> pam_s[c][i] ----
    {
        int gr = lane >> 2, tc = lane & 3;
        int i1 = w*16 + gr, i2 = i1 + 8;
        float z1 = z_s[i1], z2 = z_s[i2];
#pragma unroll
        for (int ng = 0; ng < 8; ng++) {
            int c = ng*8 + 2*tc;
            pam_s[c*132 + i1]     = acc[ng][0]*z1 + psi_s[c*132 + i1];
            pam_s[(c+1)*132 + i1] = acc[ng][1]*z1 + psi_s[(c+1)*132 + i1];
            pam_s[c*132 + i2]     = acc[ng][2]*z2 + psi_s[c*132 + i2];
            pam_s[(c+1)*132 + i2] = acc[ng][3]*z2 + psi_s[(c+1)*132 + i2];
        }
    }
    __syncthreads();
    // ---- fused CAM + gate ----
    {
        int p = t & 127, half = t >> 7;
        int c0 = half*32, d0 = half*32;
        float part1 = 0.f;
#pragma unroll 8
        for (int c = 0; c < 32; c++) {
            int cc = c0 + c;
            part1 += wp_s[cc] * psi_s[cc*132 + p] * pam_s[cc*132 + p];
        }
        ull v[16];
#pragma unroll
        for (int q = 0; q < 16; q++) v[q] = 0ull;
        for (int c = 0; c < 64; c++) {
            float pm = pam_s[c*132 + p];
            ull pm2 = pk2(pm, pm);
            const ull* wr = (const ull*)&W2_s[c*64 + d0];
#pragma unroll
            for (int q = 0; q < 16; q++) v[q] = ffma2(pm2, wr[q], v[q]);
        }
        float part2 = 0.f;
#pragma unroll
        for (int q = 0; q < 16; q++) {
            float v0, v1; upk2(v[q], v0, v1);
            part2 += psi_s[(d0+2*q)*132 + p]*v0 + psi_s[(d0+2*q+1)*132 + p]*v1;
        }
        gred[half*128 + p] = part1 + part2;
    }
    __syncthreads();
    if (t < 128) {
        float gate = d_bp[0] + gred[t] + gred[128 + t];
        z_s[t] = 1.f / (1.f + __expf(-gate));   // da
    }
    __syncthreads();
    // ---- fused final multiply: out[b,:,I0..I0+127] = x * da ----
    {
        int p = t & 127, hb = t >> 7;
        float da = z_s[p];
        const float* xp = x + ((size_t)b*256)*HWn + I0 + p;
        float* op = out + ((size_t)b*256)*HWn + I0 + p;
#pragma unroll 8
        for (int c = hb; c < 256; c += 2)
            op[(size_t)c*HWn] = xp[(size_t)c*HWn] * da;
    }
}

// ---------------- launch ----------------
extern "C" void kernel_launch(void* const* d_in, const int* in_sizes, int n_in,
                              void* d_out, int out_size) {
    const float* g = (const float*)d_in[0];
    const float* x = (const float*)d_in[1];

    cudaFuncSetAttribute(k_psi2,  cudaFuncAttributeMaxDynamicSharedMemorySize, 82176);
    cudaFuncSetAttribute(k_small, cudaFuncAttributeMaxDynamicSharedMemorySize, 13456*4);
    cudaFuncSetAttribute(k_pam3,  cudaFuncAttributeMaxDynamicSharedMemorySize, 85760);

    k_prep<<<64, 256>>>((const float*)d_in[2],  (const float*)d_in[3],  (const float*)d_in[4],
                        (const float*)d_in[5],  (const float*)d_in[6],  (const float*)d_in[7],
                        (const float*)d_in[8],  (const float*)d_in[9],  (const float*)d_in[10],
                        (const float*)d_in[11], (const float*)d_in[12], (const float*)d_in[13],
                        (const float*)d_in[14], (const float*)d_in[15], (const float*)d_in[16],
                        (const float*)d_in[17], (const float*)d_in[18], (const float*)d_in[19]);

    k_psi2<<<dim3(32, 8), 256, 82176>>>(g, x);

    k_small<<<dim3(32, 8), 256, 13456*4>>>(
        (const float*)d_in[20], (const float*)d_in[21],
        (const float*)d_in[22], (const float*)d_in[23],
        (const float*)d_in[24], (const float*)d_in[25]);

    k_cam_soft<<<8, 64>>>((const float*)d_in[27]);

    k_pam3<<<dim3(32, 8), 256, 85760>>>((const float*)d_in[26], x, (float*)d_out);
}

// round 7
// speedup vs baseline: 4.5497x; 1.1921x over previous
#include <cuda_runtime.h>
#include <cuda_bf16.h>
#include <math.h>
#include <stdint.h>

typedef unsigned long long ull;

#define Bn 8
#define Cn 64
#define HWn 4096
#define LOG2E 1.4426950408889634f

// ---------------- scratch (device globals; no allocs allowed) ----------------
__device__ __align__(16) float d_psi[Bn*Cn*HWn];     // 8MB
__device__ __align__(16) float d_fb [Bn*8*HWn];      // pre-scaled by log2(e)
__device__ __align__(16) float d_fc [Bn*8*HWn];
__device__ __align__(16) __nv_bfloat16 d_fdh[Bn*Cn*HWn];  // 4MB bf16 [b][c][j]
__device__ __align__(16) float d_attp[32*Bn*64*64];  // CAM partial gram
__device__ __align__(16) float d_W2[Bn*64*64];       // beta*wp[c]*attw[c][d]
__device__ __align__(16) __nv_bfloat16 d_Wh[512*64]; // folded weight hi, [cin][out]
__device__ __align__(16) __nv_bfloat16 d_Wl[512*64]; // folded weight lo
__device__ __align__(16) float d_bias[64];
__device__ __align__(16) float d_wp[64];
__device__ __align__(16) float d_bp[1];
__device__ unsigned d_cmax_u[8];                     // max_j ||fc_j||^2 (bits)

// ---------------- f32x2 helpers ----------------
__device__ __forceinline__ ull pk2(float lo, float hi) {
    ull r; asm("mov.b64 %0, {%1, %2};" : "=l"(r) : "f"(lo), "f"(hi)); return r;
}
__device__ __forceinline__ void upk2(ull v, float& lo, float& hi) {
    asm("mov.b64 {%0, %1}, %2;" : "=f"(lo), "=f"(hi) : "l"(v));
}
__device__ __forceinline__ ull ffma2(ull a, ull b, ull c) {
    ull d; asm("fma.rn.f32x2 %0, %1, %2, %3;" : "=l"(d) : "l"(a), "l"(b), "l"(c)); return d;
}
__device__ __forceinline__ float ex2f(float x) {
    float r; asm("ex2.approx.f32 %0, %1;" : "=f"(r) : "f"(x)); return r;
}

// ---------------- warp MMA helpers ----------------
__device__ __forceinline__ uint32_t smem_u32(const void* p) {
    uint32_t a;
    asm("{ .reg .u64 t; cvta.to.shared.u64 t, %1; cvt.u32.u64 %0, t; }" : "=r"(a) : "l"(p));
    return a;
}
#define SWZ(off) ((off) ^ (((off) >> 3) & 0x70))
__device__ __forceinline__ void ldsm_x4(uint32_t& r0, uint32_t& r1, uint32_t& r2, uint32_t& r3,
                                        uint32_t addr) {
    asm volatile("ldmatrix.sync.aligned.m8n8.x4.shared.b16 {%0,%1,%2,%3}, [%4];"
                 : "=r"(r0), "=r"(r1), "=r"(r2), "=r"(r3) : "r"(addr));
}
__device__ __forceinline__ void ldsm_x4t(uint32_t& r0, uint32_t& r1, uint32_t& r2, uint32_t& r3,
                                         uint32_t addr) {
    asm volatile("ldmatrix.sync.aligned.m8n8.x4.trans.shared.b16 {%0,%1,%2,%3}, [%4];"
                 : "=r"(r0), "=r"(r1), "=r"(r2), "=r"(r3) : "r"(addr));
}
__device__ __forceinline__ void mma_bf16(float* d, const uint32_t* a, const uint32_t* b) {
    asm volatile(
        "mma.sync.aligned.m16n8k16.row.col.f32.bf16.bf16.f32 "
        "{%0,%1,%2,%3}, {%4,%5,%6,%7}, {%8,%9}, {%0,%1,%2,%3};"
        : "+f"(d[0]), "+f"(d[1]), "+f"(d[2]), "+f"(d[3])
        : "r"(a[0]), "r"(a[1]), "r"(a[2]), "r"(a[3]), "r"(b[0]), "r"(b[1]));
}
__device__ __forceinline__ void mma_bf16s(float* d, const uint32_t* a, uint32_t b0, uint32_t b1) {
    asm volatile(
        "mma.sync.aligned.m16n8k16.row.col.f32.bf16.bf16.f32 "
        "{%0,%1,%2,%3}, {%4,%5,%6,%7}, {%8,%9}, {%0,%1,%2,%3};"
        : "+f"(d[0]), "+f"(d[1]), "+f"(d[2]), "+f"(d[3])
        : "r"(a[0]), "r"(a[1]), "r"(a[2]), "r"(a[3]), "r"(b0), "r"(b1));
}
__device__ __forceinline__ uint32_t cvt_bf16x2(float a, float b) {
    uint32_t r;
    asm("cvt.rn.satfinite.bf16x2.f32 %0, %1, %2;" : "=r"(r) : "f"(b), "f"(a));
    return r;
}

// ---------------- prep: fold BN into conv weights, split hi/lo bf16 ----------------
__global__ void k_prep(const float* Wg_w, const float* Wg_b, const float* gg, const float* gb,
                       const float* gm, const float* gv,
                       const float* Wx_w, const float* Wx_b, const float* xg, const float* xb,
                       const float* xm, const float* xv,
                       const float* psi_w, const float* psi_b, const float* pg, const float* pbt,
                       const float* pm, const float* pv) {
    int o = blockIdx.x, t = threadIdx.x;
    float invg = gg[o] * rsqrtf(gv[o] + 1e-5f);
    float invx = xg[o] * rsqrtf(xv[o] + 1e-5f);
    float vg = Wg_w[o*256 + t] * invg;
    float vx = Wx_w[o*256 + t] * invx;
    __nv_bfloat16 hg = __float2bfloat16(vg);
    __nv_bfloat16 hx = __float2bfloat16(vx);
    d_Wh[t*64 + o]       = hg;
    d_Wl[t*64 + o]       = __float2bfloat16(vg - __bfloat162float(hg));
    d_Wh[(256+t)*64 + o] = hx;
    d_Wl[(256+t)*64 + o] = __float2bfloat16(vx - __bfloat162float(hx));
    if (t == 0) {
        d_bias[o] = (Wg_b[o] - gm[o]) * invg + gb[o]
                  + (Wx_b[o] - xm[o]) * invx + xb[o];
    }
    if (o == 0) {
        if (t < 8) d_cmax_u[t] = 0u;
        if (t < 64) {
            float invp = pg[0] * rsqrtf(pv[0] + 1e-5f);
            d_wp[t] = psi_w[t] * invp;
            if (t == 0) d_bp[0] = (psi_b[0] - pm[0]) * invp + pbt[0];
        }
    }
}

// ---------------- psi via bf16-split HMMA ----------------
__global__ void __launch_bounds__(256) k_psi2(const float* __restrict__ g, const float* __restrict__ x) {
    extern __shared__ __align__(1024) char ps[];
    uint32_t base = smem_u32(ps);
    uint32_t ahi = base, whi = base + 32768;
    float* f32s   = (float*)(ps + 49152);
    float* bias_s = (float*)(ps + 81920);
    float* psi_t  = (float*)ps;

    int b = blockIdx.y, p0 = blockIdx.x*128, t = threadIdx.x;
    int w = t >> 5, lane = t & 31;
    if (t < 64) bias_s[t] = d_bias[t];

    float dfr[8][4];
#pragma unroll
    for (int nf = 0; nf < 8; nf++)
#pragma unroll
        for (int q = 0; q < 4; q++) dfr[nf][q] = 0.f;

    int r7 = lane & 7;
    int hsel = lane >> 4;
    uint32_t a_row = ahi + (uint32_t)(w*16 + (lane & 15))*128;
    uint32_t b_row = whi + (uint32_t)((((lane >> 3) & 1)*8 + r7))*128;

    for (int cb = 0; cb < 8; cb++) {
        __syncthreads();
        {
            const float* src = (cb < 4) ? g + ((size_t)b*256 + cb*64)*HWn
                                        : x + ((size_t)b*256 + (cb-4)*64)*HWn;
#pragma unroll
            for (int i = 0; i < 8; i++) {
                int idx = t + i*256;
                int c = idx >> 5, p4 = idx & 31;
                float4 v = *(const float4*)&src[(size_t)c*HWn + p0 + p4*4];
                *(float4*)&f32s[c*128 + p4*4] = v;
            }
        }
        {
#pragma unroll
            for (int q = 0; q < 2; q++) {
                int qi = t + q*256;
                int row = qi >> 3, qq = qi & 7;
                uint32_t so = SWZ((uint32_t)(row*128 + qq*16));
                *(uint4*)(ps + 32768 + so) =
                    *(const uint4*)((const char*)d_Wh + (size_t)(cb*64+row)*128 + qq*16);
                *(uint4*)(ps + 40960 + so) =
                    *(const uint4*)((const char*)d_Wl + (size_t)(cb*64+row)*128 + qq*16);
            }
        }
        __syncthreads();
        {
            int p = t & 127, half = t >> 7;
#pragma unroll
            for (int oct = 0; oct < 4; oct++) {
                int c0 = half*32 + oct*8;
                float v[8];
#pragma unroll
                for (int j = 0; j < 8; j++) v[j] = f32s[(c0+j)*128 + p];
                uint32_t uh[4], ul[4];
#pragma unroll
                for (int j = 0; j < 4; j++) {
                    uint32_t h = cvt_bf16x2(v[2*j], v[2*j+1]);
                    float h0 = __uint_as_float(h << 16);
                    float h1 = __uint_as_float(h & 0xffff0000u);
                    uh[j] = h;
                    ul[j] = cvt_bf16x2(v[2*j] - h0, v[2*j+1] - h1);
                }
                uint32_t so = SWZ((uint32_t)(p*128 + c0*2));
                *(uint4*)(ps + so)         = make_uint4(uh[0], uh[1], uh[2], uh[3]);
                *(uint4*)(ps + 16384 + so) = make_uint4(ul[0], ul[1], ul[2], ul[3]);
            }
        }
        __syncthreads();
        uint32_t afh[4][4], afl[4][4];
#pragma unroll
        for (int ks = 0; ks < 4; ks++) {
            uint32_t aq = (uint32_t)(((2*ks + hsel) ^ r7) * 16);
            ldsm_x4(afh[ks][0], afh[ks][1], afh[ks][2], afh[ks][3], a_row + aq);
            ldsm_x4(afl[ks][0], afl[ks][1], afl[ks][2], afl[ks][3], a_row + 16384 + aq);
        }
#pragma unroll
        for (int ks = 0; ks < 4; ks++) {
#pragma unroll
            for (int nn = 0; nn < 4; nn++) {
                uint32_t bq = (uint32_t)(((2*nn + hsel) ^ r7) * 16);
                uint32_t baddr = b_row + ks*2048 + bq;
                uint32_t bh[4], bl[4];
                ldsm_x4t(bh[0], bh[1], bh[2], bh[3], baddr);
                ldsm_x4t(bl[0], bl[1], bl[2], bl[3], baddr + 8192);
                mma_bf16(dfr[2*nn],   afh[ks], bh);
                mma_bf16(dfr[2*nn],   afh[ks], bl);
                mma_bf16(dfr[2*nn],   afl[ks], bh);
                mma_bf16(dfr[2*nn+1], afh[ks], bh + 2);
                mma_bf16(dfr[2*nn+1], afh[ks], bl + 2);
                mma_bf16(dfr[2*nn+1], afl[ks], bh + 2);
            }
        }
    }
    __syncthreads();
    {
        int gr = lane >> 2, tc = lane & 3;
        int i1 = w*16 + gr, i2 = i1 + 8;
#pragma unroll
        for (int nf = 0; nf < 8; nf++) {
            int c0 = nf*8 + 2*tc;
            float b0 = bias_s[c0], b1 = bias_s[c0+1];
            psi_t[c0*132 + i1]     = fmaxf(dfr[nf][0] + b0, 0.f);
            psi_t[(c0+1)*132 + i1] = fmaxf(dfr[nf][1] + b1, 0.f);
            psi_t[c0*132 + i2]     = fmaxf(dfr[nf][2] + b0, 0.f);
            psi_t[(c0+1)*132 + i2] = fmaxf(dfr[nf][3] + b1, 0.f);
        }
    }
    __syncthreads();
    for (int idx = t; idx < 8192; idx += 256) {
        int c = idx >> 7, p = idx & 127;
        d_psi[((size_t)b*Cn + c)*HWn + p0 + p] = psi_t[c*132 + p];
    }
}

// ---------------- fb/fc/fd convs + fc-norm max + CAM gram partial ----------------
__global__ void __launch_bounds__(256) k_small(const float* __restrict__ pb_w, const float* __restrict__ pb_b,
                                               const float* __restrict__ pc_w, const float* __restrict__ pc_b,
                                               const float* __restrict__ pd_w, const float* __restrict__ pd_b) {
    extern __shared__ float smm[];
    float* A      = smm;              // psi tile [64][129]
    float* w_s    = smm + 8256;       // [c][o] 64*80
    float* bias_s = w_s + 5120;       // 80
    int b = blockIdx.y, p0 = blockIdx.x*128, t = threadIdx.x;
    int pos = t & 127, half = t >> 7;
    for (int idx = t; idx < 8192; idx += 256) {
        int c = idx >> 7, p = idx & 127;
        A[c*129 + p] = d_psi[((size_t)b*Cn + c)*HWn + p0 + p];
    }
    for (int idx = t; idx < 5120; idx += 256) {
        int c = idx / 80, o = idx % 80;
        float w;
        if (o < 8)       w = pb_w[o*64 + c];
        else if (o < 16) w = pc_w[(o-8)*64 + c];
        else             w = pd_w[(o-16)*64 + c];
        w_s[idx] = w;
    }
    if (t < 80) bias_s[t] = (t < 8) ? pb_b[t] : (t < 16 ? pc_b[t-8] : pd_b[t-16]);
    __syncthreads();
    int o0 = half*40;
    ull acc[20];
#pragma unroll
    for (int q = 0; q < 20; q++) acc[q] = pk2(bias_s[o0 + 2*q], bias_s[o0 + 2*q + 1]);
    for (int c = 0; c < 64; c++) {
        float v = A[c*129 + pos];
        ull v2 = pk2(v, v);
        const ull* wr = (const ull*)&w_s[c*80 + o0];
#pragma unroll
        for (int q = 0; q < 20; q++) acc[q] = ffma2(v2, wr[q], acc[q]);
    }
    if (half == 0) {
        float s = 0.f;
#pragma unroll
        for (int q = 4; q < 8; q++) { float v0, v1; upk2(acc[q], v0, v1); s += v0*v0 + v1*v1; }
#pragma unroll
        for (int m = 16; m; m >>= 1) s = fmaxf(s, __shfl_xor_sync(0xffffffffu, s, m));
        if ((t & 31) == 0) atomicMax(&d_cmax_u[b], __float_as_uint(s));
    }
#pragma unroll
    for (int q = 0; q < 20; q++) {
        float v0, v1; upk2(acc[q], v0, v1);
        int o = o0 + 2*q;
#pragma unroll
        for (int s = 0; s < 2; s++) {
            float v = s ? v1 : v0;
            int oo = o + s;
            if (oo < 8)       d_fb[((size_t)b*8 + oo)*HWn + p0 + pos] = v * LOG2E;
            else if (oo < 16) d_fc[((size_t)b*8 + (oo-8))*HWn + p0 + pos] = v;
            else              d_fdh[((size_t)b*64 + (oo-16))*HWn + p0 + pos] = __float2bfloat16(v);
        }
    }
    // CAM gram partial over this 128-pos segment
    {
        int cjg = t & 15, cig = t >> 4;
        float ga[4][4];
#pragma unroll
        for (int r = 0; r < 4; r++)
#pragma unroll
            for (int q = 0; q < 4; q++) ga[r][q] = 0.f;
        for (int p = 0; p < 128; p++) {
            float a0 = A[(cig*4+0)*129 + p];
            float a1 = A[(cig*4+1)*129 + p];
            float a2 = A[(cig*4+2)*129 + p];
            float a3 = A[(cig*4+3)*129 + p];
            float b0 = A[(cjg*4+0)*129 + p];
            float b1 = A[(cjg*4+1)*129 + p];
            float b2 = A[(cjg*4+2)*129 + p];
            float b3 = A[(cjg*4+3)*129 + p];
            ga[0][0]+=a0*b0; ga[0][1]+=a0*b1; ga[0][2]+=a0*b2; ga[0][3]+=a0*b3;
            ga[1][0]+=a1*b0; ga[1][1]+=a1*b1; ga[1][2]+=a1*b2; ga[1][3]+=a1*b3;
            ga[2][0]+=a2*b0; ga[2][1]+=a2*b1; ga[2][2]+=a2*b2; ga[2][3]+=a2*b3;
            ga[3][0]+=a3*b0; ga[3][1]+=a3*b1; ga[3][2]+=a3*b2; ga[3][3]+=a3*b3;
        }
#pragma unroll
        for (int r = 0; r < 4; r++)
#pragma unroll
            for (int q = 0; q < 4; q++)
                d_attp[blockIdx.x*(Bn*4096) + (b*64 + cig*4 + r)*64 + cjg*4 + q] = ga[r][q];
    }
}

// ---------------- CAM softmax (parallel reduction) -> W2 ----------------
__global__ void __launch_bounds__(256) k_cam_soft2(const float* __restrict__ beta_p) {
    __shared__ float att[64*65];
    int b = blockIdx.x, t = threadIdx.x;
    for (int idx = t; idx < 4096; idx += 256) {
        float s = 0.f;
#pragma unroll
        for (int sgm = 0; sgm < 32; sgm++)
            s += d_attp[sgm*(Bn*4096) + b*4096 + idx];
        att[(idx >> 6)*65 + (idx & 63)] = s;
    }
    __syncthreads();
    if (t < 64) {
        float v[64];
#pragma unroll
        for (int d = 0; d < 64; d++) v[d] = att[t*65 + d];
        float mx = -1e30f, mn = 1e30f;
#pragma unroll
        for (int d = 0; d < 64; d++) { mx = fmaxf(mx, v[d]); mn = fminf(mn, v[d]); }
        float m2 = mx - mn;
        float ssum = 0.f;
#pragma unroll
        for (int d = 0; d < 64; d++) { float e = __expf((mx - v[d]) - m2); v[d] = e; ssum += e; }
        float scale = beta_p[0] * d_wp[t] / ssum;
#pragma unroll
        for (int d = 0; d < 64; d++) d_W2[b*4096 + t*64 + d] = v[d] * scale;
    }
}

// ---------------- PAM + CAM-gate + final multiply, energy on tensor pipe ----------------
// grid (32 I-tiles, 8 b), 256 threads, 85760B dynamic smem.
// e = fb^T fc via bf16-split HMMA (3 products, exact to ~2^-16); exp in fragments;
// p packed directly into A-frags of the P*fd accumulate mma (p never touches smem).
__global__ void __launch_bounds__(256, 2) k_pam3(const float* __restrict__ alpha_p,
                                                 const float* __restrict__ x,
                                                 float* __restrict__ out) {
    extern __shared__ __align__(1024) char dsm[];
    // mainloop: fd_bf 0..8192 (SWZ [c][j]); fbh 8192..14336 (128x48B); fbl 14336..20480;
    //           fch 20480..23552 (64x48B); fcl 23552..26624; mh 26624..27136; zr 27136..29184
    float* mh_s = (float*)(dsm + 26624);
    float* zr_s = (float*)(dsm + 27136);
    // epilogue union
    float* psi_s = (float*)dsm;               // 64*132 f
    float* pam_s = (float*)(dsm + 33792);     // 64*132 f
    float* W2_s  = (float*)(dsm + 67584);     // 4096 f
    float* wp_s  = (float*)(dsm + 83968);     // 64 f
    float* gred  = (float*)(dsm + 84224);     // 256 f
    float* z_s   = (float*)(dsm + 85248);     // 128 f

    uint32_t sbase  = smem_u32(dsm);
    uint32_t fdbase = sbase;
    uint32_t fbh = sbase + 8192;
    uint32_t fch = sbase + 20480;

    int b = blockIdx.y, I0 = blockIdx.x*128, t = threadIdx.x;
    int w = t >> 5, lane = t & 31;
    int gr = lane >> 2, tc = lane & 3;
    int i1 = w*16 + gr, i2 = i1 + 8;

    // zero k8-15 pad of fb (2 bufs x 128 rows x 16B) and fc (2 bufs x 64 rows x 16B)
    for (int idx = t; idx < 1536; idx += 256) {
        char* p;
        if (idx < 512)        p = dsm + 8192  + (idx>>2)*48 + 16 + (idx&3)*4;
        else if (idx < 1024)  p = dsm + 14336 + ((idx-512)>>2)*48 + 16 + (idx&3)*4;
        else if (idx < 1280)  p = dsm + 20480 + ((idx-1024)>>2)*48 + 16 + (idx&3)*4;
        else                  p = dsm + 23552 + ((idx-1280)>>2)*48 + 16 + (idx&3)*4;
        *(uint32_t*)p = 0u;
    }
    // stage fb bf16 hi/lo [i][k] (48B rows) + sumsq partials
    {
        int i = t & 127, half = t >> 7;
        float v0 = d_fb[((size_t)b*8 + half*4 + 0)*HWn + I0 + i];
        float v1 = d_fb[((size_t)b*8 + half*4 + 1)*HWn + I0 + i];
        float v2 = d_fb[((size_t)b*8 + half*4 + 2)*HWn + I0 + i];
        float v3 = d_fb[((size_t)b*8 + half*4 + 3)*HWn + I0 + i];
        uint32_t h0 = cvt_bf16x2(v0, v1), h1 = cvt_bf16x2(v2, v3);
        float r0 = __uint_as_float(h0 << 16), r1 = __uint_as_float(h0 & 0xffff0000u);
        float r2 = __uint_as_float(h1 << 16), r3 = __uint_as_float(h1 & 0xffff0000u);
        uint32_t l0 = cvt_bf16x2(v0 - r0, v1 - r1), l1 = cvt_bf16x2(v2 - r2, v3 - r3);
        *(uint32_t*)(dsm + 8192  + i*48 + half*8)     = h0;
        *(uint32_t*)(dsm + 8192  + i*48 + half*8 + 4) = h1;
        *(uint32_t*)(dsm + 14336 + i*48 + half*8)     = l0;
        *(uint32_t*)(dsm + 14336 + i*48 + half*8 + 4) = l1;
        zr_s[i*2 + half] = v0*v0 + v1*v1 + v2*v2 + v3*v3;
    }
    __syncthreads();
    if (t < 128)
        mh_s[t] = sqrtf(zr_s[2*t] + zr_s[2*t+1]) * sqrtf(__uint_as_float(d_cmax_u[b]));
    __syncthreads();
    float mh1 = mh_s[i1], mh2 = mh_s[i2];

    // persistent A-frags for energy mma (fb hi/lo)
    uint32_t ah[4], al[4];
    {
        uint32_t aaddr = fbh + (uint32_t)(w*16 + (lane & 15))*48 + (lane >> 4)*16;
        ldsm_x4(ah[0], ah[1], ah[2], ah[3], aaddr);
        ldsm_x4(al[0], al[1], al[2], al[3], aaddr + 6144);
    }

    float acc[8][4];
#pragma unroll
    for (int ng = 0; ng < 8; ng++)
#pragma unroll
        for (int q = 0; q < 4; q++) acc[ng][q] = 0.f;
    float z1 = 0.f, z2 = 0.f;

    // prefetch jt=0 staging
    float fcr0, fcr1;
    uint32_t fdr[8];
    {
        int j = t & 63, kp2 = t >> 6;
        fcr0 = d_fc[((size_t)b*8 + 2*kp2 + 0)*HWn + j];
        fcr1 = d_fc[((size_t)b*8 + 2*kp2 + 1)*HWn + j];
#pragma unroll
        for (int q = 0; q < 8; q++) {
            int idx = t + q*256;
            int c = idx >> 5, jp = idx & 31;
            fdr[q] = *(const uint32_t*)&d_fdh[((size_t)b*64 + c)*HWn + jp*2];
        }
    }

    uint32_t fdrow = (uint32_t)(lane & 15)*128 + (uint32_t)(lane >> 4)*16;

    for (int jt = 0; jt < 64; jt++) {
        __syncthreads();   // prior tile's ldsm reads done
        // stage fc hi/lo [j][k] (48B rows)
        {
            int j = t & 63, kp2 = t >> 6;
            uint32_t h = cvt_bf16x2(fcr0, fcr1);
            float r0 = __uint_as_float(h << 16), r1 = __uint_as_float(h & 0xffff0000u);
            uint32_t l = cvt_bf16x2(fcr0 - r0, fcr1 - r1);
            *(uint32_t*)(dsm + 20480 + j*48 + kp2*4) = h;
            *(uint32_t*)(dsm + 23552 + j*48 + kp2*4) = l;
        }
        // stage fd (SWZ [c][j])
#pragma unroll
        for (int q = 0; q < 8; q++) {
            int idx = t + q*256;
            int c = idx >> 5, jp = idx & 31;
            *(uint32_t*)(dsm + SWZ((uint32_t)(c*128 + jp*4))) = fdr[q];
        }
        __syncthreads();
        // energy mma: e[16i][64j] (3-product hi/lo split)
        float e[8][4];
#pragma unroll
        for (int ng = 0; ng < 8; ng++)
#pragma unroll
            for (int q = 0; q < 4; q++) e[ng][q] = 0.f;
#pragma unroll
        for (int jg = 0; jg < 4; jg++) {
            uint32_t baddr = fch + (uint32_t)(jg*16 + (lane & 15))*48 + (lane >> 4)*16;
            uint32_t bh[4], bl[4];
            ldsm_x4(bh[0], bh[1], bh[2], bh[3], baddr);
            ldsm_x4(bl[0], bl[1], bl[2], bl[3], baddr + 3072);
            mma_bf16s(e[2*jg],   ah, bh[0], bh[2]);
            mma_bf16s(e[2*jg],   ah, bl[0], bl[2]);
            mma_bf16s(e[2*jg],   al, bh[0], bh[2]);
            mma_bf16s(e[2*jg+1], ah, bh[1], bh[3]);
            mma_bf16s(e[2*jg+1], ah, bl[1], bl[3]);
            mma_bf16s(e[2*jg+1], al, bh[1], bh[3]);
        }
        // prefetch next tile
        if (jt < 63) {
            int j0n = (jt+1)*64;
            int j = t & 63, kp2 = t >> 6;
            fcr0 = d_fc[((size_t)b*8 + 2*kp2 + 0)*HWn + j0n + j];
            fcr1 = d_fc[((size_t)b*8 + 2*kp2 + 1)*HWn + j0n + j];
#pragma unroll
            for (int q = 0; q < 8; q++) {
                int idx = t + q*256;
                int c = idx >> 5, jp = idx & 31;
                fdr[q] = *(const uint32_t*)&d_fdh[((size_t)b*64 + c)*HWn + j0n + jp*2];
            }
        }
        // exp in fragments -> pack p directly into A-frags of accumulate mma
        uint32_t afr[4][4];
#pragma unroll
        for (int ng = 0; ng < 8; ng++) {
            float q0 = ex2f(e[ng][0] - mh1), q1 = ex2f(e[ng][1] - mh1);
            float q2 = ex2f(e[ng][2] - mh2), q3 = ex2f(e[ng][3] - mh2);
            z1 += q0 + q1;
            z2 += q2 + q3;
            int kp = ng >> 1;
            if ((ng & 1) == 0) {
                afr[kp][0] = cvt_bf16x2(q0, q1);
                afr[kp][1] = cvt_bf16x2(q2, q3);
            } else {
                afr[kp][2] = cvt_bf16x2(q0, q1);
                afr[kp][3] = cvt_bf16x2(q2, q3);
            }
        }
        // accumulate mma: acc[16i][64c] += p * fd
#pragma unroll
        for (int ng2 = 0; ng2 < 4; ng2++) {
#pragma unroll
            for (int kp = 0; kp < 4; kp++) {
                uint32_t off = fdrow + (uint32_t)(ng2*2048 + kp*32);
                uint32_t f4[4];
                ldsm_x4(f4[0], f4[1], f4[2], f4[3], fdbase + SWZ(off));
                mma_bf16s(acc[2*ng2],   afr[kp], f4[0], f4[2]);
                mma_bf16s(acc[2*ng2+1], afr[kp], f4[1], f4[3]);
            }
        }
    }
    // ---- z reduction ----
    zr_s[i1*4 + tc] = z1;
    zr_s[i2*4 + tc] = z2;
    __syncthreads();
    if (t < 128) {
        float4 zz = *(const float4*)&zr_s[t*4];
        z_s[t] = alpha_p[0] / ((zz.x + zz.y) + (zz.z + zz.w));
    }
    __syncthreads();
    // ---- load psi tile / W2 / wp (overwrites mainloop smem) ----
    for (int idx = t; idx < 8192; idx += 256) {
        int c = idx >> 7, p = idx & 127;
        psi_s[c*132 + p] = d_psi[((size_t)b*Cn + c)*HWn + I0 + p];
    }
    for (int idx = t; idx < 4096; idx += 256) W2_s[idx] = d_W2[b*4096 + idx];
    if (t < 64) wp_s[t] = d_wp[t];
    __syncthreads();
    // ---- fragments -> pam_s[c][i] ----
    {
        float zz1 = z_s[i1], zz2 = z_s[i2];
#pragma unroll
        for (int ng = 0; ng < 8; ng++) {
            int c = ng*8 + 2*tc;
            pam_s[c*132 + i1]     = acc[ng][0]*zz1 + psi_s[c*132 + i1];
            pam_s[(c+1)*132 + i1] = acc[ng][1]*zz1 + psi_s[(c+1)*132 + i1];
            pam_s[c*132 + i2]     = acc[ng][2]*zz2 + psi_s[c*132 + i2];
            pam_s[(c+1)*132 + i2] = acc[ng][3]*zz2 + psi_s[(c+1)*132 + i2];
        }
    }
    __syncthreads();
    // ---- fused CAM + gate ----
    {
        int p = t & 127, half = t >> 7;
        int c0 = half*32, d0 = half*32;
        float part1 = 0.f;
#pragma unroll 8
        for (int c = 0; c < 32; c++) {
            int cc = c0 + c;
            part1 += wp_s[cc] * psi_s[cc*132 + p] * pam_s[cc*132 + p];
        }
        ull v[16];
#pragma unroll
        for (int q = 0; q < 16; q++) v[q] = 0ull;
        for (int c = 0; c < 64; c++) {
            float pm = pam_s[c*132 + p];
            ull pm2 = pk2(pm, pm);
            const ull* wr = (const ull*)&W2_s[c*64 + d0];
#pragma unroll
            for (int q = 0; q < 16; q++) v[q] = ffma2(pm2, wr[q], v[q]);
        }
        float part2 = 0.f;
#pragma unroll
        for (int q = 0; q < 16; q++) {
            float v0, v1; upk2(v[q], v0, v1);
            part2 += psi_s[(d0+2*q)*132 + p]*v0 + psi_s[(d0+2*q+1)*132 + p]*v1;
        }
        gred[half*128 + p] = part1 + part2;
    }
    __syncthreads();
    if (t < 128) {
        float gate = d_bp[0] + gred[t] + gred[128 + t];
        z_s[t] = 1.f / (1.f + __expf(-gate));   // da
    }
    __syncthreads();
    // ---- fused final multiply ----
    {
        int p = t & 127, hb = t >> 7;
        float da = z_s[p];
        const float* xp = x + ((size_t)b*256)*HWn + I0 + p;
        float* op = out + ((size_t)b*256)*HWn + I0 + p;
#pragma unroll 8
        for (int c = hb; c < 256; c += 2)
            op[(size_t)c*HWn] = xp[(size_t)c*HWn] * da;
    }
}

// ---------------- launch ----------------
extern "C" void kernel_launch(void* const* d_in, const int* in_sizes, int n_in,
                              void* d_out, int out_size) {
    const float* g = (const float*)d_in[0];
    const float* x = (const float*)d_in[1];

    cudaFuncSetAttribute(k_psi2,  cudaFuncAttributeMaxDynamicSharedMemorySize, 82176);
    cudaFuncSetAttribute(k_small, cudaFuncAttributeMaxDynamicSharedMemorySize, 13456*4);
    cudaFuncSetAttribute(k_pam3,  cudaFuncAttributeMaxDynamicSharedMemorySize, 85760);

    k_prep<<<64, 256>>>((const float*)d_in[2],  (const float*)d_in[3],  (const float*)d_in[4],
                        (const float*)d_in[5],  (const float*)d_in[6],  (const float*)d_in[7],
                        (const float*)d_in[8],  (const float*)d_in[9],  (const float*)d_in[10],
                        (const float*)d_in[11], (const float*)d_in[12], (const float*)d_in[13],
                        (const float*)d_in[14], (const float*)d_in[15], (const float*)d_in[16],
                        (const float*)d_in[17], (const float*)d_in[18], (const float*)d_in[19]);

    k_psi2<<<dim3(32, 8), 256, 82176>>>(g, x);

    k_small<<<dim3(32, 8), 256, 13456*4>>>(
        (const float*)d_in[20], (const float*)d_in[21],
        (const float*)d_in[22], (const float*)d_in[23],
        (const float*)d_in[24], (const float*)d_in[25]);

    k_cam_soft2<<<8, 256>>>((const float*)d_in[27]);

    k_pam3<<<dim3(32, 8), 256, 85760>>>((const float*)d_in[26], x, (float*)d_out);
}

// round 9
// speedup vs baseline: 4.7763x; 1.0498x over previous
#include <cuda_runtime.h>
#include <cuda_bf16.h>
#include <cuda_fp16.h>
#include <math.h>
#include <stdint.h>

typedef unsigned long long ull;

#define Bn 8
#define Cn 64
#define HWn 4096
#define LOG2E 1.4426950408889634f

// ---------------- scratch (device globals; no allocs allowed) ----------------
__device__ __align__(16) float d_psi[Bn*Cn*HWn];     // 8MB
__device__ __align__(16) float d_fb [Bn*8*HWn];      // pre-scaled by log2(e)
__device__ __align__(16) float d_fc [Bn*8*HWn];
__device__ __align__(16) __half d_fdh[Bn*Cn*HWn];    // 4MB fp16 [b][c][j]
__device__ __align__(16) float d_att[Bn*64*64];      // CAM gram (atomic-accumulated)
__device__ __align__(16) float d_W2[Bn*64*64];       // beta*wp[c]*attw[c][d]
__device__ __align__(16) __nv_bfloat16 d_Wh[512*64]; // folded weight hi, [cin][out]
__device__ __align__(16) __nv_bfloat16 d_Wl[512*64]; // folded weight lo
__device__ __align__(16) float d_bias[64];
__device__ __align__(16) float d_wp[64];
__device__ __align__(16) float d_bp[1];

// ---------------- f32x2 helpers ----------------
__device__ __forceinline__ ull pk2(float lo, float hi) {
    ull r; asm("mov.b64 %0, {%1, %2};" : "=l"(r) : "f"(lo), "f"(hi)); return r;
}
__device__ __forceinline__ void upk2(ull v, float& lo, float& hi) {
    asm("mov.b64 {%0, %1}, %2;" : "=f"(lo), "=f"(hi) : "l"(v));
}
__device__ __forceinline__ ull ffma2(ull a, ull b, ull c) {
    ull d; asm("fma.rn.f32x2 %0, %1, %2, %3;" : "=l"(d) : "l"(a), "l"(b), "l"(c)); return d;
}
__device__ __forceinline__ float ex2f(float x) {
    float r; asm("ex2.approx.f32 %0, %1;" : "=f"(r) : "f"(x)); return r;
}

// ---------------- warp MMA helpers ----------------
__device__ __forceinline__ uint32_t smem_u32(const void* p) {
    uint32_t a;
    asm("{ .reg .u64 t; cvta.to.shared.u64 t, %1; cvt.u32.u64 %0, t; }" : "=r"(a) : "l"(p));
    return a;
}
#define SWZ(off) ((off) ^ (((off) >> 3) & 0x70))
__device__ __forceinline__ void ldsm_x4(uint32_t& r0, uint32_t& r1, uint32_t& r2, uint32_t& r3,
                                        uint32_t addr) {
    asm volatile("ldmatrix.sync.aligned.m8n8.x4.shared.b16 {%0,%1,%2,%3}, [%4];"
                 : "=r"(r0), "=r"(r1), "=r"(r2), "=r"(r3) : "r"(addr));
}
__device__ __forceinline__ void ldsm_x4t(uint32_t& r0, uint32_t& r1, uint32_t& r2, uint32_t& r3,
                                         uint32_t addr) {
    asm volatile("ldmatrix.sync.aligned.m8n8.x4.trans.shared.b16 {%0,%1,%2,%3}, [%4];"
                 : "=r"(r0), "=r"(r1), "=r"(r2), "=r"(r3) : "r"(addr));
}
__device__ __forceinline__ void mma_bf16(float* d, const uint32_t* a, const uint32_t* b) {
    asm volatile(
        "mma.sync.aligned.m16n8k16.row.col.f32.bf16.bf16.f32 "
        "{%0,%1,%2,%3}, {%4,%5,%6,%7}, {%8,%9}, {%0,%1,%2,%3};"
        : "+f"(d[0]), "+f"(d[1]), "+f"(d[2]), "+f"(d[3])
        : "r"(a[0]), "r"(a[1]), "r"(a[2]), "r"(a[3]), "r"(b[0]), "r"(b[1]));
}
__device__ __forceinline__ void mma_bf16s(float* d, const uint32_t* a, uint32_t b0, uint32_t b1) {
    asm volatile(
        "mma.sync.aligned.m16n8k16.row.col.f32.bf16.bf16.f32 "
        "{%0,%1,%2,%3}, {%4,%5,%6,%7}, {%8,%9}, {%0,%1,%2,%3};"
        : "+f"(d[0]), "+f"(d[1]), "+f"(d[2]), "+f"(d[3])
        : "r"(a[0]), "r"(a[1]), "r"(a[2]), "r"(a[3]), "r"(b0), "r"(b1));
}
__device__ __forceinline__ void mma_f16s(float* d, const uint32_t* a, uint32_t b0, uint32_t b1) {
    asm volatile(
        "mma.sync.aligned.m16n8k16.row.col.f32.f16.f16.f32 "
        "{%0,%1,%2,%3}, {%4,%5,%6,%7}, {%8,%9}, {%0,%1,%2,%3};"
        : "+f"(d[0]), "+f"(d[1]), "+f"(d[2]), "+f"(d[3])
        : "r"(a[0]), "r"(a[1]), "r"(a[2]), "r"(a[3]), "r"(b0), "r"(b1));
}
__device__ __forceinline__ uint32_t cvt_bf16x2(float a, float b) {
    uint32_t r;
    asm("cvt.rn.satfinite.bf16x2.f32 %0, %1, %2;" : "=r"(r) : "f"(b), "f"(a));
    return r;
}
__device__ __forceinline__ uint32_t cvt_f16x2(float a, float b) {
    // lower half = a, upper = b
    uint32_t r;
    asm("cvt.rn.f16x2.f32 %0, %1, %2;" : "=r"(r) : "f"(b), "f"(a));
    return r;
}
__device__ __forceinline__ uint32_t ex2h2(uint32_t a) {
    uint32_t r;
    asm("ex2.approx.f16x2 %0, %1;" : "=r"(r) : "r"(a));
    return r;
}
__device__ __forceinline__ uint32_t hadd2u(uint32_t a, uint32_t b) {
    uint32_t r;
    asm("add.rn.f16x2 %0, %1, %2;" : "=r"(r) : "r"(a), "r"(b));
    return r;
}

// ---------------- prep: fold BN into conv weights, split hi/lo bf16 ----------------
__global__ void k_prep(const float* Wg_w, const float* Wg_b, const float* gg, const float* gb,
                       const float* gm, const float* gv,
                       const float* Wx_w, const float* Wx_b, const float* xg, const float* xb,
                       const float* xm, const float* xv,
                       const float* psi_w, const float* psi_b, const float* pg, const float* pbt,
                       const float* pm, const float* pv) {
    int o = blockIdx.x, t = threadIdx.x;
    float invg = gg[o] * rsqrtf(gv[o] + 1e-5f);
    float invx = xg[o] * rsqrtf(xv[o] + 1e-5f);
    float vg = Wg_w[o*256 + t] * invg;
    float vx = Wx_w[o*256 + t] * invx;
    __nv_bfloat16 hg = __float2bfloat16(vg);
    __nv_bfloat16 hx = __float2bfloat16(vx);
    d_Wh[t*64 + o]       = hg;
    d_Wl[t*64 + o]       = __float2bfloat16(vg - __bfloat162float(hg));
    d_Wh[(256+t)*64 + o] = hx;
    d_Wl[(256+t)*64 + o] = __float2bfloat16(vx - __bfloat162float(hx));
    // zero CAM gram accumulator (32768 floats over 16384 threads)
    int gi = o*256 + t;
    d_att[gi*2]     = 0.f;
    d_att[gi*2 + 1] = 0.f;
    if (t == 0) {
        d_bias[o] = (Wg_b[o] - gm[o]) * invg + gb[o]
                  + (Wx_b[o] - xm[o]) * invx + xb[o];
    }
    if (o == 0 && t < 64) {
        float invp = pg[0] * rsqrtf(pv[0] + 1e-5f);
        d_wp[t] = psi_w[t] * invp;
        if (t == 0) d_bp[0] = (psi_b[0] - pm[0]) * invp + pbt[0];
    }
}

// ---------------- psi via bf16-split HMMA ----------------
__global__ void __launch_bounds__(256) k_psi2(const float* __restrict__ g, const float* __restrict__ x) {
    extern __shared__ __align__(1024) char ps[];
    uint32_t base = smem_u32(ps);
    uint32_t ahi = base, whi = base + 32768;
    float* f32s   = (float*)(ps + 49152);
    float* bias_s = (float*)(ps + 81920);
    float* psi_t  = (float*)ps;

    int b = blockIdx.y, p0 = blockIdx.x*128, t = threadIdx.x;
    int w = t >> 5, lane = t & 31;
    if (t < 64) bias_s[t] = d_bias[t];

    float dfr[8][4];
#pragma unroll
    for (int nf = 0; nf < 8; nf++)
#pragma unroll
        for (int q = 0; q < 4; q++) dfr[nf][q] = 0.f;

    int r7 = lane & 7;
    int hsel = lane >> 4;
    uint32_t a_row = ahi + (uint32_t)(w*16 + (lane & 15))*128;
    uint32_t b_row = whi + (uint32_t)((((lane >> 3) & 1)*8 + r7))*128;

    for (int cb = 0; cb < 8; cb++) {
        __syncthreads();
        {
            const float* src = (cb < 4) ? g + ((size_t)b*256 + cb*64)*HWn
                                        : x + ((size_t)b*256 + (cb-4)*64)*HWn;
#pragma unroll
            for (int i = 0; i < 8; i++) {
                int idx = t + i*256;
                int c = idx >> 5, p4 = idx & 31;
                float4 v = *(const float4*)&src[(size_t)c*HWn + p0 + p4*4];
                *(float4*)&f32s[c*128 + p4*4] = v;
            }
        }
        {
#pragma unroll
            for (int q = 0; q < 2; q++) {
                int qi = t + q*256;
                int row = qi >> 3, qq = qi & 7;
                uint32_t so = SWZ((uint32_t)(row*128 + qq*16));
                *(uint4*)(ps + 32768 + so) =
                    *(const uint4*)((const char*)d_Wh + (size_t)(cb*64+row)*128 + qq*16);
                *(uint4*)(ps + 40960 + so) =
                    *(const uint4*)((const char*)d_Wl + (size_t)(cb*64+row)*128 + qq*16);
            }
        }
        __syncthreads();
        {
            int p = t & 127, half = t >> 7;
#pragma unroll
            for (int oct = 0; oct < 4; oct++) {
                int c0 = half*32 + oct*8;
                float v[8];
#pragma unroll
                for (int j = 0; j < 8; j++) v[j] = f32s[(c0+j)*128 + p];
                uint32_t uh[4], ul[4];
#pragma unroll
                for (int j = 0; j < 4; j++) {
                    uint32_t h = cvt_bf16x2(v[2*j], v[2*j+1]);
                    float h0 = __uint_as_float(h << 16);
                    float h1 = __uint_as_float(h & 0xffff0000u);
                    uh[j] = h;
                    ul[j] = cvt_bf16x2(v[2*j] - h0, v[2*j+1] - h1);
                }
                uint32_t so = SWZ((uint32_t)(p*128 + c0*2));
                *(uint4*)(ps + so)         = make_uint4(uh[0], uh[1], uh[2], uh[3]);
                *(uint4*)(ps + 16384 + so) = make_uint4(ul[0], ul[1], ul[2], ul[3]);
            }
        }
        __syncthreads();
        uint32_t afh[4][4], afl[4][4];
#pragma unroll
        for (int ks = 0; ks < 4; ks++) {
            uint32_t aq = (uint32_t)(((2*ks + hsel) ^ r7) * 16);
            ldsm_x4(afh[ks][0], afh[ks][1], afh[ks][2], afh[ks][3], a_row + aq);
            ldsm_x4(afl[ks][0], afl[ks][1], afl[ks][2], afl[ks][3], a_row + 16384 + aq);
        }
#pragma unroll
        for (int ks = 0; ks < 4; ks++) {
#pragma unroll
            for (int nn = 0; nn < 4; nn++) {
                uint32_t bq = (uint32_t)(((2*nn + hsel) ^ r7) * 16);
                uint32_t baddr = b_row + ks*2048 + bq;
                uint32_t bh[4], bl[4];
                ldsm_x4t(bh[0], bh[1], bh[2], bh[3], baddr);
                ldsm_x4t(bl[0], bl[1], bl[2], bl[3], baddr + 8192);
                mma_bf16(dfr[2*nn],   afh[ks], bh);
                mma_bf16(dfr[2*nn],   afh[ks], bl);
                mma_bf16(dfr[2*nn],   afl[ks], bh);
                mma_bf16(dfr[2*nn+1], afh[ks], bh + 2);
                mma_bf16(dfr[2*nn+1], afh[ks], bl + 2);
                mma_bf16(dfr[2*nn+1], afl[ks], bh + 2);
            }
        }
    }
    __syncthreads();
    {
        int gr = lane >> 2, tc = lane & 3;
        int i1 = w*16 + gr, i2 = i1 + 8;
#pragma unroll
        for (int nf = 0; nf < 8; nf++) {
            int c0 = nf*8 + 2*tc;
            float b0 = bias_s[c0], b1 = bias_s[c0+1];
            psi_t[c0*132 + i1]     = fmaxf(dfr[nf][0] + b0, 0.f);
            psi_t[(c0+1)*132 + i1] = fmaxf(dfr[nf][1] + b1, 0.f);
            psi_t[c0*132 + i2]     = fmaxf(dfr[nf][2] + b0, 0.f);
            psi_t[(c0+1)*132 + i2] = fmaxf(dfr[nf][3] + b1, 0.f);
        }
    }
    __syncthreads();
    for (int idx = t; idx < 8192; idx += 256) {
        int c = idx >> 7, p = idx & 127;
        d_psi[((size_t)b*Cn + c)*HWn + p0 + p] = psi_t[c*132 + p];
    }
}

// ---------------- fb/fc/fd convs + CAM gram (atomic) ----------------
__global__ void __launch_bounds__(256) k_small(const float* __restrict__ pb_w, const float* __restrict__ pb_b,
                                               const float* __restrict__ pc_w, const float* __restrict__ pc_b,
                                               const float* __restrict__ pd_w, const float* __restrict__ pd_b) {
    extern __shared__ float smm[];
    float* A      = smm;              // psi tile [64][129]
    float* w_s    = smm + 8256;       // [c][o] 64*80
    float* bias_s = w_s + 5120;       // 80
    int b = blockIdx.y, p0 = blockIdx.x*128, t = threadIdx.x;
    int pos = t & 127, half = t >> 7;
    for (int idx = t; idx < 8192; idx += 256) {
        int c = idx >> 7, p = idx & 127;
        A[c*129 + p] = d_psi[((size_t)b*Cn + c)*HWn + p0 + p];
    }
    for (int idx = t; idx < 5120; idx += 256) {
        int c = idx / 80, o = idx % 80;
        float w;
        if (o < 8)       w = pb_w[o*64 + c];
        else if (o < 16) w = pc_w[(o-8)*64 + c];
        else             w = pd_w[(o-16)*64 + c];
        w_s[idx] = w;
    }
    if (t < 80) bias_s[t] = (t < 8) ? pb_b[t] : (t < 16 ? pc_b[t-8] : pd_b[t-16]);
    __syncthreads();
    int o0 = half*40;
    ull acc[20];
#pragma unroll
    for (int q = 0; q < 20; q++) acc[q] = pk2(bias_s[o0 + 2*q], bias_s[o0 + 2*q + 1]);
    for (int c = 0; c < 64; c++) {
        float v = A[c*129 + pos];
        ull v2 = pk2(v, v);
        const ull* wr = (const ull*)&w_s[c*80 + o0];
#pragma unroll
        for (int q = 0; q < 20; q++) acc[q] = ffma2(v2, wr[q], acc[q]);
    }
#pragma unroll
    for (int q = 0; q < 20; q++) {
        float v0, v1; upk2(acc[q], v0, v1);
        int o = o0 + 2*q;
#pragma unroll
        for (int s = 0; s < 2; s++) {
            float v = s ? v1 : v0;
            int oo = o + s;
            if (oo < 8)       d_fb[((size_t)b*8 + oo)*HWn + p0 + pos] = v * LOG2E;
            else if (oo < 16) d_fc[((size_t)b*8 + (oo-8))*HWn + p0 + pos] = v;
            else              d_fdh[((size_t)b*64 + (oo-16))*HWn + p0 + pos] = __float2half(v);
        }
    }
    // CAM gram partial over this 128-pos segment, accumulated atomically
    {
        int cjg = t & 15, cig = t >> 4;
        float ga[4][4];
#pragma unroll
        for (int r = 0; r < 4; r++)
#pragma unroll
            for (int q = 0; q < 4; q++) ga[r][q] = 0.f;
        for (int p = 0; p < 128; p++) {
            float a0 = A[(cig*4+0)*129 + p];
            float a1 = A[(cig*4+1)*129 + p];
            float a2 = A[(cig*4+2)*129 + p];
            float a3 = A[(cig*4+3)*129 + p];
            float b0 = A[(cjg*4+0)*129 + p];
            float b1 = A[(cjg*4+1)*129 + p];
            float b2 = A[(cjg*4+2)*129 + p];
            float b3 = A[(cjg*4+3)*129 + p];
            ga[0][0]+=a0*b0; ga[0][1]+=a0*b1; ga[0][2]+=a0*b2; ga[0][3]+=a0*b3;
            ga[1][0]+=a1*b0; ga[1][1]+=a1*b1; ga[1][2]+=a1*b2; ga[1][3]+=a1*b3;
            ga[2][0]+=a2*b0; ga[2][1]+=a2*b1; ga[2][2]+=a2*b2; ga[2][3]+=a2*b3;
            ga[3][0]+=a3*b0; ga[3][1]+=a3*b1; ga[3][2]+=a3*b2; ga[3][3]+=a3*b3;
        }
#pragma unroll
        for (int r = 0; r < 4; r++)
#pragma unroll
            for (int q = 0; q < 4; q++)
                atomicAdd(&d_att[(b*64 + cig*4 + r)*64 + cjg*4 + q], ga[r][q]);
    }
}

// ---------------- CAM softmax -> W2 ----------------
__global__ void __launch_bounds__(256) k_cam_soft2(const float* __restrict__ beta_p) {
    __shared__ float att[64*65];
    int b = blockIdx.x, t = threadIdx.x;
    for (int idx = t; idx < 4096; idx += 256)
        att[(idx >> 6)*65 + (idx & 63)] = d_att[b*4096 + idx];
    __syncthreads();
    if (t < 64) {
        float v[64];
#pragma unroll
        for (int d = 0; d < 64; d++) v[d] = att[t*65 + d];
        float mx = -1e30f, mn = 1e30f;
#pragma unroll
        for (int d = 0; d < 64; d++) { mx = fmaxf(mx, v[d]); mn = fminf(mn, v[d]); }
        float m2 = mx - mn;
        float ssum = 0.f;
#pragma unroll
        for (int d = 0; d < 64; d++) { float e = __expf((mx - v[d]) - m2); v[d] = e; ssum += e; }
        float scale = beta_p[0] * d_wp[t] / ssum;
#pragma unroll
        for (int d = 0; d < 64; d++) d_W2[b*4096 + t*64 + d] = v[d] * scale;
    }
}

// ---------------- PAM + CAM-gate + final multiply ----------------
// e via bf16-split HMMA; TRUE online row-max (quad shfl) with register-fragment
// rescale; p = ex2.f16x2 into fp16 A-frags; P*fd on fp16 HMMA.
__global__ void __launch_bounds__(256, 2) k_pam3(const float* __restrict__ alpha_p,
                                                 const float* __restrict__ x,
                                                 float* __restrict__ out) {
    extern __shared__ __align__(1024) char dsm[];
    float* zr_s = (float*)(dsm + 27136);
    // epilogue union
    float* psi_s = (float*)dsm;               // 64*132 f
    float* pam_s = (float*)(dsm + 33792);     // 64*132 f
    float* W2_s  = (float*)(dsm + 67584);     // 4096 f
    float* wp_s  = (float*)(dsm + 83968);     // 64 f
    float* gred  = (float*)(dsm + 84224);     // 256 f
    float* z_s   = (float*)(dsm + 85248);     // 128 f

    uint32_t sbase  = smem_u32(dsm);
    uint32_t fdbase = sbase;
    uint32_t fbh = sbase + 8192;
    uint32_t fch = sbase + 20480;

    int b = blockIdx.y, I0 = blockIdx.x*128, t = threadIdx.x;
    int w = t >> 5, lane = t & 31;
    int gr = lane >> 2, tc = lane & 3;
    int i1 = w*16 + gr, i2 = i1 + 8;

    // zero k8-15 pad of fb/fc hi+lo rows
    for (int idx = t; idx < 1536; idx += 256) {
        char* p;
        if (idx < 512)        p = dsm + 8192  + (idx>>2)*48 + 16 + (idx&3)*4;
        else if (idx < 1024)  p = dsm + 14336 + ((idx-512)>>2)*48 + 16 + (idx&3)*4;
        else if (idx < 1280)  p = dsm + 20480 + ((idx-1024)>>2)*48 + 16 + (idx&3)*4;
        else                  p = dsm + 23552 + ((idx-1280)>>2)*48 + 16 + (idx&3)*4;
        *(uint32_t*)p = 0u;
    }
    // stage fb bf16 hi/lo [i][k] (48B rows)
    {
        int i = t & 127, half = t >> 7;
        float v0 = d_fb[((size_t)b*8 + half*4 + 0)*HWn + I0 + i];
        float v1 = d_fb[((size_t)b*8 + half*4 + 1)*HWn + I0 + i];
        float v2 = d_fb[((size_t)b*8 + half*4 + 2)*HWn + I0 + i];
        float v3 = d_fb[((size_t)b*8 + half*4 + 3)*HWn + I0 + i];
        uint32_t h0 = cvt_bf16x2(v0, v1), h1 = cvt_bf16x2(v2, v3);
        float r0 = __uint_as_float(h0 << 16), r1 = __uint_as_float(h0 & 0xffff0000u);
        float r2 = __uint_as_float(h1 << 16), r3 = __uint_as_float(h1 & 0xffff0000u);
        uint32_t l0 = cvt_bf16x2(v0 - r0, v1 - r1), l1 = cvt_bf16x2(v2 - r2, v3 - r3);
        *(uint32_t*)(dsm + 8192  + i*48 + half*8)     = h0;
        *(uint32_t*)(dsm + 8192  + i*48 + half*8 + 4) = h1;
        *(uint32_t*)(dsm + 14336 + i*48 + half*8)     = l0;
        *(uint32_t*)(dsm + 14336 + i*48 + half*8 + 4) = l1;
    }
    __syncthreads();

    uint32_t ah[4], al[4];
    {
        uint32_t aaddr = fbh + (uint32_t)(w*16 + (lane & 15))*48 + (lane >> 4)*16;
        ldsm_x4(ah[0], ah[1], ah[2], ah[3], aaddr);
        ldsm_x4(al[0], al[1], al[2], al[3], aaddr + 6144);
    }

    float acc[8][4];
#pragma unroll
    for (int ng = 0; ng < 8; ng++)
#pragma unroll
        for (int q = 0; q < 4; q++) acc[ng][q] = 0.f;
    float z1 = 0.f, z2 = 0.f;
    float m1 = -1e30f, m2 = -1e30f;   // running row maxes (log2 domain)

    float fcr0, fcr1;
    uint32_t fdr[8];
    {
        int j = t & 63, kp2 = t >> 6;
        fcr0 = d_fc[((size_t)b*8 + 2*kp2 + 0)*HWn + j];
        fcr1 = d_fc[((size_t)b*8 + 2*kp2 + 1)*HWn + j];
#pragma unroll
        for (int q = 0; q < 8; q++) {
            int idx = t + q*256;
            int c = idx >> 5, jp = idx & 31;
            fdr[q] = *(const uint32_t*)&d_fdh[((size_t)b*64 + c)*HWn + jp*2];
        }
    }

    uint32_t fdrow = (uint32_t)(lane & 15)*128 + (uint32_t)(lane >> 4)*16;

    for (int jt = 0; jt < 64; jt++) {
        __syncthreads();
        {
            int j = t & 63, kp2 = t >> 6;
            uint32_t h = cvt_bf16x2(fcr0, fcr1);
            float r0 = __uint_as_float(h << 16), r1 = __uint_as_float(h & 0xffff0000u);
            uint32_t l = cvt_bf16x2(fcr0 - r0, fcr1 - r1);
            *(uint32_t*)(dsm + 20480 + j*48 + kp2*4) = h;
            *(uint32_t*)(dsm + 23552 + j*48 + kp2*4) = l;
        }
#pragma unroll
        for (int q = 0; q < 8; q++) {
            int idx = t + q*256;
            int c = idx >> 5, jp = idx & 31;
            *(uint32_t*)(dsm + SWZ((uint32_t)(c*128 + jp*4))) = fdr[q];
        }
        __syncthreads();
        // energy mma
        float e[8][4];
#pragma unroll
        for (int ng = 0; ng < 8; ng++)
#pragma unroll
            for (int q = 0; q < 4; q++) e[ng][q] = 0.f;
#pragma unroll
        for (int jg = 0; jg < 4; jg++) {
            uint32_t baddr = fch + (uint32_t)(jg*16 + (lane & 15))*48 + (lane >> 4)*16;
            uint32_t bh[4], bl[4];
            ldsm_x4(bh[0], bh[1], bh[2], bh[3], baddr);
            ldsm_x4(bl[0], bl[1], bl[2], bl[3], baddr + 3072);
            mma_bf16s(e[2*jg],   ah, bh[0], bh[2]);
            mma_bf16s(e[2*jg],   ah, bl[0], bl[2]);
            mma_bf16s(e[2*jg],   al, bh[0], bh[2]);
            mma_bf16s(e[2*jg+1], ah, bh[1], bh[3]);
            mma_bf16s(e[2*jg+1], ah, bl[1], bl[3]);
            mma_bf16s(e[2*jg+1], al, bh[1], bh[3]);
        }
        if (jt < 63) {
            int j0n = (jt+1)*64;
            int j = t & 63, kp2 = t >> 6;
            fcr0 = d_fc[((size_t)b*8 + 2*kp2 + 0)*HWn + j0n + j];
            fcr1 = d_fc[((size_t)b*8 + 2*kp2 + 1)*HWn + j0n + j];
#pragma unroll
            for (int q = 0; q < 8; q++) {
                int idx = t + q*256;
                int c = idx >> 5, jp = idx & 31;
                fdr[q] = *(const uint32_t*)&d_fdh[((size_t)b*64 + c)*HWn + j0n + jp*2];
            }
        }
        // ---- online row max: thread-local, then quad (tc 0..3) via shfl ----
        float tm1 = -1e30f, tm2 = -1e30f;
#pragma unroll
        for (int ng = 0; ng < 8; ng++) {
            tm1 = fmaxf(tm1, fmaxf(e[ng][0], e[ng][1]));
            tm2 = fmaxf(tm2, fmaxf(e[ng][2], e[ng][3]));
        }
        tm1 = fmaxf(tm1, __shfl_xor_sync(0xffffffffu, tm1, 1));
        tm1 = fmaxf(tm1, __shfl_xor_sync(0xffffffffu, tm1, 2));
        tm2 = fmaxf(tm2, __shfl_xor_sync(0xffffffffu, tm2, 1));
        tm2 = fmaxf(tm2, __shfl_xor_sync(0xffffffffu, tm2, 2));
        float mn1 = fmaxf(m1, tm1), mn2 = fmaxf(m2, tm2);
        float sc1 = ex2f(m1 - mn1), sc2 = ex2f(m2 - mn2);
        m1 = mn1; m2 = mn2;
        z1 *= sc1; z2 *= sc2;
#pragma unroll
        for (int ng = 0; ng < 8; ng++) {
            acc[ng][0] *= sc1; acc[ng][1] *= sc1;
            acc[ng][2] *= sc2; acc[ng][3] *= sc2;
        }
        // exp via ex2.f16x2 -> p fragments packed directly
        uint32_t afr[4][4];
#pragma unroll
        for (int ng = 0; ng < 8; ng++) {
            uint32_t a01 = cvt_f16x2(e[ng][0] - mn1, e[ng][1] - mn1);
            uint32_t a23 = cvt_f16x2(e[ng][2] - mn2, e[ng][3] - mn2);
            uint32_t p01 = ex2h2(a01);
            uint32_t p23 = ex2h2(a23);
            int kp = ng >> 1;
            if ((ng & 1) == 0) { afr[kp][0] = p01; afr[kp][1] = p23; }
            else               { afr[kp][2] = p01; afr[kp][3] = p23; }
        }
        // z partial via HADD2 tree (consistent with quantized p)
        {
            uint32_t s1 = hadd2u(hadd2u(hadd2u(afr[0][0], afr[0][2]), hadd2u(afr[1][0], afr[1][2])),
                                 hadd2u(hadd2u(afr[2][0], afr[2][2]), hadd2u(afr[3][0], afr[3][2])));
            uint32_t s2 = hadd2u(hadd2u(hadd2u(afr[0][1], afr[0][3]), hadd2u(afr[1][1], afr[1][3])),
                                 hadd2u(hadd2u(afr[2][1], afr[2][3]), hadd2u(afr[3][1], afr[3][3])));
            float2 f1 = __half22float2(*(__half2*)&s1);
            float2 f2 = __half22float2(*(__half2*)&s2);
            z1 += f1.x + f1.y;
            z2 += f2.x + f2.y;
        }
        // accumulate mma (fp16): acc[16i][64c] += p * fd
#pragma unroll
        for (int ng2 = 0; ng2 < 4; ng2++) {
#pragma unroll
            for (int kp = 0; kp < 4; kp++) {
                uint32_t off = fdrow + (uint32_t)(ng2*2048 + kp*32);
                uint32_t f4[4];
                ldsm_x4(f4[0], f4[1], f4[2], f4[3], fdbase + SWZ(off));
                mma_f16s(acc[2*ng2],   afr[kp], f4[0], f4[2]);
                mma_f16s(acc[2*ng2+1], afr[kp], f4[1], f4[3]);
            }
        }
    }
    // ---- z reduction across the quad ----
    z1 += __shfl_xor_sync(0xffffffffu, z1, 1);
    z1 += __shfl_xor_sync(0xffffffffu, z1, 2);
    z2 += __shfl_xor_sync(0xffffffffu, z2, 1);
    z2 += __shfl_xor_sync(0xffffffffu, z2, 2);
    __syncthreads();   // mainloop smem reads done before epilogue overwrites
    if (tc == 0) {
        zr_s[i1] = alpha_p[0] / z1;
        zr_s[i2] = alpha_p[0] / z2;
    }
    __syncthreads();
    if (t < 128) z_s[t] = zr_s[t];
    __syncthreads();
    // ---- load psi tile / W2 / wp ----
    for (int idx = t; idx < 8192; idx += 256) {
        int c = idx >> 7, p = idx & 127;
        psi_s[c*132 + p] = d_psi[((size_t)b*Cn + c)*HWn + I0 + p];
    }
    for (int idx = t; idx < 4096; idx += 256) W2_s[idx] = d_W2[b*4096 + idx];
    if (t < 64) wp_s[t] = d_wp[t];
    __syncthreads();
    // ---- fragments -> pam_s[c][i] ----
    {
        float zz1 = z_s[i1], zz2 = z_s[i2];
#pragma unroll
        for (int ng = 0; ng < 8; ng++) {
            int c = ng*8 + 2*tc;
            pam_s[c*132 + i1]     = acc[ng][0]*zz1 + psi_s[c*132 + i1];
            pam_s[(c+1)*132 + i1] = acc[ng][1]*zz1 + psi_s[(c+1)*132 + i1];
            pam_s[c*132 + i2]     = acc[ng][2]*zz2 + psi_s[c*132 + i2];
            pam_s[(c+1)*132 + i2] = acc[ng][3]*zz2 + psi_s[(c+1)*132 + i2];
        }
    }
    __syncthreads();
    // ---- fused CAM + gate ----
    {
        int p = t & 127, half = t >> 7;
        int c0 = half*32, d0 = half*32;
        float part1 = 0.f;
#pragma unroll 8
        for (int c = 0; c < 32; c++) {
            int cc = c0 + c;
            part1 += wp_s[cc] * psi_s[cc*132 + p] * pam_s[cc*132 + p];
        }
        ull v[16];
#pragma unroll
        for (int q = 0; q < 16; q++) v[q] = 0ull;
        for (int c = 0; c < 64; c++) {
            float pm = pam_s[c*132 + p];
            ull pm2 = pk2(pm, pm);
            const ull* wr = (const ull*)&W2_s[c*64 + d0];
#pragma unroll
            for (int q = 0; q < 16; q++) v[q] = ffma2(pm2, wr[q], v[q]);
        }
        float part2 = 0.f;
#pragma unroll
        for (int q = 0; q < 16; q++) {
            float v0, v1; upk2(v[q], v0, v1);
            part2 += psi_s[(d0+2*q)*132 + p]*v0 + psi_s[(d0+2*q+1)*132 + p]*v1;
        }
        gred[half*128 + p] = part1 + part2;
    }
    __syncthreads();
    if (t < 128) {
        float gate = d_bp[0] + gred[t] + gred[128 + t];
        z_s[t] = 1.f / (1.f + __expf(-gate));   // da
    }
    __syncthreads();
    // ---- fused final multiply ----
    {
        int p = t & 127, hb = t >> 7;
        float da = z_s[p];
        const float* xp = x + ((size_t)b*256)*HWn + I0 + p;
        float* op = out + ((size_t)b*256)*HWn + I0 + p;
#pragma unroll 8
        for (int c = hb; c < 256; c += 2)
            op[(size_t)c*HWn] = xp[(size_t)c*HWn] * da;
    }
}

// ---------------- launch ----------------
extern "C" void kernel_launch(void* const* d_in, const int* in_sizes, int n_in,
                              void* d_out, int out_size) {
    const float* g = (const float*)d_in[0];
    const float* x = (const float*)d_in[1];

    cudaFuncSetAttribute(k_psi2,  cudaFuncAttributeMaxDynamicSharedMemorySize, 82176);
    cudaFuncSetAttribute(k_small, cudaFuncAttributeMaxDynamicSharedMemorySize, 13456*4);
    cudaFuncSetAttribute(k_pam3,  cudaFuncAttributeMaxDynamicSharedMemorySize, 85760);

    k_prep<<<64, 256>>>((const float*)d_in[2],  (const float*)d_in[3],  (const float*)d_in[4],
                        (const float*)d_in[5],  (const float*)d_in[6],  (const float*)d_in[7],
                        (const float*)d_in[8],  (const float*)d_in[9],  (const float*)d_in[10],
                        (const float*)d_in[11], (const float*)d_in[12], (const float*)d_in[13],
                        (const float*)d_in[14], (const float*)d_in[15], (const float*)d_in[16],
                        (const float*)d_in[17], (const float*)d_in[18], (const float*)d_in[19]);

    k_psi2<<<dim3(32, 8), 256, 82176>>>(g, x);

    k_small<<<dim3(32, 8), 256, 13456*4>>>(
        (const float*)d_in[20], (const float*)d_in[21],
        (const float*)d_in[22], (const float*)d_in[23],
        (const float*)d_in[24], (const float*)d_in[25]);

    k_cam_soft2<<<8, 256>>>((const float*)d_in[27]);

    k_pam3<<<dim3(32, 8), 256, 85760>>>((const float*)d_in[26], x, (float*)d_out);
}

// round 10
// speedup vs baseline: 5.0395x; 1.0551x over previous
#include <cuda_runtime.h>
#include <cuda_bf16.h>
#include <cuda_fp16.h>
#include <math.h>
#include <stdint.h>

typedef unsigned long long ull;

#define Bn 8
#define Cn 64
#define HWn 4096
#define LOG2E 1.4426950408889634f

// ---------------- scratch (device globals; no allocs allowed) ----------------
__device__ __align__(16) float d_psi[Bn*Cn*HWn];     // 8MB
__device__ __align__(16) float d_fb [Bn*8*HWn];      // pre-scaled by log2(e)
__device__ __align__(16) float d_fc [Bn*8*HWn];
__device__ __align__(16) __half d_fdh[Bn*Cn*HWn];    // 4MB fp16 [b][c][j]
__device__ __align__(16) float d_att[Bn*64*64];      // CAM gram (atomic-accumulated)
__device__ __align__(16) __nv_bfloat16 d_Wh[512*64]; // folded weight hi, [cin][out]
__device__ __align__(16) __nv_bfloat16 d_Wl[512*64]; // folded weight lo
__device__ __align__(16) float d_bias[64];
__device__ __align__(16) float d_wp[64];
__device__ __align__(16) float d_bp[1];

// ---------------- f32x2 helpers ----------------
__device__ __forceinline__ ull pk2(float lo, float hi) {
    ull r; asm("mov.b64 %0, {%1, %2};" : "=l"(r) : "f"(lo), "f"(hi)); return r;
}
__device__ __forceinline__ void upk2(ull v, float& lo, float& hi) {
    asm("mov.b64 {%0, %1}, %2;" : "=f"(lo), "=f"(hi) : "l"(v));
}
__device__ __forceinline__ ull ffma2(ull a, ull b, ull c) {
    ull d; asm("fma.rn.f32x2 %0, %1, %2, %3;" : "=l"(d) : "l"(a), "l"(b), "l"(c)); return d;
}
__device__ __forceinline__ float ex2f(float x) {
    float r; asm("ex2.approx.f32 %0, %1;" : "=f"(r) : "f"(x)); return r;
}

// ---------------- warp MMA helpers ----------------
__device__ __forceinline__ uint32_t smem_u32(const void* p) {
    uint32_t a;
    asm("{ .reg .u64 t; cvta.to.shared.u64 t, %1; cvt.u32.u64 %0, t; }" : "=r"(a) : "l"(p));
    return a;
}
#define SWZ(off) ((off) ^ (((off) >> 3) & 0x70))
__device__ __forceinline__ void ldsm_x4(uint32_t& r0, uint32_t& r1, uint32_t& r2, uint32_t& r3,
                                        uint32_t addr) {
    asm volatile("ldmatrix.sync.aligned.m8n8.x4.shared.b16 {%0,%1,%2,%3}, [%4];"
                 : "=r"(r0), "=r"(r1), "=r"(r2), "=r"(r3) : "r"(addr));
}
__device__ __forceinline__ void ldsm_x4t(uint32_t& r0, uint32_t& r1, uint32_t& r2, uint32_t& r3,
                                         uint32_t addr) {
    asm volatile("ldmatrix.sync.aligned.m8n8.x4.trans.shared.b16 {%0,%1,%2,%3}, [%4];"
                 : "=r"(r0), "=r"(r1), "=r"(r2), "=r"(r3) : "r"(addr));
}
__device__ __forceinline__ void mma_bf16(float* d, const uint32_t* a, const uint32_t* b) {
    asm volatile(
        "mma.sync.aligned.m16n8k16.row.col.f32.bf16.bf16.f32 "
        "{%0,%1,%2,%3}, {%4,%5,%6,%7}, {%8,%9}, {%0,%1,%2,%3};"
        : "+f"(d[0]), "+f"(d[1]), "+f"(d[2]), "+f"(d[3])
        : "r"(a[0]), "r"(a[1]), "r"(a[2]), "r"(a[3]), "r"(b[0]), "r"(b[1]));
}
__device__ __forceinline__ void mma_bf16s(float* d, const uint32_t* a, uint32_t b0, uint32_t b1) {
    asm volatile(
        "mma.sync.aligned.m16n8k16.row.col.f32.bf16.bf16.f32 "
        "{%0,%1,%2,%3}, {%4,%5,%6,%7}, {%8,%9}, {%0,%1,%2,%3};"
        : "+f"(d[0]), "+f"(d[1]), "+f"(d[2]), "+f"(d[3])
        : "r"(a[0]), "r"(a[1]), "r"(a[2]), "r"(a[3]), "r"(b0), "r"(b1));
}
__device__ __forceinline__ void mma_f16s(float* d, const uint32_t* a, uint32_t b0, uint32_t b1) {
    asm volatile(
        "mma.sync.aligned.m16n8k16.row.col.f32.f16.f16.f32 "
        "{%0,%1,%2,%3}, {%4,%5,%6,%7}, {%8,%9}, {%0,%1,%2,%3};"
        : "+f"(d[0]), "+f"(d[1]), "+f"(d[2]), "+f"(d[3])
        : "r"(a[0]), "r"(a[1]), "r"(a[2]), "r"(a[3]), "r"(b0), "r"(b1));
}
__device__ __forceinline__ uint32_t cvt_bf16x2(float a, float b) {
    uint32_t r;
    asm("cvt.rn.satfinite.bf16x2.f32 %0, %1, %2;" : "=r"(r) : "f"(b), "f"(a));
    return r;
}
__device__ __forceinline__ uint32_t cvt_f16x2(float a, float b) {
    uint32_t r;
    asm("cvt.rn.f16x2.f32 %0, %1, %2;" : "=r"(r) : "f"(b), "f"(a));
    return r;
}
__device__ __forceinline__ uint32_t ex2h2(uint32_t a) {
    uint32_t r;
    asm("ex2.approx.f16x2 %0, %1;" : "=r"(r) : "r"(a));
    return r;
}
__device__ __forceinline__ uint32_t hadd2u(uint32_t a, uint32_t b) {
    uint32_t r;
    asm("add.rn.f16x2 %0, %1, %2;" : "=r"(r) : "r"(a), "r"(b));
    return r;
}

// ---------------- prep ----------------
__global__ void k_prep(const float* Wg_w, const float* Wg_b, const float* gg, const float* gb,
                       const float* gm, const float* gv,
                       const float* Wx_w, const float* Wx_b, const float* xg, const float* xb,
                       const float* xm, const float* xv,
                       const float* psi_w, const float* psi_b, const float* pg, const float* pbt,
                       const float* pm, const float* pv) {
    int o = blockIdx.x, t = threadIdx.x;
    float invg = gg[o] * rsqrtf(gv[o] + 1e-5f);
    float invx = xg[o] * rsqrtf(xv[o] + 1e-5f);
    float vg = Wg_w[o*256 + t] * invg;
    float vx = Wx_w[o*256 + t] * invx;
    __nv_bfloat16 hg = __float2bfloat16(vg);
    __nv_bfloat16 hx = __float2bfloat16(vx);
    d_Wh[t*64 + o]       = hg;
    d_Wl[t*64 + o]       = __float2bfloat16(vg - __bfloat162float(hg));
    d_Wh[(256+t)*64 + o] = hx;
    d_Wl[(256+t)*64 + o] = __float2bfloat16(vx - __bfloat162float(hx));
    int gi = o*256 + t;
    d_att[gi*2]     = 0.f;
    d_att[gi*2 + 1] = 0.f;
    if (t == 0) {
        d_bias[o] = (Wg_b[o] - gm[o]) * invg + gb[o]
                  + (Wx_b[o] - xm[o]) * invx + xb[o];
    }
    if (o == 0 && t < 64) {
        float invp = pg[0] * rsqrtf(pv[0] + 1e-5f);
        d_wp[t] = psi_w[t] * invp;
        if (t == 0) d_bp[0] = (psi_b[0] - pm[0]) * invp + pbt[0];
    }
}

// ---------------- psi via bf16-split HMMA + fused fb/fc/fd convs + CAM gram ----------------
// grid (32, 8), 256 threads, 82176B dynamic smem.
__global__ void __launch_bounds__(256) k_psi2(const float* __restrict__ g, const float* __restrict__ x,
                                              const float* __restrict__ pb_w, const float* __restrict__ pb_b,
                                              const float* __restrict__ pc_w, const float* __restrict__ pc_b,
                                              const float* __restrict__ pd_w, const float* __restrict__ pd_b) {
    extern __shared__ __align__(1024) char ps[];
    // mainloop: A_hi 0..16384 | A_lo 16384..32768 | W_hi 32768..40960 | W_lo 40960..49152
    //           f32stage 49152..81920 | bias 81920..82176
    // epilogue: psi_t [64][129] f 0..33024 | cw_s [64][80] f 33024..53504 | cbias 53504..53824
    uint32_t base = smem_u32(ps);
    uint32_t ahi = base, whi = base + 32768;
    float* f32s   = (float*)(ps + 49152);
    float* bias_s = (float*)(ps + 81920);
    float* psi_t  = (float*)ps;
    float* cw_s   = (float*)(ps + 33024);
    float* cbias  = (float*)(ps + 53504);

    int b = blockIdx.y, p0 = blockIdx.x*128, t = threadIdx.x;
    int w = t >> 5, lane = t & 31;
    if (t < 64) bias_s[t] = d_bias[t];

    float dfr[8][4];
#pragma unroll
    for (int nf = 0; nf < 8; nf++)
#pragma unroll
        for (int q = 0; q < 4; q++) dfr[nf][q] = 0.f;

    int r7 = lane & 7;
    int hsel = lane >> 4;
    uint32_t a_row = ahi + (uint32_t)(w*16 + (lane & 15))*128;
    uint32_t b_row = whi + (uint32_t)((((lane >> 3) & 1)*8 + r7))*128;

    for (int cb = 0; cb < 8; cb++) {
        __syncthreads();
        {
            const float* src = (cb < 4) ? g + ((size_t)b*256 + cb*64)*HWn
                                        : x + ((size_t)b*256 + (cb-4)*64)*HWn;
#pragma unroll
            for (int i = 0; i < 8; i++) {
                int idx = t + i*256;
                int c = idx >> 5, p4 = idx & 31;
                float4 v = *(const float4*)&src[(size_t)c*HWn + p0 + p4*4];
                *(float4*)&f32s[c*128 + p4*4] = v;
            }
        }
        {
#pragma unroll
            for (int q = 0; q < 2; q++) {
                int qi = t + q*256;
                int row = qi >> 3, qq = qi & 7;
                uint32_t so = SWZ((uint32_t)(row*128 + qq*16));
                *(uint4*)(ps + 32768 + so) =
                    *(const uint4*)((const char*)d_Wh + (size_t)(cb*64+row)*128 + qq*16);
                *(uint4*)(ps + 40960 + so) =
                    *(const uint4*)((const char*)d_Wl + (size_t)(cb*64+row)*128 + qq*16);
            }
        }
        __syncthreads();
        {
            int p = t & 127, half = t >> 7;
#pragma unroll
            for (int oct = 0; oct < 4; oct++) {
                int c0 = half*32 + oct*8;
                float v[8];
#pragma unroll
                for (int j = 0; j < 8; j++) v[j] = f32s[(c0+j)*128 + p];
                uint32_t uh[4], ul[4];
#pragma unroll
                for (int j = 0; j < 4; j++) {
                    uint32_t h = cvt_bf16x2(v[2*j], v[2*j+1]);
                    float h0 = __uint_as_float(h << 16);
                    float h1 = __uint_as_float(h & 0xffff0000u);
                    uh[j] = h;
                    ul[j] = cvt_bf16x2(v[2*j] - h0, v[2*j+1] - h1);
                }
                uint32_t so = SWZ((uint32_t)(p*128 + c0*2));
                *(uint4*)(ps + so)         = make_uint4(uh[0], uh[1], uh[2], uh[3]);
                *(uint4*)(ps + 16384 + so) = make_uint4(ul[0], ul[1], ul[2], ul[3]);
            }
        }
        __syncthreads();
        uint32_t afh[4][4], afl[4][4];
#pragma unroll
        for (int ks = 0; ks < 4; ks++) {
            uint32_t aq = (uint32_t)(((2*ks + hsel) ^ r7) * 16);
            ldsm_x4(afh[ks][0], afh[ks][1], afh[ks][2], afh[ks][3], a_row + aq);
            ldsm_x4(afl[ks][0], afl[ks][1], afl[ks][2], afl[ks][3], a_row + 16384 + aq);
        }
#pragma unroll
        for (int ks = 0; ks < 4; ks++) {
#pragma unroll
            for (int nn = 0; nn < 4; nn++) {
                uint32_t bq = (uint32_t)(((2*nn + hsel) ^ r7) * 16);
                uint32_t baddr = b_row + ks*2048 + bq;
                uint32_t bh[4], bl[4];
                ldsm_x4t(bh[0], bh[1], bh[2], bh[3], baddr);
                ldsm_x4t(bl[0], bl[1], bl[2], bl[3], baddr + 8192);
                mma_bf16(dfr[2*nn],   afh[ks], bh);
                mma_bf16(dfr[2*nn],   afh[ks], bl);
                mma_bf16(dfr[2*nn],   afl[ks], bh);
                mma_bf16(dfr[2*nn+1], afh[ks], bh + 2);
                mma_bf16(dfr[2*nn+1], afh[ks], bl + 2);
                mma_bf16(dfr[2*nn+1], afl[ks], bh + 2);
            }
        }
    }
    __syncthreads();
    // ---- epilogue 1: fragments -> psi_t [c][129], stage conv weights ----
    {
        int gr = lane >> 2, tc = lane & 3;
        int i1 = w*16 + gr, i2 = i1 + 8;
#pragma unroll
        for (int nf = 0; nf < 8; nf++) {
            int c0 = nf*8 + 2*tc;
            float b0 = bias_s[c0], b1 = bias_s[c0+1];
            psi_t[c0*129 + i1]     = fmaxf(dfr[nf][0] + b0, 0.f);
            psi_t[(c0+1)*129 + i1] = fmaxf(dfr[nf][1] + b1, 0.f);
            psi_t[c0*129 + i2]     = fmaxf(dfr[nf][2] + b0, 0.f);
            psi_t[(c0+1)*129 + i2] = fmaxf(dfr[nf][3] + b1, 0.f);
        }
    }
    for (int idx = t; idx < 5120; idx += 256) {
        int c = idx / 80, o = idx % 80;
        float wv;
        if (o < 8)       wv = pb_w[o*64 + c];
        else if (o < 16) wv = pc_w[(o-8)*64 + c];
        else             wv = pd_w[(o-16)*64 + c];
        cw_s[idx] = wv;
    }
    if (t < 80) cbias[t] = (t < 8) ? pb_b[t] : (t < 16 ? pc_b[t-8] : pd_b[t-16]);
    __syncthreads();
    // ---- epilogue 2: store psi, run fb/fc/fd convs, CAM gram atomics ----
    for (int idx = t; idx < 8192; idx += 256) {
        int c = idx >> 7, p = idx & 127;
        d_psi[((size_t)b*Cn + c)*HWn + p0 + p] = psi_t[c*129 + p];
    }
    {
        int pos = t & 127, half = t >> 7;
        int o0 = half*40;
        ull acc[20];
#pragma unroll
        for (int q = 0; q < 20; q++) acc[q] = pk2(cbias[o0 + 2*q], cbias[o0 + 2*q + 1]);
        for (int c = 0; c < 64; c++) {
            float v = psi_t[c*129 + pos];
            ull v2 = pk2(v, v);
            const ull* wr = (const ull*)&cw_s[c*80 + o0];
#pragma unroll
            for (int q = 0; q < 20; q++) acc[q] = ffma2(v2, wr[q], acc[q]);
        }
#pragma unroll
        for (int q = 0; q < 20; q++) {
            float v0, v1; upk2(acc[q], v0, v1);
            int o = o0 + 2*q;
#pragma unroll
            for (int s = 0; s < 2; s++) {
                float v = s ? v1 : v0;
                int oo = o + s;
                if (oo < 8)       d_fb[((size_t)b*8 + oo)*HWn + p0 + pos] = v * LOG2E;
                else if (oo < 16) d_fc[((size_t)b*8 + (oo-8))*HWn + p0 + pos] = v;
                else              d_fdh[((size_t)b*64 + (oo-16))*HWn + p0 + pos] = __float2half(v);
            }
        }
    }
    {
        int cjg = t & 15, cig = t >> 4;
        float ga[4][4];
#pragma unroll
        for (int r = 0; r < 4; r++)
#pragma unroll
            for (int q = 0; q < 4; q++) ga[r][q] = 0.f;
        for (int p = 0; p < 128; p++) {
            float a0 = psi_t[(cig*4+0)*129 + p];
            float a1 = psi_t[(cig*4+1)*129 + p];
            float a2 = psi_t[(cig*4+2)*129 + p];
            float a3 = psi_t[(cig*4+3)*129 + p];
            float b0 = psi_t[(cjg*4+0)*129 + p];
            float b1 = psi_t[(cjg*4+1)*129 + p];
            float b2 = psi_t[(cjg*4+2)*129 + p];
            float b3 = psi_t[(cjg*4+3)*129 + p];
            ga[0][0]+=a0*b0; ga[0][1]+=a0*b1; ga[0][2]+=a0*b2; ga[0][3]+=a0*b3;
            ga[1][0]+=a1*b0; ga[1][1]+=a1*b1; ga[1][2]+=a1*b2; ga[1][3]+=a1*b3;
            ga[2][0]+=a2*b0; ga[2][1]+=a2*b1; ga[2][2]+=a2*b2; ga[2][3]+=a2*b3;
            ga[3][0]+=a3*b0; ga[3][1]+=a3*b1; ga[3][2]+=a3*b2; ga[3][3]+=a3*b3;
        }
#pragma unroll
        for (int r = 0; r < 4; r++)
#pragma unroll
            for (int q = 0; q < 4; q++)
                atomicAdd(&d_att[(b*64 + cig*4 + r)*64 + cjg*4 + q], ga[r][q]);
    }
}

// ---------------- PAM + CAM softmax + gate + final multiply ----------------
// grid (32, 8), 256 threads, 102912B dynamic smem.
__global__ void __launch_bounds__(256, 2) k_pam3(const float* __restrict__ alpha_p,
                                                 const float* __restrict__ beta_p,
                                                 const float* __restrict__ x,
                                                 float* __restrict__ out) {
    extern __shared__ __align__(1024) char dsm[];
    float* zr_s = (float*)(dsm + 27136);
    // epilogue union
    float* psi_s = (float*)dsm;               // 64*132 f      0..33792
    float* pam_s = (float*)(dsm + 33792);     // 64*132 f      ..67584
    float* W2_s  = (float*)(dsm + 67584);     // 64*66 f       ..84480
    float* wp_s  = (float*)(dsm + 84480);     // 64 f          ..84736
    float* gred  = (float*)(dsm + 84736);     // 256 f         ..85760
    float* z_s   = (float*)(dsm + 85760);     // 128 f         ..86272
    float* att_s = (float*)(dsm + 86272);     // 64*65 f       ..102912

    uint32_t sbase  = smem_u32(dsm);
    uint32_t fdbase = sbase;
    uint32_t fbh = sbase + 8192;
    uint32_t fch = sbase + 20480;

    int b = blockIdx.y, I0 = blockIdx.x*128, t = threadIdx.x;
    int w = t >> 5, lane = t & 31;
    int gr = lane >> 2, tc = lane & 3;
    int i1 = w*16 + gr, i2 = i1 + 8;

    // zero k8-15 pad of fb/fc hi+lo rows
    for (int idx = t; idx < 1536; idx += 256) {
        char* p;
        if (idx < 512)        p = dsm + 8192  + (idx>>2)*48 + 16 + (idx&3)*4;
        else if (idx < 1024)  p = dsm + 14336 + ((idx-512)>>2)*48 + 16 + (idx&3)*4;
        else if (idx < 1280)  p = dsm + 20480 + ((idx-1024)>>2)*48 + 16 + (idx&3)*4;
        else                  p = dsm + 23552 + ((idx-1280)>>2)*48 + 16 + (idx&3)*4;
        *(uint32_t*)p = 0u;
    }
    // stage fb bf16 hi/lo [i][k] (48B rows)
    {
        int i = t & 127, half = t >> 7;
        float v0 = d_fb[((size_t)b*8 + half*4 + 0)*HWn + I0 + i];
        float v1 = d_fb[((size_t)b*8 + half*4 + 1)*HWn + I0 + i];
        float v2 = d_fb[((size_t)b*8 + half*4 + 2)*HWn + I0 + i];
        float v3 = d_fb[((size_t)b*8 + half*4 + 3)*HWn + I0 + i];
        uint32_t h0 = cvt_bf16x2(v0, v1), h1 = cvt_bf16x2(v2, v3);
        float r0 = __uint_as_float(h0 << 16), r1 = __uint_as_float(h0 & 0xffff0000u);
        float r2 = __uint_as_float(h1 << 16), r3 = __uint_as_float(h1 & 0xffff0000u);
        uint32_t l0 = cvt_bf16x2(v0 - r0, v1 - r1), l1 = cvt_bf16x2(v2 - r2, v3 - r3);
        *(uint32_t*)(dsm + 8192  + i*48 + half*8)     = h0;
        *(uint32_t*)(dsm + 8192  + i*48 + half*8 + 4) = h1;
        *(uint32_t*)(dsm + 14336 + i*48 + half*8)     = l0;
        *(uint32_t*)(dsm + 14336 + i*48 + half*8 + 4) = l1;
    }
    __syncthreads();

    uint32_t ah[4], al[4];
    {
        uint32_t aaddr = fbh + (uint32_t)(w*16 + (lane & 15))*48 + (lane >> 4)*16;
        ldsm_x4(ah[0], ah[1], ah[2], ah[3], aaddr);
        ldsm_x4(al[0], al[1], al[2], al[3], aaddr + 6144);
    }

    float acc[8][4];
#pragma unroll
    for (int ng = 0; ng < 8; ng++)
#pragma unroll
        for (int q = 0; q < 4; q++) acc[ng][q] = 0.f;
    float z1 = 0.f, z2 = 0.f;
    float m1 = -1e30f, m2 = -1e30f;

    float fcr0, fcr1;
    uint32_t fdr[8];
    {
        int j = t & 63, kp2 = t >> 6;
        fcr0 = d_fc[((size_t)b*8 + 2*kp2 + 0)*HWn + j];
        fcr1 = d_fc[((size_t)b*8 + 2*kp2 + 1)*HWn + j];
#pragma unroll
        for (int q = 0; q < 8; q++) {
            int idx = t + q*256;
            int c = idx >> 5, jp = idx & 31;
            fdr[q] = *(const uint32_t*)&d_fdh[((size_t)b*64 + c)*HWn + jp*2];
        }
    }

    uint32_t fdrow = (uint32_t)(lane & 15)*128 + (uint32_t)(lane >> 4)*16;

    for (int jt = 0; jt < 64; jt++) {
        __syncthreads();
        {
            int j = t & 63, kp2 = t >> 6;
            uint32_t h = cvt_bf16x2(fcr0, fcr1);
            float r0 = __uint_as_float(h << 16), r1 = __uint_as_float(h & 0xffff0000u);
            uint32_t l = cvt_bf16x2(fcr0 - r0, fcr1 - r1);
            *(uint32_t*)(dsm + 20480 + j*48 + kp2*4) = h;
            *(uint32_t*)(dsm + 23552 + j*48 + kp2*4) = l;
        }
#pragma unroll
        for (int q = 0; q < 8; q++) {
            int idx = t + q*256;
            int c = idx >> 5, jp = idx & 31;
            *(uint32_t*)(dsm + SWZ((uint32_t)(c*128 + jp*4))) = fdr[q];
        }
        __syncthreads();
        // energy mma
        float e[8][4];
#pragma unroll
        for (int ng = 0; ng < 8; ng++)
#pragma unroll
            for (int q = 0; q < 4; q++) e[ng][q] = 0.f;
#pragma unroll
        for (int jg = 0; jg < 4; jg++) {
            uint32_t baddr = fch + (uint32_t)(jg*16 + (lane & 15))*48 + (lane >> 4)*16;
            uint32_t bh[4], bl[4];
            ldsm_x4(bh[0], bh[1], bh[2], bh[3], baddr);
            ldsm_x4(bl[0], bl[1], bl[2], bl[3], baddr + 3072);
            mma_bf16s(e[2*jg],   ah, bh[0], bh[2]);
            mma_bf16s(e[2*jg],   ah, bl[0], bl[2]);
            mma_bf16s(e[2*jg],   al, bh[0], bh[2]);
            mma_bf16s(e[2*jg+1], ah, bh[1], bh[3]);
            mma_bf16s(e[2*jg+1], ah, bl[1], bl[3]);
            mma_bf16s(e[2*jg+1], al, bh[1], bh[3]);
        }
        if (jt < 63) {
            int j0n = (jt+1)*64;
            int j = t & 63, kp2 = t >> 6;
            fcr0 = d_fc[((size_t)b*8 + 2*kp2 + 0)*HWn + j0n + j];
            fcr1 = d_fc[((size_t)b*8 + 2*kp2 + 1)*HWn + j0n + j];
#pragma unroll
            for (int q = 0; q < 8; q++) {
                int idx = t + q*256;
                int c = idx >> 5, jp = idx & 31;
                fdr[q] = *(const uint32_t*)&d_fdh[((size_t)b*64 + c)*HWn + j0n + jp*2];
            }
        }
        // online row max (quad shfl) + register rescale
        float tm1 = -1e30f, tm2 = -1e30f;
#pragma unroll
        for (int ng = 0; ng < 8; ng++) {
            tm1 = fmaxf(tm1, fmaxf(e[ng][0], e[ng][1]));
            tm2 = fmaxf(tm2, fmaxf(e[ng][2], e[ng][3]));
        }
        tm1 = fmaxf(tm1, __shfl_xor_sync(0xffffffffu, tm1, 1));
        tm1 = fmaxf(tm1, __shfl_xor_sync(0xffffffffu, tm1, 2));
        tm2 = fmaxf(tm2, __shfl_xor_sync(0xffffffffu, tm2, 1));
        tm2 = fmaxf(tm2, __shfl_xor_sync(0xffffffffu, tm2, 2));
        float mn1 = fmaxf(m1, tm1), mn2 = fmaxf(m2, tm2);
        float sc1 = ex2f(m1 - mn1), sc2 = ex2f(m2 - mn2);
        m1 = mn1; m2 = mn2;
        z1 *= sc1; z2 *= sc2;
#pragma unroll
        for (int ng = 0; ng < 8; ng++) {
            acc[ng][0] *= sc1; acc[ng][1] *= sc1;
            acc[ng][2] *= sc2; acc[ng][3] *= sc2;
        }
        // exp via ex2.f16x2 -> p fragments
        uint32_t afr[4][4];
#pragma unroll
        for (int ng = 0; ng < 8; ng++) {
            uint32_t a01 = cvt_f16x2(e[ng][0] - mn1, e[ng][1] - mn1);
            uint32_t a23 = cvt_f16x2(e[ng][2] - mn2, e[ng][3] - mn2);
            uint32_t p01 = ex2h2(a01);
            uint32_t p23 = ex2h2(a23);
            int kp = ng >> 1;
            if ((ng & 1) == 0) { afr[kp][0] = p01; afr[kp][1] = p23; }
            else               { afr[kp][2] = p01; afr[kp][3] = p23; }
        }
        // z partial via HADD2 tree
        {
            uint32_t s1 = hadd2u(hadd2u(hadd2u(afr[0][0], afr[0][2]), hadd2u(afr[1][0], afr[1][2])),
                                 hadd2u(hadd2u(afr[2][0], afr[2][2]), hadd2u(afr[3][0], afr[3][2])));
            uint32_t s2 = hadd2u(hadd2u(hadd2u(afr[0][1], afr[0][3]), hadd2u(afr[1][1], afr[1][3])),
                                 hadd2u(hadd2u(afr[2][1], afr[2][3]), hadd2u(afr[3][1], afr[3][3])));
            float2 f1 = __half22float2(*(__half2*)&s1);
            float2 f2 = __half22float2(*(__half2*)&s2);
            z1 += f1.x + f1.y;
            z2 += f2.x + f2.y;
        }
        // accumulate mma (fp16)
#pragma unroll
        for (int ng2 = 0; ng2 < 4; ng2++) {
#pragma unroll
            for (int kp = 0; kp < 4; kp++) {
                uint32_t off = fdrow + (uint32_t)(ng2*2048 + kp*32);
                uint32_t f4[4];
                ldsm_x4(f4[0], f4[1], f4[2], f4[3], fdbase + SWZ(off));
                mma_f16s(acc[2*ng2],   afr[kp], f4[0], f4[2]);
                mma_f16s(acc[2*ng2+1], afr[kp], f4[1], f4[3]);
            }
        }
    }
    // ---- z reduction across the quad ----
    z1 += __shfl_xor_sync(0xffffffffu, z1, 1);
    z1 += __shfl_xor_sync(0xffffffffu, z1, 2);
    z2 += __shfl_xor_sync(0xffffffffu, z2, 1);
    z2 += __shfl_xor_sync(0xffffffffu, z2, 2);
    __syncthreads();   // mainloop smem reads done before epilogue overwrites
    if (tc == 0) {
        zr_s[i1] = alpha_p[0] / z1;
        zr_s[i2] = alpha_p[0] / z2;
    }
    __syncthreads();
    if (t < 128) z_s[t] = zr_s[t];
    __syncthreads();
    // ---- load psi tile / att / wp ----
    for (int idx = t; idx < 8192; idx += 256) {
        int c = idx >> 7, p = idx & 127;
        psi_s[c*132 + p] = d_psi[((size_t)b*Cn + c)*HWn + I0 + p];
    }
    for (int idx = t; idx < 4096; idx += 256)
        att_s[(idx >> 6)*65 + (idx & 63)] = d_att[b*4096 + idx];
    if (t < 64) wp_s[t] = d_wp[t];
    __syncthreads();
    // ---- CAM softmax -> W2_s[c][66] (4 threads per row) ----
    {
        int r = t >> 2, q4 = t & 3;
        float v[16];
#pragma unroll
        for (int k = 0; k < 16; k++) v[k] = att_s[r*65 + q4*16 + k];
        float mx = -1e30f, mn = 1e30f;
#pragma unroll
        for (int k = 0; k < 16; k++) { mx = fmaxf(mx, v[k]); mn = fminf(mn, v[k]); }
        mx = fmaxf(mx, __shfl_xor_sync(0xffffffffu, mx, 1));
        mx = fmaxf(mx, __shfl_xor_sync(0xffffffffu, mx, 2));
        mn = fminf(mn, __shfl_xor_sync(0xffffffffu, mn, 1));
        mn = fminf(mn, __shfl_xor_sync(0xffffffffu, mn, 2));
        float m2r = mx - mn;
        float ssum = 0.f;
#pragma unroll
        for (int k = 0; k < 16; k++) { float ev = __expf((mx - v[k]) - m2r); v[k] = ev; ssum += ev; }
        ssum += __shfl_xor_sync(0xffffffffu, ssum, 1);
        ssum += __shfl_xor_sync(0xffffffffu, ssum, 2);
        float scale = beta_p[0] * wp_s[r] / ssum;
#pragma unroll
        for (int k = 0; k < 16; k++) W2_s[r*66 + q4*16 + k] = v[k] * scale;
    }
    // ---- fragments -> pam_s[c][i] ----
    {
        float zz1 = z_s[i1], zz2 = z_s[i2];
#pragma unroll
        for (int ng = 0; ng < 8; ng++) {
            int c = ng*8 + 2*tc;
            pam_s[c*132 + i1]     = acc[ng][0]*zz1 + psi_s[c*132 + i1];
            pam_s[(c+1)*132 + i1] = acc[ng][1]*zz1 + psi_s[(c+1)*132 + i1];
            pam_s[c*132 + i2]     = acc[ng][2]*zz2 + psi_s[c*132 + i2];
            pam_s[(c+1)*132 + i2] = acc[ng][3]*zz2 + psi_s[(c+1)*132 + i2];
        }
    }
    __syncthreads();
    // ---- fused CAM + gate ----
    {
        int p = t & 127, half = t >> 7;
        int c0 = half*32, d0 = half*32;
        float part1 = 0.f;
#pragma unroll 8
        for (int c = 0; c < 32; c++) {
            int cc = c0 + c;
            part1 += wp_s[cc] * psi_s[cc*132 + p] * pam_s[cc*132 + p];
        }
        ull v[16];
#pragma unroll
        for (int q = 0; q < 16; q++) v[q] = 0ull;
        for (int c = 0; c < 64; c++) {
            float pm = pam_s[c*132 + p];
            ull pm2 = pk2(pm, pm);
            const ull* wr = (const ull*)&W2_s[c*66 + d0];
#pragma unroll
            for (int q = 0; q < 16; q++) v[q] = ffma2(pm2, wr[q], v[q]);
        }
        float part2 = 0.f;
#pragma unroll
        for (int q = 0; q < 16; q++) {
            float v0, v1; upk2(v[q], v0, v1);
            part2 += psi_s[(d0+2*q)*132 + p]*v0 + psi_s[(d0+2*q+1)*132 + p]*v1;
        }
        gred[half*128 + p] = part1 + part2;
    }
    __syncthreads();
    if (t < 128) {
        float gate = d_bp[0] + gred[t] + gred[128 + t];
        z_s[t] = 1.f / (1.f + __expf(-gate));   // da
    }
    __syncthreads();
    // ---- fused final multiply ----
    {
        int p = t & 127, hb = t >> 7;
        float da = z_s[p];
        const float* xp = x + ((size_t)b*256)*HWn + I0 + p;
        float* op = out + ((size_t)b*256)*HWn + I0 + p;
#pragma unroll 8
        for (int c = hb; c < 256; c += 2)
            op[(size_t)c*HWn] = xp[(size_t)c*HWn] * da;
    }
}

// ---------------- launch ----------------
extern "C" void kernel_launch(void* const* d_in, const int* in_sizes, int n_in,
                              void* d_out, int out_size) {
    const float* g = (const float*)d_in[0];
    const float* x = (const float*)d_in[1];

    cudaFuncSetAttribute(k_psi2, cudaFuncAttributeMaxDynamicSharedMemorySize, 82176);
    cudaFuncSetAttribute(k_pam3, cudaFuncAttributeMaxDynamicSharedMemorySize, 102912);

    k_prep<<<64, 256>>>((const float*)d_in[2],  (const float*)d_in[3],  (const float*)d_in[4],
                        (const float*)d_in[5],  (const float*)d_in[6],  (const float*)d_in[7],
                        (const float*)d_in[8],  (const float*)d_in[9],  (const float*)d_in[10],
                        (const float*)d_in[11], (const float*)d_in[12], (const float*)d_in[13],
                        (const float*)d_in[14], (const float*)d_in[15], (const float*)d_in[16],
                        (const float*)d_in[17], (const float*)d_in[18], (const float*)d_in[19]);

    k_psi2<<<dim3(32, 8), 256, 82176>>>(g, x,
        (const float*)d_in[20], (const float*)d_in[21],
        (const float*)d_in[22], (const float*)d_in[23],
        (const float*)d_in[24], (const float*)d_in[25]);

    k_pam3<<<dim3(32, 8), 256, 102912>>>((const float*)d_in[26], (const float*)d_in[27],
                                         x, (float*)d_out);
}

// round 11
// speedup vs baseline: 5.5803x; 1.1073x over previous
#include <cuda_runtime.h>
#include <cuda_bf16.h>
#include <cuda_fp16.h>
#include <math.h>
#include <stdint.h>

typedef unsigned long long ull;

#define Bn 8
#define Cn 64
#define HWn 4096
#define LOG2E 1.4426950408889634f

// ---------------- scratch (device globals; no allocs allowed) ----------------
__device__ __align__(16) float d_psi[Bn*Cn*HWn];     // 8MB
__device__ __align__(16) float d_fb [Bn*8*HWn];      // pre-scaled by log2(e)
__device__ __align__(16) float d_fc [Bn*8*HWn];
__device__ __align__(16) __half d_fdh[Bn*Cn*HWn];    // 4MB fp16 [b][c][j]
__device__ __align__(16) float d_att[Bn*64*64];      // CAM gram (atomic-accumulated)
__device__ __align__(16) __nv_bfloat16 d_Wh[512*64]; // folded weight hi, [cin][out]
__device__ __align__(16) __nv_bfloat16 d_Wl[512*64]; // folded weight lo
__device__ __align__(16) float d_bias[64];
__device__ __align__(16) float d_wp[64];
__device__ __align__(16) float d_bp[1];

// ---------------- f32x2 helpers ----------------
__device__ __forceinline__ ull pk2(float lo, float hi) {
    ull r; asm("mov.b64 %0, {%1, %2};" : "=l"(r) : "f"(lo), "f"(hi)); return r;
}
__device__ __forceinline__ void upk2(ull v, float& lo, float& hi) {
    asm("mov.b64 {%0, %1}, %2;" : "=f"(lo), "=f"(hi) : "l"(v));
}
__device__ __forceinline__ ull ffma2(ull a, ull b, ull c) {
    ull d; asm("fma.rn.f32x2 %0, %1, %2, %3;" : "=l"(d) : "l"(a), "l"(b), "l"(c)); return d;
}
__device__ __forceinline__ float ex2f(float x) {
    float r; asm("ex2.approx.f32 %0, %1;" : "=f"(r) : "f"(x)); return r;
}

// ---------------- warp MMA helpers ----------------
__device__ __forceinline__ uint32_t smem_u32(const void* p) {
    uint32_t a;
    asm("{ .reg .u64 t; cvta.to.shared.u64 t, %1; cvt.u32.u64 %0, t; }" : "=r"(a) : "l"(p));
    return a;
}
#define SWZ(off) ((off) ^ (((off) >> 3) & 0x70))
__device__ __forceinline__ void ldsm_x4(uint32_t& r0, uint32_t& r1, uint32_t& r2, uint32_t& r3,
                                        uint32_t addr) {
    asm volatile("ldmatrix.sync.aligned.m8n8.x4.shared.b16 {%0,%1,%2,%3}, [%4];"
                 : "=r"(r0), "=r"(r1), "=r"(r2), "=r"(r3) : "r"(addr));
}
__device__ __forceinline__ void ldsm_x4t(uint32_t& r0, uint32_t& r1, uint32_t& r2, uint32_t& r3,
                                         uint32_t addr) {
    asm volatile("ldmatrix.sync.aligned.m8n8.x4.trans.shared.b16 {%0,%1,%2,%3}, [%4];"
                 : "=r"(r0), "=r"(r1), "=r"(r2), "=r"(r3) : "r"(addr));
}
__device__ __forceinline__ void mma_bf16(float* d, const uint32_t* a, const uint32_t* b) {
    asm volatile(
        "mma.sync.aligned.m16n8k16.row.col.f32.bf16.bf16.f32 "
        "{%0,%1,%2,%3}, {%4,%5,%6,%7}, {%8,%9}, {%0,%1,%2,%3};"
        : "+f"(d[0]), "+f"(d[1]), "+f"(d[2]), "+f"(d[3])
        : "r"(a[0]), "r"(a[1]), "r"(a[2]), "r"(a[3]), "r"(b[0]), "r"(b[1]));
}
__device__ __forceinline__ void mma_f16s(float* d, const uint32_t* a, uint32_t b0, uint32_t b1) {
    asm volatile(
        "mma.sync.aligned.m16n8k16.row.col.f32.f16.f16.f32 "
        "{%0,%1,%2,%3}, {%4,%5,%6,%7}, {%8,%9}, {%0,%1,%2,%3};"
        : "+f"(d[0]), "+f"(d[1]), "+f"(d[2]), "+f"(d[3])
        : "r"(a[0]), "r"(a[1]), "r"(a[2]), "r"(a[3]), "r"(b0), "r"(b1));
}
__device__ __forceinline__ uint32_t cvt_bf16x2(float a, float b) {
    uint32_t r;
    asm("cvt.rn.satfinite.bf16x2.f32 %0, %1, %2;" : "=r"(r) : "f"(b), "f"(a));
    return r;
}
__device__ __forceinline__ uint32_t cvt_f16x2(float a, float b) {
    // lower half = a, upper = b
    uint32_t r;
    asm("cvt.rn.f16x2.f32 %0, %1, %2;" : "=r"(r) : "f"(b), "f"(a));
    return r;
}
__device__ __forceinline__ uint32_t ex2h2(uint32_t a) {
    uint32_t r;
    asm("ex2.approx.f16x2 %0, %1;" : "=r"(r) : "r"(a));
    return r;
}
__device__ __forceinline__ uint32_t hadd2u(uint32_t a, uint32_t b) {
    uint32_t r;
    asm("add.rn.f16x2 %0, %1, %2;" : "=r"(r) : "r"(a), "r"(b));
    return r;
}

// ---------------- prep (grid (64,4) x 64 threads for latency hiding) ----------------
__global__ void k_prep(const float* Wg_w, const float* Wg_b, const float* gg, const float* gb,
                       const float* gm, const float* gv,
                       const float* Wx_w, const float* Wx_b, const float* xg, const float* xb,
                       const float* xm, const float* xv,
                       const float* psi_w, const float* psi_b, const float* pg, const float* pbt,
                       const float* pm, const float* pv) {
    int o = blockIdx.x, t = threadIdx.x;
    int cin = blockIdx.y*64 + t;
    float invg = gg[o] * rsqrtf(gv[o] + 1e-5f);
    float invx = xg[o] * rsqrtf(xv[o] + 1e-5f);
    float vg = Wg_w[o*256 + cin] * invg;
    float vx = Wx_w[o*256 + cin] * invx;
    __nv_bfloat16 hg = __float2bfloat16(vg);
    __nv_bfloat16 hx = __float2bfloat16(vx);
    d_Wh[cin*64 + o]       = hg;
    d_Wl[cin*64 + o]       = __float2bfloat16(vg - __bfloat162float(hg));
    d_Wh[(256+cin)*64 + o] = hx;
    d_Wl[(256+cin)*64 + o] = __float2bfloat16(vx - __bfloat162float(hx));
    int gi = (o*4 + blockIdx.y)*64 + t;        // 16384 ids
    d_att[gi*2]     = 0.f;
    d_att[gi*2 + 1] = 0.f;
    if (blockIdx.y == 0 && t == 0) {
        d_bias[o] = (Wg_b[o] - gm[o]) * invg + gb[o]
                  + (Wx_b[o] - xm[o]) * invx + xb[o];
    }
    if (o == 0 && blockIdx.y == 0) {
        float invp = pg[0] * rsqrtf(pv[0] + 1e-5f);
        d_wp[t] = psi_w[t] * invp;
        if (t == 0) d_bp[0] = (psi_b[0] - pm[0]) * invp + pbt[0];
    }
}

// ---------------- psi via bf16-split HMMA + fused fb/fc/fd convs + CAM gram ----------------
__global__ void __launch_bounds__(256) k_psi2(const float* __restrict__ g, const float* __restrict__ x,
                                              const float* __restrict__ pb_w, const float* __restrict__ pb_b,
                                              const float* __restrict__ pc_w, const float* __restrict__ pc_b,
                                              const float* __restrict__ pd_w, const float* __restrict__ pd_b) {
    extern __shared__ __align__(1024) char ps[];
    uint32_t base = smem_u32(ps);
    uint32_t ahi = base, whi = base + 32768;
    float* f32s   = (float*)(ps + 49152);
    float* bias_s = (float*)(ps + 81920);
    float* psi_t  = (float*)ps;
    float* cw_s   = (float*)(ps + 33024);
    float* cbias  = (float*)(ps + 53504);

    int b = blockIdx.y, p0 = blockIdx.x*128, t = threadIdx.x;
    int w = t >> 5, lane = t & 31;
    if (t < 64) bias_s[t] = d_bias[t];

    float dfr[8][4];
#pragma unroll
    for (int nf = 0; nf < 8; nf++)
#pragma unroll
        for (int q = 0; q < 4; q++) dfr[nf][q] = 0.f;

    int r7 = lane & 7;
    int hsel = lane >> 4;
    uint32_t a_row = ahi + (uint32_t)(w*16 + (lane & 15))*128;
    uint32_t b_row = whi + (uint32_t)((((lane >> 3) & 1)*8 + r7))*128;

    for (int cb = 0; cb < 8; cb++) {
        __syncthreads();
        {
            const float* src = (cb < 4) ? g + ((size_t)b*256 + cb*64)*HWn
                                        : x + ((size_t)b*256 + (cb-4)*64)*HWn;
#pragma unroll
            for (int i = 0; i < 8; i++) {
                int idx = t + i*256;
                int c = idx >> 5, p4 = idx & 31;
                float4 v = *(const float4*)&src[(size_t)c*HWn + p0 + p4*4];
                *(float4*)&f32s[c*128 + p4*4] = v;
            }
        }
        {
#pragma unroll
            for (int q = 0; q < 2; q++) {
                int qi = t + q*256;
                int row = qi >> 3, qq = qi & 7;
                uint32_t so = SWZ((uint32_t)(row*128 + qq*16));
                *(uint4*)(ps + 32768 + so) =
                    *(const uint4*)((const char*)d_Wh + (size_t)(cb*64+row)*128 + qq*16);
                *(uint4*)(ps + 40960 + so) =
                    *(const uint4*)((const char*)d_Wl + (size_t)(cb*64+row)*128 + qq*16);
            }
        }
        __syncthreads();
        {
            int p = t & 127, half = t >> 7;
#pragma unroll
            for (int oct = 0; oct < 4; oct++) {
                int c0 = half*32 + oct*8;
                float v[8];
#pragma unroll
                for (int j = 0; j < 8; j++) v[j] = f32s[(c0+j)*128 + p];
                uint32_t uh[4], ul[4];
#pragma unroll
                for (int j = 0; j < 4; j++) {
                    uint32_t h = cvt_bf16x2(v[2*j], v[2*j+1]);
                    float h0 = __uint_as_float(h << 16);
                    float h1 = __uint_as_float(h & 0xffff0000u);
                    uh[j] = h;
                    ul[j] = cvt_bf16x2(v[2*j] - h0, v[2*j+1] - h1);
                }
                uint32_t so = SWZ((uint32_t)(p*128 + c0*2));
                *(uint4*)(ps + so)         = make_uint4(uh[0], uh[1], uh[2], uh[3]);
                *(uint4*)(ps + 16384 + so) = make_uint4(ul[0], ul[1], ul[2], ul[3]);
            }
        }
        __syncthreads();
        uint32_t afh[4][4], afl[4][4];
#pragma unroll
        for (int ks = 0; ks < 4; ks++) {
            uint32_t aq = (uint32_t)(((2*ks + hsel) ^ r7) * 16);
            ldsm_x4(afh[ks][0], afh[ks][1], afh[ks][2], afh[ks][3], a_row + aq);
            ldsm_x4(afl[ks][0], afl[ks][1], afl[ks][2], afl[ks][3], a_row + 16384 + aq);
        }
#pragma unroll
        for (int ks = 0; ks < 4; ks++) {
#pragma unroll
            for (int nn = 0; nn < 4; nn++) {
                uint32_t bq = (uint32_t)(((2*nn + hsel) ^ r7) * 16);
                uint32_t baddr = b_row + ks*2048 + bq;
                uint32_t bh[4], bl[4];
                ldsm_x4t(bh[0], bh[1], bh[2], bh[3], baddr);
                ldsm_x4t(bl[0], bl[1], bl[2], bl[3], baddr + 8192);
                mma_bf16(dfr[2*nn],   afh[ks], bh);
                mma_bf16(dfr[2*nn],   afh[ks], bl);
                mma_bf16(dfr[2*nn],   afl[ks], bh);
                mma_bf16(dfr[2*nn+1], afh[ks], bh + 2);
                mma_bf16(dfr[2*nn+1], afh[ks], bl + 2);
                mma_bf16(dfr[2*nn+1], afl[ks], bh + 2);
            }
        }
    }
    __syncthreads();
    // ---- epilogue 1: fragments -> psi_t [c][129], stage conv weights ----
    {
        int gr = lane >> 2, tc = lane & 3;
        int i1 = w*16 + gr, i2 = i1 + 8;
#pragma unroll
        for (int nf = 0; nf < 8; nf++) {
            int c0 = nf*8 + 2*tc;
            float b0 = bias_s[c0], b1 = bias_s[c0+1];
            psi_t[c0*129 + i1]     = fmaxf(dfr[nf][0] + b0, 0.f);
            psi_t[(c0+1)*129 + i1] = fmaxf(dfr[nf][1] + b1, 0.f);
            psi_t[c0*129 + i2]     = fmaxf(dfr[nf][2] + b0, 0.f);
            psi_t[(c0+1)*129 + i2] = fmaxf(dfr[nf][3] + b1, 0.f);
        }
    }
    for (int idx = t; idx < 5120; idx += 256) {
        int c = idx / 80, o = idx % 80;
        float wv;
        if (o < 8)       wv = pb_w[o*64 + c];
        else if (o < 16) wv = pc_w[(o-8)*64 + c];
        else             wv = pd_w[(o-16)*64 + c];
        cw_s[idx] = wv;
    }
    if (t < 80) cbias[t] = (t < 8) ? pb_b[t] : (t < 16 ? pc_b[t-8] : pd_b[t-16]);
    __syncthreads();
    // ---- epilogue 2: store psi, fb/fc/fd convs, CAM gram atomics ----
    for (int idx = t; idx < 8192; idx += 256) {
        int c = idx >> 7, p = idx & 127;
        d_psi[((size_t)b*Cn + c)*HWn + p0 + p] = psi_t[c*129 + p];
    }
    {
        int pos = t & 127, half = t >> 7;
        int o0 = half*40;
        ull acc[20];
#pragma unroll
        for (int q = 0; q < 20; q++) acc[q] = pk2(cbias[o0 + 2*q], cbias[o0 + 2*q + 1]);
        for (int c = 0; c < 64; c++) {
            float v = psi_t[c*129 + pos];
            ull v2 = pk2(v, v);
            const ull* wr = (const ull*)&cw_s[c*80 + o0];
#pragma unroll
            for (int q = 0; q < 20; q++) acc[q] = ffma2(v2, wr[q], acc[q]);
        }
#pragma unroll
        for (int q = 0; q < 20; q++) {
            float v0, v1; upk2(acc[q], v0, v1);
            int o = o0 + 2*q;
#pragma unroll
            for (int s = 0; s < 2; s++) {
                float v = s ? v1 : v0;
                int oo = o + s;
                if (oo < 8)       d_fb[((size_t)b*8 + oo)*HWn + p0 + pos] = v * LOG2E;
                else if (oo < 16) d_fc[((size_t)b*8 + (oo-8))*HWn + p0 + pos] = v;
                else              d_fdh[((size_t)b*64 + (oo-16))*HWn + p0 + pos] = __float2half(v);
            }
        }
    }
    {
        int cjg = t & 15, cig = t >> 4;
        float ga[4][4];
#pragma unroll
        for (int r = 0; r < 4; r++)
#pragma unroll
            for (int q = 0; q < 4; q++) ga[r][q] = 0.f;
        for (int p = 0; p < 128; p++) {
            float a0 = psi_t[(cig*4+0)*129 + p];
            float a1 = psi_t[(cig*4+1)*129 + p];
            float a2 = psi_t[(cig*4+2)*129 + p];
            float a3 = psi_t[(cig*4+3)*129 + p];
            float b0 = psi_t[(cjg*4+0)*129 + p];
            float b1 = psi_t[(cjg*4+1)*129 + p];
            float b2 = psi_t[(cjg*4+2)*129 + p];
            float b3 = psi_t[(cjg*4+3)*129 + p];
            ga[0][0]+=a0*b0; ga[0][1]+=a0*b1; ga[0][2]+=a0*b2; ga[0][3]+=a0*b3;
            ga[1][0]+=a1*b0; ga[1][1]+=a1*b1; ga[1][2]+=a1*b2; ga[1][3]+=a1*b3;
            ga[2][0]+=a2*b0; ga[2][1]+=a2*b1; ga[2][2]+=a2*b2; ga[2][3]+=a2*b3;
            ga[3][0]+=a3*b0; ga[3][1]+=a3*b1; ga[3][2]+=a3*b2; ga[3][3]+=a3*b3;
        }
#pragma unroll
        for (int r = 0; r < 4; r++)
#pragma unroll
            for (int q = 0; q < 4; q++)
                atomicAdd(&d_att[(b*64 + cig*4 + r)*64 + cjg*4 + q], ga[r][q]);
    }
}

// ---------------- PAM + CAM softmax + gate + final multiply ----------------
// fp16 single-product energies; double-buffered fc/fd, ONE sync per j-tile.
// Mainloop smem: fd 2x8192 @0 | fb 128x48 @16384 | fc 2x3072 @22528 (..28672)
__global__ void __launch_bounds__(256, 2) k_pam3(const float* __restrict__ alpha_p,
                                                 const float* __restrict__ beta_p,
                                                 const float* __restrict__ x,
                                                 float* __restrict__ out) {
    extern __shared__ __align__(1024) char dsm[];
    // epilogue union
    float* psi_s = (float*)dsm;               // 64*132 f      0..33792
    float* pam_s = (float*)(dsm + 33792);     // 64*132 f      ..67584
    float* W2_s  = (float*)(dsm + 67584);     // 64*66 f       ..84480
    float* wp_s  = (float*)(dsm + 84480);     // 64 f          ..84736
    float* gred  = (float*)(dsm + 84736);     // 256 f         ..85760
    float* z_s   = (float*)(dsm + 85760);     // 128 f         ..86272
    float* att_s = (float*)(dsm + 86272);     // 64*65 f       ..102912

    uint32_t sbase = smem_u32(dsm);
    uint32_t fbb   = sbase + 16384;
    uint32_t fcb   = sbase + 22528;

    int b = blockIdx.y, I0 = blockIdx.x*128, t = threadIdx.x;
    int w = t >> 5, lane = t & 31;
    int gr = lane >> 2, tc = lane & 3;
    int i1 = w*16 + gr, i2 = i1 + 8;

    // zero k8-15 pads: fb 128 rows, fc 128 rows (both bufs contiguous)
    for (int idx = t; idx < 1024; idx += 256) {
        char* p;
        if (idx < 512) p = dsm + 16384 + (idx>>2)*48 + 16 + (idx&3)*4;
        else { int r = idx - 512; p = dsm + 22528 + (r>>2)*48 + 16 + (r&3)*4; }
        *(uint32_t*)p = 0u;
    }
    // stage fb fp16 [i][k] (48B rows)
    {
        int i = t & 127, half = t >> 7;
        float v0 = d_fb[((size_t)b*8 + half*4 + 0)*HWn + I0 + i];
        float v1 = d_fb[((size_t)b*8 + half*4 + 1)*HWn + I0 + i];
        float v2 = d_fb[((size_t)b*8 + half*4 + 2)*HWn + I0 + i];
        float v3 = d_fb[((size_t)b*8 + half*4 + 3)*HWn + I0 + i];
        *(uint32_t*)(dsm + 16384 + i*48 + half*8)     = cvt_f16x2(v0, v1);
        *(uint32_t*)(dsm + 16384 + i*48 + half*8 + 4) = cvt_f16x2(v2, v3);
    }
    __syncthreads();

    uint32_t af[4];
    {
        uint32_t aaddr = fbb + (uint32_t)(w*16 + (lane & 15))*48 + (lane >> 4)*16;
        ldsm_x4(af[0], af[1], af[2], af[3], aaddr);
    }

    float acc[8][4];
#pragma unroll
    for (int ng = 0; ng < 8; ng++)
#pragma unroll
        for (int q = 0; q < 4; q++) acc[ng][q] = 0.f;
    float z1 = 0.f, z2 = 0.f;
    float m1 = -1e30f, m2 = -1e30f;

    float fcr0, fcr1;
    uint32_t fdr[8];
    {
        int j = t & 63, kp2 = t >> 6;
        fcr0 = d_fc[((size_t)b*8 + 2*kp2 + 0)*HWn + j];
        fcr1 = d_fc[((size_t)b*8 + 2*kp2 + 1)*HWn + j];
#pragma unroll
        for (int q = 0; q < 8; q++) {
            int idx = t + q*256;
            int c = idx >> 5, jp = idx & 31;
            fdr[q] = *(const uint32_t*)&d_fdh[((size_t)b*64 + c)*HWn + jp*2];
        }
    }

    uint32_t fdrow = (uint32_t)(lane & 15)*128 + (uint32_t)(lane >> 4)*16;

    for (int jt = 0; jt < 64; jt++) {
        uint32_t buf = (uint32_t)(jt & 1);
        // store staged regs into buf
        {
            int j = t & 63, kp2 = t >> 6;
            *(uint32_t*)(dsm + 22528 + buf*3072 + j*48 + kp2*4) = cvt_f16x2(fcr0, fcr1);
        }
#pragma unroll
        for (int q = 0; q < 8; q++) {
            int idx = t + q*256;
            int c = idx >> 5, jp = idx & 31;
            *(uint32_t*)(dsm + buf*8192 + SWZ((uint32_t)(c*128 + jp*4))) = fdr[q];
        }
        __syncthreads();
        // prefetch next tile immediately (latency covered by compute below)
        if (jt < 63) {
            int j0n = (jt+1)*64;
            int j = t & 63, kp2 = t >> 6;
            fcr0 = d_fc[((size_t)b*8 + 2*kp2 + 0)*HWn + j0n + j];
            fcr1 = d_fc[((size_t)b*8 + 2*kp2 + 1)*HWn + j0n + j];
#pragma unroll
            for (int q = 0; q < 8; q++) {
                int idx = t + q*256;
                int c = idx >> 5, jp = idx & 31;
                fdr[q] = *(const uint32_t*)&d_fdh[((size_t)b*64 + c)*HWn + j0n + jp*2];
            }
        }
        // energy mma (fp16 single product)
        float e[8][4];
#pragma unroll
        for (int ng = 0; ng < 8; ng++)
#pragma unroll
            for (int q = 0; q < 4; q++) e[ng][q] = 0.f;
#pragma unroll
        for (int jg = 0; jg < 4; jg++) {
            uint32_t baddr = fcb + buf*3072 + (uint32_t)(jg*16 + (lane & 15))*48 + (lane >> 4)*16;
            uint32_t bh[4];
            ldsm_x4(bh[0], bh[1], bh[2], bh[3], baddr);
            mma_f16s(e[2*jg],   af, bh[0], bh[2]);
            mma_f16s(e[2*jg+1], af, bh[1], bh[3]);
        }
        // online row max (quad shfl) + register rescale
        float tm1 = -1e30f, tm2 = -1e30f;
#pragma unroll
        for (int ng = 0; ng < 8; ng++) {
            tm1 = fmaxf(tm1, fmaxf(e[ng][0], e[ng][1]));
            tm2 = fmaxf(tm2, fmaxf(e[ng][2], e[ng][3]));
        }
        tm1 = fmaxf(tm1, __shfl_xor_sync(0xffffffffu, tm1, 1));
        tm1 = fmaxf(tm1, __shfl_xor_sync(0xffffffffu, tm1, 2));
        tm2 = fmaxf(tm2, __shfl_xor_sync(0xffffffffu, tm2, 1));
        tm2 = fmaxf(tm2, __shfl_xor_sync(0xffffffffu, tm2, 2));
        float mn1 = fmaxf(m1, tm1), mn2 = fmaxf(m2, tm2);
        float sc1 = ex2f(m1 - mn1), sc2 = ex2f(m2 - mn2);
        m1 = mn1; m2 = mn2;
        z1 *= sc1; z2 *= sc2;
#pragma unroll
        for (int ng = 0; ng < 8; ng++) {
            acc[ng][0] *= sc1; acc[ng][1] *= sc1;
            acc[ng][2] *= sc2; acc[ng][3] *= sc2;
        }
        // exp via ex2.f16x2 -> p fragments
        uint32_t afr[4][4];
#pragma unroll
        for (int ng = 0; ng < 8; ng++) {
            uint32_t a01 = cvt_f16x2(e[ng][0] - mn1, e[ng][1] - mn1);
            uint32_t a23 = cvt_f16x2(e[ng][2] - mn2, e[ng][3] - mn2);
            uint32_t p01 = ex2h2(a01);
            uint32_t p23 = ex2h2(a23);
            int kp = ng >> 1;
            if ((ng & 1) == 0) { afr[kp][0] = p01; afr[kp][1] = p23; }
            else               { afr[kp][2] = p01; afr[kp][3] = p23; }
        }
        // z partial via HADD2 tree
        {
            uint32_t s1 = hadd2u(hadd2u(hadd2u(afr[0][0], afr[0][2]), hadd2u(afr[1][0], afr[1][2])),
                                 hadd2u(hadd2u(afr[2][0], afr[2][2]), hadd2u(afr[3][0], afr[3][2])));
            uint32_t s2 = hadd2u(hadd2u(hadd2u(afr[0][1], afr[0][3]), hadd2u(afr[1][1], afr[1][3])),
                                 hadd2u(hadd2u(afr[2][1], afr[2][3]), hadd2u(afr[3][1], afr[3][3])));
            float2 f1 = __half22float2(*(__half2*)&s1);
            float2 f2 = __half22float2(*(__half2*)&s2);
            z1 += f1.x + f1.y;
            z2 += f2.x + f2.y;
        }
        // accumulate mma (fp16)
#pragma unroll
        for (int ng2 = 0; ng2 < 4; ng2++) {
#pragma unroll
            for (int kp = 0; kp < 4; kp++) {
                uint32_t off = fdrow + (uint32_t)(ng2*2048 + kp*32);
                uint32_t f4[4];
                ldsm_x4(f4[0], f4[1], f4[2], f4[3], sbase + buf*8192 + SWZ(off));
                mma_f16s(acc[2*ng2],   afr[kp], f4[0], f4[2]);
                mma_f16s(acc[2*ng2+1], afr[kp], f4[1], f4[3]);
            }
        }
    }
    // ---- z reduction across the quad; leaders write z_s directly ----
    z1 += __shfl_xor_sync(0xffffffffu, z1, 1);
    z1 += __shfl_xor_sync(0xffffffffu, z1, 2);
    z2 += __shfl_xor_sync(0xffffffffu, z2, 1);
    z2 += __shfl_xor_sync(0xffffffffu, z2, 2);
    if (tc == 0) {
        z_s[i1] = alpha_p[0] / z1;
        z_s[i2] = alpha_p[0] / z2;
    }
    __syncthreads();   // fences mainloop smem reads + z_s writes
    // ---- load psi tile / att / wp ----
    for (int idx = t; idx < 8192; idx += 256) {
        int c = idx >> 7, p = idx & 127;
        psi_s[c*132 + p] = d_psi[((size_t)b*Cn + c)*HWn + I0 + p];
    }
    for (int idx = t; idx < 4096; idx += 256)
        att_s[(idx >> 6)*65 + (idx & 63)] = d_att[b*4096 + idx];
    if (t < 64) wp_s[t] = d_wp[t];
    __syncthreads();
    // ---- CAM softmax -> W2_s[c][66] (4 threads per row) ----
    {
        int r = t >> 2, q4 = t & 3;
        float v[16];
#pragma unroll
        for (int k = 0; k < 16; k++) v[k] = att_s[r*65 + q4*16 + k];
        float mx = -1e30f, mn = 1e30f;
#pragma unroll
        for (int k = 0; k < 16; k++) { mx = fmaxf(mx, v[k]); mn = fminf(mn, v[k]); }
        mx = fmaxf(mx, __shfl_xor_sync(0xffffffffu, mx, 1));
        mx = fmaxf(mx, __shfl_xor_sync(0xffffffffu, mx, 2));
        mn = fminf(mn, __shfl_xor_sync(0xffffffffu, mn, 1));
        mn = fminf(mn, __shfl_xor_sync(0xffffffffu, mn, 2));
        float m2r = mx - mn;
        float ssum = 0.f;
#pragma unroll
        for (int k = 0; k < 16; k++) { float ev = __expf((mx - v[k]) - m2r); v[k] = ev; ssum += ev; }
        ssum += __shfl_xor_sync(0xffffffffu, ssum, 1);
        ssum += __shfl_xor_sync(0xffffffffu, ssum, 2);
        float scale = beta_p[0] * wp_s[r] / ssum;
#pragma unroll
        for (int k = 0; k < 16; k++) W2_s[r*66 + q4*16 + k] = v[k] * scale;
    }
    // ---- fragments -> pam_s[c][i] ----
    {
        float zz1 = z_s[i1], zz2 = z_s[i2];
#pragma unroll
        for (int ng = 0; ng < 8; ng++) {
            int c = ng*8 + 2*tc;
            pam_s[c*132 + i1]     = acc[ng][0]*zz1 + psi_s[c*132 + i1];
            pam_s[(c+1)*132 + i1] = acc[ng][1]*zz1 + psi_s[(c+1)*132 + i1];
            pam_s[c*132 + i2]     = acc[ng][2]*zz2 + psi_s[c*132 + i2];
            pam_s[(c+1)*132 + i2] = acc[ng][3]*zz2 + psi_s[(c+1)*132 + i2];
        }
    }
    __syncthreads();
    // ---- fused CAM + gate ----
    {
        int p = t & 127, half = t >> 7;
        int c0 = half*32, d0 = half*32;
        float part1 = 0.f;
#pragma unroll 8
        for (int c = 0; c < 32; c++) {
            int cc = c0 + c;
            part1 += wp_s[cc] * psi_s[cc*132 + p] * pam_s[cc*132 + p];
        }
        ull v[16];
#pragma unroll
        for (int q = 0; q < 16; q++) v[q] = 0ull;
        for (int c = 0; c < 64; c++) {
            float pm = pam_s[c*132 + p];
            ull pm2 = pk2(pm, pm);
            const ull* wr = (const ull*)&W2_s[c*66 + d0];
#pragma unroll
            for (int q = 0; q < 16; q++) v[q] = ffma2(pm2, wr[q], v[q]);
        }
        float part2 = 0.f;
#pragma unroll
        for (int q = 0; q < 16; q++) {
            float v0, v1; upk2(v[q], v0, v1);
            part2 += psi_s[(d0+2*q)*132 + p]*v0 + psi_s[(d0+2*q+1)*132 + p]*v1;
        }
        gred[half*128 + p] = part1 + part2;
    }
    __syncthreads();
    if (t < 128) {
        float gate = d_bp[0] + gred[t] + gred[128 + t];
        z_s[t] = 1.f / (1.f + __expf(-gate));   // da
    }
    __syncthreads();
    // ---- fused final multiply ----
    {
        int p = t & 127, hb = t >> 7;
        float da = z_s[p];
        const float* xp = x + ((size_t)b*256)*HWn + I0 + p;
        float* op = out + ((size_t)b*256)*HWn + I0 + p;
#pragma unroll 8
        for (int c = hb; c < 256; c += 2)
            op[(size_t)c*HWn] = xp[(size_t)c*HWn] * da;
    }
}

// ---------------- launch ----------------
extern "C" void kernel_launch(void* const* d_in, const int* in_sizes, int n_in,
                              void* d_out, int out_size) {
    const float* g = (const float*)d_in[0];
    const float* x = (const float*)d_in[1];

    cudaFuncSetAttribute(k_psi2, cudaFuncAttributeMaxDynamicSharedMemorySize, 82176);
    cudaFuncSetAttribute(k_pam3, cudaFuncAttributeMaxDynamicSharedMemorySize, 102912);

    k_prep<<<dim3(64, 4), 64>>>((const float*)d_in[2],  (const float*)d_in[3],  (const float*)d_in[4],
                        (const float*)d_in[5],  (const float*)d_in[6],  (const float*)d_in[7],
                        (const float*)d_in[8],  (const float*)d_in[9],  (const float*)d_in[10],
                        (const float*)d_in[11], (const float*)d_in[12], (const float*)d_in[13],
                        (const float*)d_in[14], (const float*)d_in[15], (const float*)d_in[16],
                        (const float*)d_in[17], (const float*)d_in[18], (const float*)d_in[19]);

    k_psi2<<<dim3(32, 8), 256, 82176>>>(g, x,
        (const float*)d_in[20], (const float*)d_in[21],
        (const float*)d_in[22], (const float*)d_in[23],
        (const float*)d_in[24], (const float*)d_in[25]);

    k_pam3<<<dim3(32, 8), 256, 102912>>>((const float*)d_in[26], (const float*)d_in[27],
                                         x, (float*)d_out);
}

// round 12
// speedup vs baseline: 5.8337x; 1.0454x over previous
#include <cuda_runtime.h>
#include <cuda_bf16.h>
#include <cuda_fp16.h>
#include <math.h>
#include <stdint.h>

typedef unsigned long long ull;

#define Bn 8
#define Cn 64
#define HWn 4096
#define LOG2E 1.4426950408889634f

// ---------------- scratch (device globals; no allocs allowed) ----------------
__device__ __align__(16) float d_psi[Bn*Cn*HWn];     // 8MB
__device__ __align__(16) float d_fb [Bn*8*HWn];      // pre-scaled by log2(e)
__device__ __align__(16) float d_fc [Bn*8*HWn];
__device__ __align__(16) __half d_fdh[Bn*Cn*HWn];    // 4MB fp16 [b][c][j]
__device__ __align__(16) float d_att[Bn*64*64];      // CAM gram (atomic-accumulated)
__device__ __align__(16) __nv_bfloat16 d_Wh[512*64]; // folded weight hi, [cin][out]
__device__ __align__(16) __nv_bfloat16 d_Wl[512*64]; // folded weight lo
__device__ __align__(16) float d_bias[64];
__device__ __align__(16) float d_wp[64];
__device__ __align__(16) float d_bp[1];

// ---------------- f32x2 helpers ----------------
__device__ __forceinline__ ull pk2(float lo, float hi) {
    ull r; asm("mov.b64 %0, {%1, %2};" : "=l"(r) : "f"(lo), "f"(hi)); return r;
}
__device__ __forceinline__ void upk2(ull v, float& lo, float& hi) {
    asm("mov.b64 {%0, %1}, %2;" : "=f"(lo), "=f"(hi) : "l"(v));
}
__device__ __forceinline__ ull ffma2(ull a, ull b, ull c) {
    ull d; asm("fma.rn.f32x2 %0, %1, %2, %3;" : "=l"(d) : "l"(a), "l"(b), "l"(c)); return d;
}
__device__ __forceinline__ float ex2f(float x) {
    float r; asm("ex2.approx.f32 %0, %1;" : "=f"(r) : "f"(x)); return r;
}

// ---------------- warp MMA helpers ----------------
__device__ __forceinline__ uint32_t smem_u32(const void* p) {
    uint32_t a;
    asm("{ .reg .u64 t; cvta.to.shared.u64 t, %1; cvt.u32.u64 %0, t; }" : "=r"(a) : "l"(p));
    return a;
}
#define SWZ(off) ((off) ^ (((off) >> 3) & 0x70))
__device__ __forceinline__ void ldsm_x4(uint32_t& r0, uint32_t& r1, uint32_t& r2, uint32_t& r3,
                                        uint32_t addr) {
    asm volatile("ldmatrix.sync.aligned.m8n8.x4.shared.b16 {%0,%1,%2,%3}, [%4];"
                 : "=r"(r0), "=r"(r1), "=r"(r2), "=r"(r3) : "r"(addr));
}
__device__ __forceinline__ void ldsm_x4t(uint32_t& r0, uint32_t& r1, uint32_t& r2, uint32_t& r3,
                                         uint32_t addr) {
    asm volatile("ldmatrix.sync.aligned.m8n8.x4.trans.shared.b16 {%0,%1,%2,%3}, [%4];"
                 : "=r"(r0), "=r"(r1), "=r"(r2), "=r"(r3) : "r"(addr));
}
__device__ __forceinline__ void mma_bf16(float* d, const uint32_t* a, const uint32_t* b) {
    asm volatile(
        "mma.sync.aligned.m16n8k16.row.col.f32.bf16.bf16.f32 "
        "{%0,%1,%2,%3}, {%4,%5,%6,%7}, {%8,%9}, {%0,%1,%2,%3};"
        : "+f"(d[0]), "+f"(d[1]), "+f"(d[2]), "+f"(d[3])
        : "r"(a[0]), "r"(a[1]), "r"(a[2]), "r"(a[3]), "r"(b[0]), "r"(b[1]));
}
__device__ __forceinline__ void mma_f16s(float* d, const uint32_t* a, uint32_t b0, uint32_t b1) {
    asm volatile(
        "mma.sync.aligned.m16n8k16.row.col.f32.f16.f16.f32 "
        "{%0,%1,%2,%3}, {%4,%5,%6,%7}, {%8,%9}, {%0,%1,%2,%3};"
        : "+f"(d[0]), "+f"(d[1]), "+f"(d[2]), "+f"(d[3])
        : "r"(a[0]), "r"(a[1]), "r"(a[2]), "r"(a[3]), "r"(b0), "r"(b1));
}
__device__ __forceinline__ uint32_t cvt_bf16x2(float a, float b) {
    uint32_t r;
    asm("cvt.rn.satfinite.bf16x2.f32 %0, %1, %2;" : "=r"(r) : "f"(b), "f"(a));
    return r;
}
__device__ __forceinline__ uint32_t cvt_f16x2(float a, float b) {
    // lower half = a, upper = b
    uint32_t r;
    asm("cvt.rn.f16x2.f32 %0, %1, %2;" : "=r"(r) : "f"(b), "f"(a));
    return r;
}
__device__ __forceinline__ uint32_t ex2h2(uint32_t a) {
    uint32_t r;
    asm("ex2.approx.f16x2 %0, %1;" : "=r"(r) : "r"(a));
    return r;
}
__device__ __forceinline__ uint32_t hadd2u(uint32_t a, uint32_t b) {
    uint32_t r;
    asm("add.rn.f16x2 %0, %1, %2;" : "=r"(r) : "r"(a), "r"(b));
    return r;
}

// ---------------- prep: coalesced-store remap (grid 128 x 256) ----------------
__global__ void __launch_bounds__(256) k_prep(
                       const float* Wg_w, const float* Wg_b, const float* gg, const float* gb,
                       const float* gm, const float* gv,
                       const float* Wx_w, const float* Wx_b, const float* xg, const float* xb,
                       const float* xm, const float* xv,
                       const float* psi_w, const float* psi_b, const float* pg, const float* pbt,
                       const float* pm, const float* pv) {
    int t = threadIdx.x;
    int r = blockIdx.x*4 + (t >> 6);   // 0..511 output row of d_Wh
    int o = t & 63;
    int set = r >> 8;                  // 0: g-weights, 1: x-weights
    int cin = r & 255;
    const float* Ww = set ? Wx_w : Wg_w;
    float inv = set ? (xg[o] * rsqrtf(xv[o] + 1e-5f))
                    : (gg[o] * rsqrtf(gv[o] + 1e-5f));
    float v = Ww[o*256 + cin] * inv;
    __nv_bfloat16 h = __float2bfloat16(v);
    d_Wh[r*64 + o] = h;                              // coalesced per 64-thread group
    d_Wl[r*64 + o] = __float2bfloat16(v - __bfloat162float(h));
    d_att[blockIdx.x*256 + t] = 0.f;                 // 128*256 = 32768
    if (r == 0) {   // block 0, first 64 threads
        float invg = gg[o] * rsqrtf(gv[o] + 1e-5f);
        float invx = xg[o] * rsqrtf(xv[o] + 1e-5f);
        d_bias[o] = (Wg_b[o] - gm[o]) * invg + gb[o]
                  + (Wx_b[o] - xm[o]) * invx + xb[o];
        float invp = pg[0] * rsqrtf(pv[0] + 1e-5f);
        d_wp[o] = psi_w[o] * invp;
        if (o == 0) d_bp[0] = (psi_b[0] - pm[0]) * invp + pbt[0];
    }
}

// ---------------- psi via bf16-split HMMA + fused fb/fc/fd convs + CAM gram ----------------
__global__ void __launch_bounds__(256) k_psi2(const float* __restrict__ g, const float* __restrict__ x,
                                              const float* __restrict__ pb_w, const float* __restrict__ pb_b,
                                              const float* __restrict__ pc_w, const float* __restrict__ pc_b,
                                              const float* __restrict__ pd_w, const float* __restrict__ pd_b) {
    extern __shared__ __align__(1024) char ps[];
    uint32_t base = smem_u32(ps);
    uint32_t ahi = base, whi = base + 32768;
    float* f32s   = (float*)(ps + 49152);
    float* bias_s = (float*)(ps + 81920);
    float* psi_t  = (float*)ps;
    float* cw_s   = (float*)(ps + 33024);
    float* cbias  = (float*)(ps + 53504);

    int b = blockIdx.y, p0 = blockIdx.x*128, t = threadIdx.x;
    int w = t >> 5, lane = t & 31;
    if (t < 64) bias_s[t] = d_bias[t];

    float dfr[8][4];
#pragma unroll
    for (int nf = 0; nf < 8; nf++)
#pragma unroll
        for (int q = 0; q < 4; q++) dfr[nf][q] = 0.f;

    int r7 = lane & 7;
    int hsel = lane >> 4;
    uint32_t a_row = ahi + (uint32_t)(w*16 + (lane & 15))*128;
    uint32_t b_row = whi + (uint32_t)((((lane >> 3) & 1)*8 + r7))*128;

    for (int cb = 0; cb < 8; cb++) {
        __syncthreads();
        {
            const float* src = (cb < 4) ? g + ((size_t)b*256 + cb*64)*HWn
                                        : x + ((size_t)b*256 + (cb-4)*64)*HWn;
#pragma unroll
            for (int i = 0; i < 8; i++) {
                int idx = t + i*256;
                int c = idx >> 5, p4 = idx & 31;
                float4 v = *(const float4*)&src[(size_t)c*HWn + p0 + p4*4];
                *(float4*)&f32s[c*128 + p4*4] = v;
            }
        }
        {
#pragma unroll
            for (int q = 0; q < 2; q++) {
                int qi = t + q*256;
                int row = qi >> 3, qq = qi & 7;
                uint32_t so = SWZ((uint32_t)(row*128 + qq*16));
                *(uint4*)(ps + 32768 + so) =
                    *(const uint4*)((const char*)d_Wh + (size_t)(cb*64+row)*128 + qq*16);
                *(uint4*)(ps + 40960 + so) =
                    *(const uint4*)((const char*)d_Wl + (size_t)(cb*64+row)*128 + qq*16);
            }
        }
        __syncthreads();
        {
            int p = t & 127, half = t >> 7;
#pragma unroll
            for (int oct = 0; oct < 4; oct++) {
                int c0 = half*32 + oct*8;
                float v[8];
#pragma unroll
                for (int j = 0; j < 8; j++) v[j] = f32s[(c0+j)*128 + p];
                uint32_t uh[4], ul[4];
#pragma unroll
                for (int j = 0; j < 4; j++) {
                    uint32_t h = cvt_bf16x2(v[2*j], v[2*j+1]);
                    float h0 = __uint_as_float(h << 16);
                    float h1 = __uint_as_float(h & 0xffff0000u);
                    uh[j] = h;
                    ul[j] = cvt_bf16x2(v[2*j] - h0, v[2*j+1] - h1);
                }
                uint32_t so = SWZ((uint32_t)(p*128 + c0*2));
                *(uint4*)(ps + so)         = make_uint4(uh[0], uh[1], uh[2], uh[3]);
                *(uint4*)(ps + 16384 + so) = make_uint4(ul[0], ul[1], ul[2], ul[3]);
            }
        }
        __syncthreads();
        uint32_t afh[4][4], afl[4][4];
#pragma unroll
        for (int ks = 0; ks < 4; ks++) {
            uint32_t aq = (uint32_t)(((2*ks + hsel) ^ r7) * 16);
            ldsm_x4(afh[ks][0], afh[ks][1], afh[ks][2], afh[ks][3], a_row + aq);
            ldsm_x4(afl[ks][0], afl[ks][1], afl[ks][2], afl[ks][3], a_row + 16384 + aq);
        }
#pragma unroll
        for (int ks = 0; ks < 4; ks++) {
#pragma unroll
            for (int nn = 0; nn < 4; nn++) {
                uint32_t bq = (uint32_t)(((2*nn + hsel) ^ r7) * 16);
                uint32_t baddr = b_row + ks*2048 + bq;
                uint32_t bh[4], bl[4];
                ldsm_x4t(bh[0], bh[1], bh[2], bh[3], baddr);
                ldsm_x4t(bl[0], bl[1], bl[2], bl[3], baddr + 8192);
                mma_bf16(dfr[2*nn],   afh[ks], bh);
                mma_bf16(dfr[2*nn],   afh[ks], bl);
                mma_bf16(dfr[2*nn],   afl[ks], bh);
                mma_bf16(dfr[2*nn+1], afh[ks], bh + 2);
                mma_bf16(dfr[2*nn+1], afh[ks], bl + 2);
                mma_bf16(dfr[2*nn+1], afl[ks], bh + 2);
            }
        }
    }
    __syncthreads();
    // ---- epilogue 1: fragments -> psi_t [c][129], stage conv weights ----
    {
        int gr = lane >> 2, tc = lane & 3;
        int i1 = w*16 + gr, i2 = i1 + 8;
#pragma unroll
        for (int nf = 0; nf < 8; nf++) {
            int c0 = nf*8 + 2*tc;
            float b0 = bias_s[c0], b1 = bias_s[c0+1];
            psi_t[c0*129 + i1]     = fmaxf(dfr[nf][0] + b0, 0.f);
            psi_t[(c0+1)*129 + i1] = fmaxf(dfr[nf][1] + b1, 0.f);
            psi_t[c0*129 + i2]     = fmaxf(dfr[nf][2] + b0, 0.f);
            psi_t[(c0+1)*129 + i2] = fmaxf(dfr[nf][3] + b1, 0.f);
        }
    }
    for (int idx = t; idx < 5120; idx += 256) {
        int c = idx / 80, o = idx % 80;
        float wv;
        if (o < 8)       wv = pb_w[o*64 + c];
        else if (o < 16) wv = pc_w[(o-8)*64 + c];
        else             wv = pd_w[(o-16)*64 + c];
        cw_s[idx] = wv;
    }
    if (t < 80) cbias[t] = (t < 8) ? pb_b[t] : (t < 16 ? pc_b[t-8] : pd_b[t-16]);
    __syncthreads();
    // ---- epilogue 2: store psi, fb/fc/fd convs, CAM gram atomics ----
    for (int idx = t; idx < 8192; idx += 256) {
        int c = idx >> 7, p = idx & 127;
        d_psi[((size_t)b*Cn + c)*HWn + p0 + p] = psi_t[c*129 + p];
    }
    {
        int pos = t & 127, half = t >> 7;
        int o0 = half*40;
        ull acc[20];
#pragma unroll
        for (int q = 0; q < 20; q++) acc[q] = pk2(cbias[o0 + 2*q], cbias[o0 + 2*q + 1]);
        for (int c = 0; c < 64; c++) {
            float v = psi_t[c*129 + pos];
            ull v2 = pk2(v, v);
            const ull* wr = (const ull*)&cw_s[c*80 + o0];
#pragma unroll
            for (int q = 0; q < 20; q++) acc[q] = ffma2(v2, wr[q], acc[q]);
        }
#pragma unroll
        for (int q = 0; q < 20; q++) {
            float v0, v1; upk2(acc[q], v0, v1);
            int o = o0 + 2*q;
#pragma unroll
            for (int s = 0; s < 2; s++) {
                float v = s ? v1 : v0;
                int oo = o + s;
                if (oo < 8)       d_fb[((size_t)b*8 + oo)*HWn + p0 + pos] = v * LOG2E;
                else if (oo < 16) d_fc[((size_t)b*8 + (oo-8))*HWn + p0 + pos] = v;
                else              d_fdh[((size_t)b*64 + (oo-16))*HWn + p0 + pos] = __float2half(v);
            }
        }
    }
    {
        int cjg = t & 15, cig = t >> 4;
        float ga[4][4];
#pragma unroll
        for (int r = 0; r < 4; r++)
#pragma unroll
            for (int q = 0; q < 4; q++) ga[r][q] = 0.f;
        for (int p = 0; p < 128; p++) {
            float a0 = psi_t[(cig*4+0)*129 + p];
            float a1 = psi_t[(cig*4+1)*129 + p];
            float a2 = psi_t[(cig*4+2)*129 + p];
            float a3 = psi_t[(cig*4+3)*129 + p];
            float b0 = psi_t[(cjg*4+0)*129 + p];
            float b1 = psi_t[(cjg*4+1)*129 + p];
            float b2 = psi_t[(cjg*4+2)*129 + p];
            float b3 = psi_t[(cjg*4+3)*129 + p];
            ga[0][0]+=a0*b0; ga[0][1]+=a0*b1; ga[0][2]+=a0*b2; ga[0][3]+=a0*b3;
            ga[1][0]+=a1*b0; ga[1][1]+=a1*b1; ga[1][2]+=a1*b2; ga[1][3]+=a1*b3;
            ga[2][0]+=a2*b0; ga[2][1]+=a2*b1; ga[2][2]+=a2*b2; ga[2][3]+=a2*b3;
            ga[3][0]+=a3*b0; ga[3][1]+=a3*b1; ga[3][2]+=a3*b2; ga[3][3]+=a3*b3;
        }
#pragma unroll
        for (int r = 0; r < 4; r++)
#pragma unroll
            for (int q = 0; q < 4; q++)
                atomicAdd(&d_att[(b*64 + cig*4 + r)*64 + cjg*4 + q], ga[r][q]);
    }
}

// ---------------- PAM + CAM softmax + gate + final multiply ----------------
__global__ void __launch_bounds__(256, 2) k_pam3(const float* __restrict__ alpha_p,
                                                 const float* __restrict__ beta_p,
                                                 const float* __restrict__ x,
                                                 float* __restrict__ out) {
    extern __shared__ __align__(1024) char dsm[];
    // epilogue union
    float* psi_s = (float*)dsm;               // 64*132 f      0..33792
    float* pam_s = (float*)(dsm + 33792);     // 64*132 f      ..67584
    float* W2_s  = (float*)(dsm + 67584);     // 64*66 f       ..84480
    float* wp_s  = (float*)(dsm + 84480);     // 64 f          ..84736
    float* gred  = (float*)(dsm + 84736);     // 256 f         ..85760
    float* z_s   = (float*)(dsm + 85760);     // 128 f         ..86272
    float* att_s = (float*)(dsm + 86272);     // 64*65 f       ..102912

    uint32_t sbase = smem_u32(dsm);
    uint32_t fbb   = sbase + 16384;
    uint32_t fcb   = sbase + 22528;

    int b = blockIdx.y, I0 = blockIdx.x*128, t = threadIdx.x;
    int w = t >> 5, lane = t & 31;
    int gr = lane >> 2, tc = lane & 3;
    int i1 = w*16 + gr, i2 = i1 + 8;

    for (int idx = t; idx < 1024; idx += 256) {
        char* p;
        if (idx < 512) p = dsm + 16384 + (idx>>2)*48 + 16 + (idx&3)*4;
        else { int r = idx - 512; p = dsm + 22528 + (r>>2)*48 + 16 + (r&3)*4; }
        *(uint32_t*)p = 0u;
    }
    {
        int i = t & 127, half = t >> 7;
        float v0 = d_fb[((size_t)b*8 + half*4 + 0)*HWn + I0 + i];
        float v1 = d_fb[((size_t)b*8 + half*4 + 1)*HWn + I0 + i];
        float v2 = d_fb[((size_t)b*8 + half*4 + 2)*HWn + I0 + i];
        float v3 = d_fb[((size_t)b*8 + half*4 + 3)*HWn + I0 + i];
        *(uint32_t*)(dsm + 16384 + i*48 + half*8)     = cvt_f16x2(v0, v1);
        *(uint32_t*)(dsm + 16384 + i*48 + half*8 + 4) = cvt_f16x2(v2, v3);
    }
    __syncthreads();

    uint32_t af[4];
    {
        uint32_t aaddr = fbb + (uint32_t)(w*16 + (lane & 15))*48 + (lane >> 4)*16;
        ldsm_x4(af[0], af[1], af[2], af[3], aaddr);
    }

    float acc[8][4];
#pragma unroll
    for (int ng = 0; ng < 8; ng++)
#pragma unroll
        for (int q = 0; q < 4; q++) acc[ng][q] = 0.f;
    float z1 = 0.f, z2 = 0.f;
    float m1 = -1e30f, m2 = -1e30f;

    float fcr0, fcr1;
    uint32_t fdr[8];
    {
        int j = t & 63, kp2 = t >> 6;
        fcr0 = d_fc[((size_t)b*8 + 2*kp2 + 0)*HWn + j];
        fcr1 = d_fc[((size_t)b*8 + 2*kp2 + 1)*HWn + j];
#pragma unroll
        for (int q = 0; q < 8; q++) {
            int idx = t + q*256;
            int c = idx >> 5, jp = idx & 31;
            fdr[q] = *(const uint32_t*)&d_fdh[((size_t)b*64 + c)*HWn + jp*2];
        }
    }

    uint32_t fdrow = (uint32_t)(lane & 15)*128 + (uint32_t)(lane >> 4)*16;

    for (int jt = 0; jt < 64; jt++) {
        uint32_t buf = (uint32_t)(jt & 1);
        {
            int j = t & 63, kp2 = t >> 6;
            *(uint32_t*)(dsm + 22528 + buf*3072 + j*48 + kp2*4) = cvt_f16x2(fcr0, fcr1);
        }
#pragma unroll
        for (int q = 0; q < 8; q++) {
            int idx = t + q*256;
            int c = idx >> 5, jp = idx & 31;
            *(uint32_t*)(dsm + buf*8192 + SWZ((uint32_t)(c*128 + jp*4))) = fdr[q];
        }
        __syncthreads();
        if (jt < 63) {
            int j0n = (jt+1)*64;
            int j = t & 63, kp2 = t >> 6;
            fcr0 = d_fc[((size_t)b*8 + 2*kp2 + 0)*HWn + j0n + j];
            fcr1 = d_fc[((size_t)b*8 + 2*kp2 + 1)*HWn + j0n + j];
#pragma unroll
            for (int q = 0; q < 8; q++) {
                int idx = t + q*256;
                int c = idx >> 5, jp = idx & 31;
                fdr[q] = *(const uint32_t*)&d_fdh[((size_t)b*64 + c)*HWn + j0n + jp*2];
            }
        }
        // energy mma (fp16 single product)
        float e[8][4];
#pragma unroll
        for (int ng = 0; ng < 8; ng++)
#pragma unroll
            for (int q = 0; q < 4; q++) e[ng][q] = 0.f;
#pragma unroll
        for (int jg = 0; jg < 4; jg++) {
            uint32_t baddr = fcb + buf*3072 + (uint32_t)(jg*16 + (lane & 15))*48 + (lane >> 4)*16;
            uint32_t bh[4];
            ldsm_x4(bh[0], bh[1], bh[2], bh[3], baddr);
            mma_f16s(e[2*jg],   af, bh[0], bh[2]);
            mma_f16s(e[2*jg+1], af, bh[1], bh[3]);
        }
        // online row max (quad shfl); rescale only when some row max moved (warp vote)
        float tm1 = -1e30f, tm2 = -1e30f;
#pragma unroll
        for (int ng = 0; ng < 8; ng++) {
            tm1 = fmaxf(tm1, fmaxf(e[ng][0], e[ng][1]));
            tm2 = fmaxf(tm2, fmaxf(e[ng][2], e[ng][3]));
        }
        tm1 = fmaxf(tm1, __shfl_xor_sync(0xffffffffu, tm1, 1));
        tm1 = fmaxf(tm1, __shfl_xor_sync(0xffffffffu, tm1, 2));
        tm2 = fmaxf(tm2, __shfl_xor_sync(0xffffffffu, tm2, 1));
        tm2 = fmaxf(tm2, __shfl_xor_sync(0xffffffffu, tm2, 2));
        float mn1 = fmaxf(m1, tm1), mn2 = fmaxf(m2, tm2);
        if (__any_sync(0xffffffffu, (mn1 > m1) || (mn2 > m2))) {
            float sc1 = ex2f(m1 - mn1), sc2 = ex2f(m2 - mn2);
            m1 = mn1; m2 = mn2;
            z1 *= sc1; z2 *= sc2;
#pragma unroll
            for (int ng = 0; ng < 8; ng++) {
                acc[ng][0] *= sc1; acc[ng][1] *= sc1;
                acc[ng][2] *= sc2; acc[ng][3] *= sc2;
            }
        }
        // exp via ex2.f16x2 -> p fragments
        uint32_t afr[4][4];
#pragma unroll
        for (int ng = 0; ng < 8; ng++) {
            uint32_t a01 = cvt_f16x2(e[ng][0] - m1, e[ng][1] - m1);
            uint32_t a23 = cvt_f16x2(e[ng][2] - m2, e[ng][3] - m2);
            uint32_t p01 = ex2h2(a01);
            uint32_t p23 = ex2h2(a23);
            int kp = ng >> 1;
            if ((ng & 1) == 0) { afr[kp][0] = p01; afr[kp][1] = p23; }
            else               { afr[kp][2] = p01; afr[kp][3] = p23; }
        }
        // z partial via HADD2 tree
        {
            uint32_t s1 = hadd2u(hadd2u(hadd2u(afr[0][0], afr[0][2]), hadd2u(afr[1][0], afr[1][2])),
                                 hadd2u(hadd2u(afr[2][0], afr[2][2]), hadd2u(afr[3][0], afr[3][2])));
            uint32_t s2 = hadd2u(hadd2u(hadd2u(afr[0][1], afr[0][3]), hadd2u(afr[1][1], afr[1][3])),
                                 hadd2u(hadd2u(afr[2][1], afr[2][3]), hadd2u(afr[3][1], afr[3][3])));
            float2 f1 = __half22float2(*(__half2*)&s1);
            float2 f2 = __half22float2(*(__half2*)&s2);
            z1 += f1.x + f1.y;
            z2 += f2.x + f2.y;
        }
        // accumulate mma (fp16)
#pragma unroll
        for (int ng2 = 0; ng2 < 4; ng2++) {
#pragma unroll
            for (int kp = 0; kp < 4; kp++) {
                uint32_t off = fdrow + (uint32_t)(ng2*2048 + kp*32);
                uint32_t f4[4];
                ldsm_x4(f4[0], f4[1], f4[2], f4[3], sbase + buf*8192 + SWZ(off));
                mma_f16s(acc[2*ng2],   afr[kp], f4[0], f4[2]);
                mma_f16s(acc[2*ng2+1], afr[kp], f4[1], f4[3]);
            }
        }
    }
    // ---- z reduction across the quad; leaders write z_s directly ----
    z1 += __shfl_xor_sync(0xffffffffu, z1, 1);
    z1 += __shfl_xor_sync(0xffffffffu, z1, 2);
    z2 += __shfl_xor_sync(0xffffffffu, z2, 1);
    z2 += __shfl_xor_sync(0xffffffffu, z2, 2);
    if (tc == 0) {
        z_s[i1] = alpha_p[0] / z1;
        z_s[i2] = alpha_p[0] / z2;
    }
    __syncthreads();
    // ---- load psi tile / att / wp ----
    for (int idx = t; idx < 8192; idx += 256) {
        int c = idx >> 7, p = idx & 127;
        psi_s[c*132 + p] = d_psi[((size_t)b*Cn + c)*HWn + I0 + p];
    }
    for (int idx = t; idx < 4096; idx += 256)
        att_s[(idx >> 6)*65 + (idx & 63)] = d_att[b*4096 + idx];
    if (t < 64) wp_s[t] = d_wp[t];
    __syncthreads();
    // ---- CAM softmax -> W2_s[c][66] (4 threads per row) ----
    {
        int r = t >> 2, q4 = t & 3;
        float v[16];
#pragma unroll
        for (int k = 0; k < 16; k++) v[k] = att_s[r*65 + q4*16 + k];
        float mx = -1e30f, mn = 1e30f;
#pragma unroll
        for (int k = 0; k < 16; k++) { mx = fmaxf(mx, v[k]); mn = fminf(mn, v[k]); }
        mx = fmaxf(mx, __shfl_xor_sync(0xffffffffu, mx, 1));
        mx = fmaxf(mx, __shfl_xor_sync(0xffffffffu, mx, 2));
        mn = fminf(mn, __shfl_xor_sync(0xffffffffu, mn, 1));
        mn = fminf(mn, __shfl_xor_sync(0xffffffffu, mn, 2));
        float m2r = mx - mn;
        float ssum = 0.f;
#pragma unroll
        for (int k = 0; k < 16; k++) { float ev = __expf((mx - v[k]) - m2r); v[k] = ev; ssum += ev; }
        ssum += __shfl_xor_sync(0xffffffffu, ssum, 1);
        ssum += __shfl_xor_sync(0xffffffffu, ssum, 2);
        float scale = beta_p[0] * wp_s[r] / ssum;
#pragma unroll
        for (int k = 0; k < 16; k++) W2_s[r*66 + q4*16 + k] = v[k] * scale;
    }
    // ---- fragments -> pam_s[c][i] ----
    {
        float zz1 = z_s[i1], zz2 = z_s[i2];
#pragma unroll
        for (int ng = 0; ng < 8; ng++) {
            int c = ng*8 + 2*tc;
            pam_s[c*132 + i1]     = acc[ng][0]*zz1 + psi_s[c*132 + i1];
            pam_s[(c+1)*132 + i1] = acc[ng][1]*zz1 + psi_s[(c+1)*132 + i1];
            pam_s[c*132 + i2]     = acc[ng][2]*zz2 + psi_s[c*132 + i2];
            pam_s[(c+1)*132 + i2] = acc[ng][3]*zz2 + psi_s[(c+1)*132 + i2];
        }
    }
    __syncthreads();
    // ---- fused CAM + gate ----
    {
        int p = t & 127, half = t >> 7;
        int c0 = half*32, d0 = half*32;
        float part1 = 0.f;
#pragma unroll 8
        for (int c = 0; c < 32; c++) {
            int cc = c0 + c;
            part1 += wp_s[cc] * psi_s[cc*132 + p] * pam_s[cc*132 + p];
        }
        ull v[16];
#pragma unroll
        for (int q = 0; q < 16; q++) v[q] = 0ull;
        for (int c = 0; c < 64; c++) {
            float pm = pam_s[c*132 + p];
            ull pm2 = pk2(pm, pm);
            const ull* wr = (const ull*)&W2_s[c*66 + d0];
#pragma unroll
            for (int q = 0; q < 16; q++) v[q] = ffma2(pm2, wr[q], v[q]);
        }
        float part2 = 0.f;
#pragma unroll
        for (int q = 0; q < 16; q++) {
            float v0, v1; upk2(v[q], v0, v1);
            part2 += psi_s[(d0+2*q)*132 + p]*v0 + psi_s[(d0+2*q+1)*132 + p]*v1;
        }
        gred[half*128 + p] = part1 + part2;
    }
    __syncthreads();
    if (t < 128) {
        float gate = d_bp[0] + gred[t] + gred[128 + t];
        z_s[t] = 1.f / (1.f + __expf(-gate));   // da
    }
    __syncthreads();
    // ---- fused final multiply (float4 over positions) ----
    {
        int p4 = t & 31, c0 = t >> 5;           // 8 c-starts, stride 8
        float4 da = *(const float4*)&z_s[p4*4];
        const float* xp = x + ((size_t)b*256)*HWn + I0 + p4*4;
        float* op = out + ((size_t)b*256)*HWn + I0 + p4*4;
#pragma unroll 8
        for (int c = c0; c < 256; c += 8) {
            float4 v = *(const float4*)&xp[(size_t)c*HWn];
            v.x *= da.x; v.y *= da.y; v.z *= da.z; v.w *= da.w;
            *(float4*)&op[(size_t)c*HWn] = v;
        }
    }
}

// ---------------- launch ----------------
extern "C" void kernel_launch(void* const* d_in, const int* in_sizes, int n_in,
                              void* d_out, int out_size) {
    const float* g = (const float*)d_in[0];
    const float* x = (const float*)d_in[1];

    cudaFuncSetAttribute(k_psi2, cudaFuncAttributeMaxDynamicSharedMemorySize, 82176);
    cudaFuncSetAttribute(k_pam3, cudaFuncAttributeMaxDynamicSharedMemorySize, 102912);

    k_prep<<<128, 256>>>((const float*)d_in[2],  (const float*)d_in[3],  (const float*)d_in[4],
                        (const float*)d_in[5],  (const float*)d_in[6],  (const float*)d_in[7],
                        (const float*)d_in[8],  (const float*)d_in[9],  (const float*)d_in[10],
                        (const float*)d_in[11], (const float*)d_in[12], (const float*)d_in[13],
                        (const float*)d_in[14], (const float*)d_in[15], (const float*)d_in[16],
                        (const float*)d_in[17], (const float*)d_in[18], (const float*)d_in[19]);

    k_psi2<<<dim3(32, 8), 256, 82176>>>(g, x,
        (const float*)d_in[20], (const float*)d_in[21],
        (const float*)d_in[22], (const float*)d_in[23],
        (const float*)d_in[24], (const float*)d_in[25]);

    k_pam3<<<dim3(32, 8), 256, 102912>>>((const float*)d_in[26], (const float*)d_in[27],
                                         x, (float*)d_out);
}

// round 13
// speedup vs baseline: 6.2476x; 1.0710x over previous
#include <cuda_runtime.h>
#include <cuda_bf16.h>
#include <cuda_fp16.h>
#include <math.h>
#include <stdint.h>

typedef unsigned long long ull;

#define Bn 8
#define Cn 64
#define HWn 4096
#define LOG2E 1.4426950408889634f

// ---------------- scratch (device globals; no allocs allowed) ----------------
__device__ __align__(16) float d_psi[Bn*Cn*HWn];     // 8MB
__device__ __align__(16) float d_fb [Bn*8*HWn];      // pre-scaled by log2(e)
__device__ __align__(16) float d_fc [Bn*8*HWn];
__device__ __align__(16) char  d_fd2[Bn*64*8192];    // 4MB fp16, tile-major SWZ: [b][jt][SWZ(c*128+jp*4)]
__device__ __align__(16) float d_att[Bn*64*64];      // CAM gram (atomic-accumulated)
__device__ __align__(16) __nv_bfloat16 d_Wh[512*64]; // folded weight hi, [cin][out]
__device__ __align__(16) __nv_bfloat16 d_Wl[512*64]; // folded weight lo
__device__ __align__(16) float d_bias[64];
__device__ __align__(16) float d_wp[64];
__device__ __align__(16) float d_bp[1];

// ---------------- f32x2 helpers ----------------
__device__ __forceinline__ ull pk2(float lo, float hi) {
    ull r; asm("mov.b64 %0, {%1, %2};" : "=l"(r) : "f"(lo), "f"(hi)); return r;
}
__device__ __forceinline__ void upk2(ull v, float& lo, float& hi) {
    asm("mov.b64 {%0, %1}, %2;" : "=f"(lo), "=f"(hi) : "l"(v));
}
__device__ __forceinline__ ull ffma2(ull a, ull b, ull c) {
    ull d; asm("fma.rn.f32x2 %0, %1, %2, %3;" : "=l"(d) : "l"(a), "l"(b), "l"(c)); return d;
}
__device__ __forceinline__ float ex2f(float x) {
    float r; asm("ex2.approx.f32 %0, %1;" : "=f"(r) : "f"(x)); return r;
}

// ---------------- warp MMA helpers ----------------
__device__ __forceinline__ uint32_t smem_u32(const void* p) {
    uint32_t a;
    asm("{ .reg .u64 t; cvta.to.shared.u64 t, %1; cvt.u32.u64 %0, t; }" : "=r"(a) : "l"(p));
    return a;
}
#define SWZ(off) ((off) ^ (((off) >> 3) & 0x70))
__device__ __forceinline__ void ldsm_x4(uint32_t& r0, uint32_t& r1, uint32_t& r2, uint32_t& r3,
                                        uint32_t addr) {
    asm volatile("ldmatrix.sync.aligned.m8n8.x4.shared.b16 {%0,%1,%2,%3}, [%4];"
                 : "=r"(r0), "=r"(r1), "=r"(r2), "=r"(r3) : "r"(addr));
}
__device__ __forceinline__ void ldsm_x4t(uint32_t& r0, uint32_t& r1, uint32_t& r2, uint32_t& r3,
                                         uint32_t addr) {
    asm volatile("ldmatrix.sync.aligned.m8n8.x4.trans.shared.b16 {%0,%1,%2,%3}, [%4];"
                 : "=r"(r0), "=r"(r1), "=r"(r2), "=r"(r3) : "r"(addr));
}
__device__ __forceinline__ void mma_bf16(float* d, const uint32_t* a, const uint32_t* b) {
    asm volatile(
        "mma.sync.aligned.m16n8k16.row.col.f32.bf16.bf16.f32 "
        "{%0,%1,%2,%3}, {%4,%5,%6,%7}, {%8,%9}, {%0,%1,%2,%3};"
        : "+f"(d[0]), "+f"(d[1]), "+f"(d[2]), "+f"(d[3])
        : "r"(a[0]), "r"(a[1]), "r"(a[2]), "r"(a[3]), "r"(b[0]), "r"(b[1]));
}
__device__ __forceinline__ void mma_f16s(float* d, const uint32_t* a, uint32_t b0, uint32_t b1) {
    asm volatile(
        "mma.sync.aligned.m16n8k16.row.col.f32.f16.f16.f32 "
        "{%0,%1,%2,%3}, {%4,%5,%6,%7}, {%8,%9}, {%0,%1,%2,%3};"
        : "+f"(d[0]), "+f"(d[1]), "+f"(d[2]), "+f"(d[3])
        : "r"(a[0]), "r"(a[1]), "r"(a[2]), "r"(a[3]), "r"(b0), "r"(b1));
}
__device__ __forceinline__ uint32_t cvt_bf16x2(float a, float b) {
    uint32_t r;
    asm("cvt.rn.satfinite.bf16x2.f32 %0, %1, %2;" : "=r"(r) : "f"(b), "f"(a));
    return r;
}
__device__ __forceinline__ uint32_t cvt_f16x2(float a, float b) {
    // lower half = a, upper = b
    uint32_t r;
    asm("cvt.rn.f16x2.f32 %0, %1, %2;" : "=r"(r) : "f"(b), "f"(a));
    return r;
}
__device__ __forceinline__ uint32_t ex2h2(uint32_t a) {
    uint32_t r;
    asm("ex2.approx.f16x2 %0, %1;" : "=r"(r) : "r"(a));
    return r;
}
__device__ __forceinline__ uint32_t hadd2u(uint32_t a, uint32_t b) {
    uint32_t r;
    asm("add.rn.f16x2 %0, %1, %2;" : "=r"(r) : "r"(a), "r"(b));
    return r;
}

// ---------------- prep: coalesced stores + smem-cached BN factors ----------------
__global__ void __launch_bounds__(256) k_prep(
                       const float* Wg_w, const float* Wg_b, const float* gg, const float* gb,
                       const float* gm, const float* gv,
                       const float* Wx_w, const float* Wx_b, const float* xg, const float* xb,
                       const float* xm, const float* xv,
                       const float* psi_w, const float* psi_b, const float* pg, const float* pbt,
                       const float* pm, const float* pv) {
    __shared__ float invs[128];
    int t = threadIdx.x;
    if (t < 64)       invs[t] = gg[t] * rsqrtf(gv[t] + 1e-5f);
    else if (t < 128) invs[t] = xg[t-64] * rsqrtf(xv[t-64] + 1e-5f);
    __syncthreads();
    int r = blockIdx.x*4 + (t >> 6);   // 0..511 output row of d_Wh
    int o = t & 63;
    int set = r >> 8;                  // 0: g-weights, 1: x-weights
    int cin = r & 255;
    const float* Ww = set ? Wx_w : Wg_w;
    float v = Ww[o*256 + cin] * invs[set*64 + o];
    __nv_bfloat16 h = __float2bfloat16(v);
    d_Wh[r*64 + o] = h;
    d_Wl[r*64 + o] = __float2bfloat16(v - __bfloat162float(h));
    d_att[blockIdx.x*256 + t] = 0.f;
    if (r == 0) {
        d_bias[o] = (Wg_b[o] - gm[o]) * invs[o] + gb[o]
                  + (Wx_b[o] - xm[o]) * invs[64 + o] + xb[o];
        float invp = pg[0] * rsqrtf(pv[0] + 1e-5f);
        d_wp[o] = psi_w[o] * invp;
        if (o == 0) d_bp[0] = (psi_b[0] - pm[0]) * invp + pbt[0];
    }
}

// ---------------- psi via bf16-split HMMA + fused fb/fc/fd convs + CAM gram ----------------
__global__ void __launch_bounds__(256) k_psi2(const float* __restrict__ g, const float* __restrict__ x,
                                              const float* __restrict__ pb_w, const float* __restrict__ pb_b,
                                              const float* __restrict__ pc_w, const float* __restrict__ pc_b,
                                              const float* __restrict__ pd_w, const float* __restrict__ pd_b) {
    extern __shared__ __align__(1024) char ps[];
    uint32_t base = smem_u32(ps);
    uint32_t ahi = base, whi = base + 32768;
    float* f32s   = (float*)(ps + 49152);
    float* bias_s = (float*)(ps + 81920);
    // epilogue union: psi_t [64][129] f 0..33024 | cw_s 33024..53504 | cbias 53504..53824
    //                 fds (fp16 SWZ, 2 tiles) 54272..70656
    float* psi_t  = (float*)ps;
    float* cw_s   = (float*)(ps + 33024);
    float* cbias  = (float*)(ps + 53504);
    char*  fds    = ps + 54272;

    int b = blockIdx.y, p0 = blockIdx.x*128, t = threadIdx.x;
    int w = t >> 5, lane = t & 31;
    if (t < 64) bias_s[t] = d_bias[t];

    float dfr[8][4];
#pragma unroll
    for (int nf = 0; nf < 8; nf++)
#pragma unroll
        for (int q = 0; q < 4; q++) dfr[nf][q] = 0.f;

    int r7 = lane & 7;
    int hsel = lane >> 4;
    uint32_t a_row = ahi + (uint32_t)(w*16 + (lane & 15))*128;
    uint32_t b_row = whi + (uint32_t)((((lane >> 3) & 1)*8 + r7))*128;

    for (int cb = 0; cb < 8; cb++) {
        __syncthreads();
        {
            const float* src = (cb < 4) ? g + ((size_t)b*256 + cb*64)*HWn
                                        : x + ((size_t)b*256 + (cb-4)*64)*HWn;
#pragma unroll
            for (int i = 0; i < 8; i++) {
                int idx = t + i*256;
                int c = idx >> 5, p4 = idx & 31;
                float4 v = *(const float4*)&src[(size_t)c*HWn + p0 + p4*4];
                *(float4*)&f32s[c*128 + p4*4] = v;
            }
        }
        {
#pragma unroll
            for (int q = 0; q < 2; q++) {
                int qi = t + q*256;
                int row = qi >> 3, qq = qi & 7;
                uint32_t so = SWZ((uint32_t)(row*128 + qq*16));
                *(uint4*)(ps + 32768 + so) =
                    *(const uint4*)((const char*)d_Wh + (size_t)(cb*64+row)*128 + qq*16);
                *(uint4*)(ps + 40960 + so) =
                    *(const uint4*)((const char*)d_Wl + (size_t)(cb*64+row)*128 + qq*16);
            }
        }
        __syncthreads();
        {
            int p = t & 127, half = t >> 7;
#pragma unroll
            for (int oct = 0; oct < 4; oct++) {
                int c0 = half*32 + oct*8;
                float v[8];
#pragma unroll
                for (int j = 0; j < 8; j++) v[j] = f32s[(c0+j)*128 + p];
                uint32_t uh[4], ul[4];
#pragma unroll
                for (int j = 0; j < 4; j++) {
                    uint32_t h = cvt_bf16x2(v[2*j], v[2*j+1]);
                    float h0 = __uint_as_float(h << 16);
                    float h1 = __uint_as_float(h & 0xffff0000u);
                    uh[j] = h;
                    ul[j] = cvt_bf16x2(v[2*j] - h0, v[2*j+1] - h1);
                }
                uint32_t so = SWZ((uint32_t)(p*128 + c0*2));
                *(uint4*)(ps + so)         = make_uint4(uh[0], uh[1], uh[2], uh[3]);
                *(uint4*)(ps + 16384 + so) = make_uint4(ul[0], ul[1], ul[2], ul[3]);
            }
        }
        __syncthreads();
        uint32_t afh[4][4], afl[4][4];
#pragma unroll
        for (int ks = 0; ks < 4; ks++) {
            uint32_t aq = (uint32_t)(((2*ks + hsel) ^ r7) * 16);
            ldsm_x4(afh[ks][0], afh[ks][1], afh[ks][2], afh[ks][3], a_row + aq);
            ldsm_x4(afl[ks][0], afl[ks][1], afl[ks][2], afl[ks][3], a_row + 16384 + aq);
        }
#pragma unroll
        for (int ks = 0; ks < 4; ks++) {
#pragma unroll
            for (int nn = 0; nn < 4; nn++) {
                uint32_t bq = (uint32_t)(((2*nn + hsel) ^ r7) * 16);
                uint32_t baddr = b_row + ks*2048 + bq;
                uint32_t bh[4], bl[4];
                ldsm_x4t(bh[0], bh[1], bh[2], bh[3], baddr);
                ldsm_x4t(bl[0], bl[1], bl[2], bl[3], baddr + 8192);
                mma_bf16(dfr[2*nn],   afh[ks], bh);
                mma_bf16(dfr[2*nn],   afh[ks], bl);
                mma_bf16(dfr[2*nn],   afl[ks], bh);
                mma_bf16(dfr[2*nn+1], afh[ks], bh + 2);
                mma_bf16(dfr[2*nn+1], afh[ks], bl + 2);
                mma_bf16(dfr[2*nn+1], afl[ks], bh + 2);
            }
        }
    }
    __syncthreads();
    // ---- epilogue 1: fragments -> psi_t [c][129], stage conv weights ----
    {
        int gr = lane >> 2, tc = lane & 3;
        int i1 = w*16 + gr, i2 = i1 + 8;
#pragma unroll
        for (int nf = 0; nf < 8; nf++) {
            int c0 = nf*8 + 2*tc;
            float b0 = bias_s[c0], b1 = bias_s[c0+1];
            psi_t[c0*129 + i1]     = fmaxf(dfr[nf][0] + b0, 0.f);
            psi_t[(c0+1)*129 + i1] = fmaxf(dfr[nf][1] + b1, 0.f);
            psi_t[c0*129 + i2]     = fmaxf(dfr[nf][2] + b0, 0.f);
            psi_t[(c0+1)*129 + i2] = fmaxf(dfr[nf][3] + b1, 0.f);
        }
    }
    for (int idx = t; idx < 5120; idx += 256) {
        int c = idx / 80, o = idx % 80;
        float wv;
        if (o < 8)       wv = pb_w[o*64 + c];
        else if (o < 16) wv = pc_w[(o-8)*64 + c];
        else             wv = pd_w[(o-16)*64 + c];
        cw_s[idx] = wv;
    }
    if (t < 80) cbias[t] = (t < 8) ? pb_b[t] : (t < 16 ? pc_b[t-8] : pd_b[t-16]);
    __syncthreads();
    // ---- epilogue 2: store psi, fb/fc convs to global; fd -> swizzled smem ----
    for (int idx = t; idx < 8192; idx += 256) {
        int c = idx >> 7, p = idx & 127;
        d_psi[((size_t)b*Cn + c)*HWn + p0 + p] = psi_t[c*129 + p];
    }
    {
        int pos = t & 127, half = t >> 7;
        int o0 = half*40;
        int tt = pos >> 6, jp = pos & 63;
        uint32_t fbase = (uint32_t)(tt*8192 + (jp & 1)*2);
        uint32_t fslot = (uint32_t)((jp >> 1)*4);
        ull acc[20];
#pragma unroll
        for (int q = 0; q < 20; q++) acc[q] = pk2(cbias[o0 + 2*q], cbias[o0 + 2*q + 1]);
        for (int c = 0; c < 64; c++) {
            float v = psi_t[c*129 + pos];
            ull v2 = pk2(v, v);
            const ull* wr = (const ull*)&cw_s[c*80 + o0];
#pragma unroll
            for (int q = 0; q < 20; q++) acc[q] = ffma2(v2, wr[q], acc[q]);
        }
#pragma unroll
        for (int q = 0; q < 20; q++) {
            float v0, v1; upk2(acc[q], v0, v1);
            int o = o0 + 2*q;
#pragma unroll
            for (int s = 0; s < 2; s++) {
                float v = s ? v1 : v0;
                int oo = o + s;
                if (oo < 8)       d_fb[((size_t)b*8 + oo)*HWn + p0 + pos] = v * LOG2E;
                else if (oo < 16) d_fc[((size_t)b*8 + (oo-8))*HWn + p0 + pos] = v;
                else {
                    int c = oo - 16;
                    *(__half*)(fds + fbase + SWZ((uint32_t)(c*128) + fslot)) = __float2half(v);
                }
            }
        }
    }
    __syncthreads();
    // ---- copy fd tiles to global (coalesced uint4) ----
    {
        char* fdst = d_fd2 + (size_t)b*524288 + (size_t)(blockIdx.x*2)*8192;
#pragma unroll
        for (int k = 0; k < 4; k++) {
            int idx = t + k*256;
            *(uint4*)(fdst + idx*16) = *(const uint4*)(fds + idx*16);
        }
    }
    // ---- CAM gram atomics (psi_t untouched by fd path) ----
    {
        int cjg = t & 15, cig = t >> 4;
        float ga[4][4];
#pragma unroll
        for (int r = 0; r < 4; r++)
#pragma unroll
            for (int q = 0; q < 4; q++) ga[r][q] = 0.f;
        for (int p = 0; p < 128; p++) {
            float a0 = psi_t[(cig*4+0)*129 + p];
            float a1 = psi_t[(cig*4+1)*129 + p];
            float a2 = psi_t[(cig*4+2)*129 + p];
            float a3 = psi_t[(cig*4+3)*129 + p];
            float b0 = psi_t[(cjg*4+0)*129 + p];
            float b1 = psi_t[(cjg*4+1)*129 + p];
            float b2 = psi_t[(cjg*4+2)*129 + p];
            float b3 = psi_t[(cjg*4+3)*129 + p];
            ga[0][0]+=a0*b0; ga[0][1]+=a0*b1; ga[0][2]+=a0*b2; ga[0][3]+=a0*b3;
            ga[1][0]+=a1*b0; ga[1][1]+=a1*b1; ga[1][2]+=a1*b2; ga[1][3]+=a1*b3;
            ga[2][0]+=a2*b0; ga[2][1]+=a2*b1; ga[2][2]+=a2*b2; ga[2][3]+=a2*b3;
            ga[3][0]+=a3*b0; ga[3][1]+=a3*b1; ga[3][2]+=a3*b2; ga[3][3]+=a3*b3;
        }
#pragma unroll
        for (int r = 0; r < 4; r++)
#pragma unroll
            for (int q = 0; q < 4; q++)
                atomicAdd(&d_att[(b*64 + cig*4 + r)*64 + cjg*4 + q], ga[r][q]);
    }
}

// ---------------- PAM + CAM softmax + gate + final multiply ----------------
__global__ void __launch_bounds__(256, 2) k_pam3(const float* __restrict__ alpha_p,
                                                 const float* __restrict__ beta_p,
                                                 const float* __restrict__ x,
                                                 float* __restrict__ out) {
    extern __shared__ __align__(1024) char dsm[];
    // epilogue union
    float* psi_s = (float*)dsm;               // 64*132 f      0..33792
    float* pam_s = (float*)(dsm + 33792);     // 64*132 f      ..67584
    float* W2_s  = (float*)(dsm + 67584);     // 64*66 f       ..84480
    float* wp_s  = (float*)(dsm + 84480);     // 64 f          ..84736
    float* gred  = (float*)(dsm + 84736);     // 256 f         ..85760
    float* z_s   = (float*)(dsm + 85760);     // 128 f         ..86272
    float* att_s = (float*)(dsm + 86272);     // 64*65 f       ..102912

    uint32_t sbase = smem_u32(dsm);
    uint32_t fbb   = sbase + 16384;
    uint32_t fcb   = sbase + 22528;

    int b = blockIdx.y, I0 = blockIdx.x*128, t = threadIdx.x;
    int w = t >> 5, lane = t & 31;
    int gr = lane >> 2, tc = lane & 3;
    int i1 = w*16 + gr, i2 = i1 + 8;

    for (int idx = t; idx < 1024; idx += 256) {
        char* p;
        if (idx < 512) p = dsm + 16384 + (idx>>2)*48 + 16 + (idx&3)*4;
        else { int r = idx - 512; p = dsm + 22528 + (r>>2)*48 + 16 + (r&3)*4; }
        *(uint32_t*)p = 0u;
    }
    {
        int i = t & 127, half = t >> 7;
        float v0 = d_fb[((size_t)b*8 + half*4 + 0)*HWn + I0 + i];
        float v1 = d_fb[((size_t)b*8 + half*4 + 1)*HWn + I0 + i];
        float v2 = d_fb[((size_t)b*8 + half*4 + 2)*HWn + I0 + i];
        float v3 = d_fb[((size_t)b*8 + half*4 + 3)*HWn + I0 + i];
        *(uint32_t*)(dsm + 16384 + i*48 + half*8)     = cvt_f16x2(v0, v1);
        *(uint32_t*)(dsm + 16384 + i*48 + half*8 + 4) = cvt_f16x2(v2, v3);
    }
    __syncthreads();

    uint32_t af[4];
    {
        uint32_t aaddr = fbb + (uint32_t)(w*16 + (lane & 15))*48 + (lane >> 4)*16;
        ldsm_x4(af[0], af[1], af[2], af[3], aaddr);
    }

    float acc[8][4];
#pragma unroll
    for (int ng = 0; ng < 8; ng++)
#pragma unroll
        for (int q = 0; q < 4; q++) acc[ng][q] = 0.f;
    float z1 = 0.f, z2 = 0.f;
    float m1 = -1e30f, m2 = -1e30f;

    const char* fdg = d_fd2 + (size_t)b*524288;
    float fcr0, fcr1;
    uint4 fdr0, fdr1;
    {
        int j = t & 63, kp2 = t >> 6;
        fcr0 = d_fc[((size_t)b*8 + 2*kp2 + 0)*HWn + j];
        fcr1 = d_fc[((size_t)b*8 + 2*kp2 + 1)*HWn + j];
        fdr0 = *(const uint4*)(fdg + t*16);
        fdr1 = *(const uint4*)(fdg + 4096 + t*16);
    }

    uint32_t fdrow = (uint32_t)(lane & 15)*128 + (uint32_t)(lane >> 4)*16;

    for (int jt = 0; jt < 64; jt++) {
        uint32_t buf = (uint32_t)(jt & 1);
        {
            int j = t & 63, kp2 = t >> 6;
            *(uint32_t*)(dsm + 22528 + buf*3072 + j*48 + kp2*4) = cvt_f16x2(fcr0, fcr1);
        }
        *(uint4*)(dsm + buf*8192 + t*16)        = fdr0;
        *(uint4*)(dsm + buf*8192 + 4096 + t*16) = fdr1;
        __syncthreads();
        if (jt < 63) {
            int j0n = (jt+1)*64;
            int j = t & 63, kp2 = t >> 6;
            fcr0 = d_fc[((size_t)b*8 + 2*kp2 + 0)*HWn + j0n + j];
            fcr1 = d_fc[((size_t)b*8 + 2*kp2 + 1)*HWn + j0n + j];
            fdr0 = *(const uint4*)(fdg + (size_t)(jt+1)*8192 + t*16);
            fdr1 = *(const uint4*)(fdg + (size_t)(jt+1)*8192 + 4096 + t*16);
        }
        // energy mma (fp16 single product)
        float e[8][4];
#pragma unroll
        for (int ng = 0; ng < 8; ng++)
#pragma unroll
            for (int q = 0; q < 4; q++) e[ng][q] = 0.f;
#pragma unroll
        for (int jg = 0; jg < 4; jg++) {
            uint32_t baddr = fcb + buf*3072 + (uint32_t)(jg*16 + (lane & 15))*48 + (lane >> 4)*16;
            uint32_t bh[4];
            ldsm_x4(bh[0], bh[1], bh[2], bh[3], baddr);
            mma_f16s(e[2*jg],   af, bh[0], bh[2]);
            mma_f16s(e[2*jg+1], af, bh[1], bh[3]);
        }
        // online row max (quad shfl); rescale only when some row max moved (warp vote)
        float tm1 = -1e30f, tm2 = -1e30f;
#pragma unroll
        for (int ng = 0; ng < 8; ng++) {
            tm1 = fmaxf(tm1, fmaxf(e[ng][0], e[ng][1]));
            tm2 = fmaxf(tm2, fmaxf(e[ng][2], e[ng][3]));
        }
        tm1 = fmaxf(tm1, __shfl_xor_sync(0xffffffffu, tm1, 1));
        tm1 = fmaxf(tm1, __shfl_xor_sync(0xffffffffu, tm1, 2));
        tm2 = fmaxf(tm2, __shfl_xor_sync(0xffffffffu, tm2, 1));
        tm2 = fmaxf(tm2, __shfl_xor_sync(0xffffffffu, tm2, 2));
        float mn1 = fmaxf(m1, tm1), mn2 = fmaxf(m2, tm2);
        if (__any_sync(0xffffffffu, (mn1 > m1) || (mn2 > m2))) {
            float sc1 = ex2f(m1 - mn1), sc2 = ex2f(m2 - mn2);
            m1 = mn1; m2 = mn2;
            z1 *= sc1; z2 *= sc2;
#pragma unroll
            for (int ng = 0; ng < 8; ng++) {
                acc[ng][0] *= sc1; acc[ng][1] *= sc1;
                acc[ng][2] *= sc2; acc[ng][3] *= sc2;
            }
        }
        // exp via ex2.f16x2 -> p fragments
        uint32_t afr[4][4];
#pragma unroll
        for (int ng = 0; ng < 8; ng++) {
            uint32_t a01 = cvt_f16x2(e[ng][0] - m1, e[ng][1] - m1);
            uint32_t a23 = cvt_f16x2(e[ng][2] - m2, e[ng][3] - m2);
            uint32_t p01 = ex2h2(a01);
            uint32_t p23 = ex2h2(a23);
            int kp = ng >> 1;
            if ((ng & 1) == 0) { afr[kp][0] = p01; afr[kp][1] = p23; }
            else               { afr[kp][2] = p01; afr[kp][3] = p23; }
        }
        // z partial via HADD2 tree
        {
            uint32_t s1 = hadd2u(hadd2u(hadd2u(afr[0][0], afr[0][2]), hadd2u(afr[1][0], afr[1][2])),
                                 hadd2u(hadd2u(afr[2][0], afr[2][2]), hadd2u(afr[3][0], afr[3][2])));
            uint32_t s2 = hadd2u(hadd2u(hadd2u(afr[0][1], afr[0][3]), hadd2u(afr[1][1], afr[1][3])),
                                 hadd2u(hadd2u(afr[2][1], afr[2][3]), hadd2u(afr[3][1], afr[3][3])));
            float2 f1 = __half22float2(*(__half2*)&s1);
            float2 f2 = __half22float2(*(__half2*)&s2);
            z1 += f1.x + f1.y;
            z2 += f2.x + f2.y;
        }
        // accumulate mma (fp16)
#pragma unroll
        for (int ng2 = 0; ng2 < 4; ng2++) {
#pragma unroll
            for (int kp = 0; kp < 4; kp++) {
                uint32_t off = fdrow + (uint32_t)(ng2*2048 + kp*32);
                uint32_t f4[4];
                ldsm_x4(f4[0], f4[1], f4[2], f4[3], sbase + buf*8192 + SWZ(off));
                mma_f16s(acc[2*ng2],   afr[kp], f4[0], f4[2]);
                mma_f16s(acc[2*ng2+1], afr[kp], f4[1], f4[3]);
            }
        }
    }
    // ---- z reduction across the quad; leaders write z_s directly ----
    z1 += __shfl_xor_sync(0xffffffffu, z1, 1);
    z1 += __shfl_xor_sync(0xffffffffu, z1, 2);
    z2 += __shfl_xor_sync(0xffffffffu, z2, 1);
    z2 += __shfl_xor_sync(0xffffffffu, z2, 2);
    if (tc == 0) {
        z_s[i1] = alpha_p[0] / z1;
        z_s[i2] = alpha_p[0] / z2;
    }
    __syncthreads();
    // ---- load psi tile / att / wp ----
    for (int idx = t; idx < 8192; idx += 256) {
        int c = idx >> 7, p = idx & 127;
        psi_s[c*132 + p] = d_psi[((size_t)b*Cn + c)*HWn + I0 + p];
    }
    for (int idx = t; idx < 4096; idx += 256)
        att_s[(idx >> 6)*65 + (idx & 63)] = d_att[b*4096 + idx];
    if (t < 64) wp_s[t] = d_wp[t];
    __syncthreads();
    // ---- CAM softmax -> W2_s[c][66] (4 threads per row) ----
    {
        int r = t >> 2, q4 = t & 3;
        float v[16];
#pragma unroll
        for (int k = 0; k < 16; k++) v[k] = att_s[r*65 + q4*16 + k];
        float mx = -1e30f, mn = 1e30f;
#pragma unroll
        for (int k = 0; k < 16; k++) { mx = fmaxf(mx, v[k]); mn = fminf(mn, v[k]); }
        mx = fmaxf(mx, __shfl_xor_sync(0xffffffffu, mx, 1));
        mx = fmaxf(mx, __shfl_xor_sync(0xffffffffu, mx, 2));
        mn = fminf(mn, __shfl_xor_sync(0xffffffffu, mn, 1));
        mn = fminf(mn, __shfl_xor_sync(0xffffffffu, mn, 2));
        float m2r = mx - mn;
        float ssum = 0.f;
#pragma unroll
        for (int k = 0; k < 16; k++) { float ev = __expf((mx - v[k]) - m2r); v[k] = ev; ssum += ev; }
        ssum += __shfl_xor_sync(0xffffffffu, ssum, 1);
        ssum += __shfl_xor_sync(0xffffffffu, ssum, 2);
        float scale = beta_p[0] * wp_s[r] / ssum;
#pragma unroll
        for (int k = 0; k < 16; k++) W2_s[r*66 + q4*16 + k] = v[k] * scale;
    }
    // ---- fragments -> pam_s[c][i] ----
    {
        float zz1 = z_s[i1], zz2 = z_s[i2];
#pragma unroll
        for (int ng = 0; ng < 8; ng++) {
            int c = ng*8 + 2*tc;
            pam_s[c*132 + i1]     = acc[ng][0]*zz1 + psi_s[c*132 + i1];
            pam_s[(c+1)*132 + i1] = acc[ng][1]*zz1 + psi_s[(c+1)*132 + i1];
            pam_s[c*132 + i2]     = acc[ng][2]*zz2 + psi_s[c*132 + i2];
            pam_s[(c+1)*132 + i2] = acc[ng][3]*zz2 + psi_s[(c+1)*132 + i2];
        }
    }
    __syncthreads();
    // ---- fused CAM + gate ----
    {
        int p = t & 127, half = t >> 7;
        int c0 = half*32, d0 = half*32;
        float part1 = 0.f;
#pragma unroll 8
        for (int c = 0; c < 32; c++) {
            int cc = c0 + c;
            part1 += wp_s[cc] * psi_s[cc*132 + p] * pam_s[cc*132 + p];
        }
        ull v[16];
#pragma unroll
        for (int q = 0; q < 16; q++) v[q] = 0ull;
        for (int c = 0; c < 64; c++) {
            float pm = pam_s[c*132 + p];
            ull pm2 = pk2(pm, pm);
            const ull* wr = (const ull*)&W2_s[c*66 + d0];
#pragma unroll
            for (int q = 0; q < 16; q++) v[q] = ffma2(pm2, wr[q], v[q]);
        }
        float part2 = 0.f;
#pragma unroll
        for (int q = 0; q < 16; q++) {
            float v0, v1; upk2(v[q], v0, v1);
            part2 += psi_s[(d0+2*q)*132 + p]*v0 + psi_s[(d0+2*q+1)*132 + p]*v1;
        }
        gred[half*128 + p] = part1 + part2;
    }
    __syncthreads();
    if (t < 128) {
        float gate = d_bp[0] + gred[t] + gred[128 + t];
        z_s[t] = 1.f / (1.f + __expf(-gate));   // da
    }
    __syncthreads();
    // ---- fused final multiply (float4 over positions) ----
    {
        int p4 = t & 31, c0 = t >> 5;
        float4 da = *(const float4*)&z_s[p4*4];
        const float* xp = x + ((size_t)b*256)*HWn + I0 + p4*4;
        float* op = out + ((size_t)b*256)*HWn + I0 + p4*4;
#pragma unroll 8
        for (int c = c0; c < 256; c += 8) {
            float4 v = *(const float4*)&xp[(size_t)c*HWn];
            v.x *= da.x; v.y *= da.y; v.z *= da.z; v.w *= da.w;
            *(float4*)&op[(size_t)c*HWn] = v;
        }
    }
}

// ---------------- launch ----------------
extern "C" void kernel_launch(void* const* d_in, const int* in_sizes, int n_in,
                              void* d_out, int out_size) {
    const float* g = (const float*)d_in[0];
    const float* x = (const float*)d_in[1];

    cudaFuncSetAttribute(k_psi2, cudaFuncAttributeMaxDynamicSharedMemorySize, 82176);
    cudaFuncSetAttribute(k_pam3, cudaFuncAttributeMaxDynamicSharedMemorySize, 102912);

    k_prep<<<128, 256>>>((const float*)d_in[2],  (const float*)d_in[3],  (const float*)d_in[4],
                        (const float*)d_in[5],  (const float*)d_in[6],  (const float*)d_in[7],
                        (const float*)d_in[8],  (const float*)d_in[9],  (const float*)d_in[10],
                        (const float*)d_in[11], (const float*)d_in[12], (const float*)d_in[13],
                        (const float*)d_in[14], (const float*)d_in[15], (const float*)d_in[16],
                        (const float*)d_in[17], (const float*)d_in[18], (const float*)d_in[19]);

    k_psi2<<<dim3(32, 8), 256, 82176>>>(g, x,
        (const float*)d_in[20], (const float*)d_in[21],
        (const float*)d_in[22], (const float*)d_in[23],
        (const float*)d_in[24], (const float*)d_in[25]);

    k_pam3<<<dim3(32, 8), 256, 102912>>>((const float*)d_in[26], (const float*)d_in[27],
                                         x, (float*)d_out);
}